// round 1
// baseline (speedup 1.0000x reference)
#include <cuda_runtime.h>
#include <cuda_bf16.h>
#include <math.h>

// Problem constants
#define BATCH 8
#define NPIX  4096           // 64*64
#define CDIM  256
#define CKDIM 32
#define ROWS  (BATCH*NPIX)   // 32768
#define TILE  64

// Scratch (allocation-free: __device__ globals)
__device__ float g_f  [ROWS*CKDIM];   // keys   f = x Wf + bf
__device__ float g_gq [ROWS*CKDIM];   // query  g = x Wg + bg
__device__ float g_h  [ROWS*CDIM];    // values hh = x Wh + bh
__device__ float g_o  [ROWS*CDIM];    // attention output (pre-Wo)

// ---------------------------------------------------------------------------
// Kernel 1: fused f|g projection.  64 rows/block, N=64 (32 f + 32 g), K=256.
// ---------------------------------------------------------------------------
__global__ void proj_fg(const float* __restrict__ x,
                        const float* __restrict__ Wf, const float* __restrict__ bf,
                        const float* __restrict__ Wg, const float* __restrict__ bg) {
    extern __shared__ float sm[];
    float* sx = sm;            // [64][260]  (pad 260 -> bank-safe, float4-aligned)
    float* sw = sm + 64*260;   // [256][68]  cols 0..31 = Wf, 32..63 = Wg
    const int tid  = threadIdx.x;
    const int row0 = blockIdx.x * TILE;

    for (int id = tid; id < 64*64; id += 256) {         // 64 rows * 64 float4
        int r = id >> 6, c4 = (id & 63) << 2;
        *(float4*)(sx + r*260 + c4) = *(const float4*)(x + (size_t)(row0 + r)*CDIM + c4);
    }
    for (int id = tid; id < 256*32; id += 256) {
        int k = id >> 5, c = id & 31;
        sw[k*68 + c]      = Wf[id];
        sw[k*68 + 32 + c] = Wg[id];
    }
    __syncthreads();

    const int r0 = (tid >> 4) * 4;      // 4 rows
    const int cb = (tid & 15) * 4;      // 4 cols
    float acc[4][4] = {};
    #pragma unroll 4
    for (int k = 0; k < 256; k++) {
        float w0 = sw[k*68 + cb + 0], w1 = sw[k*68 + cb + 1];
        float w2 = sw[k*68 + cb + 2], w3 = sw[k*68 + cb + 3];
        #pragma unroll
        for (int i = 0; i < 4; i++) {
            float xv = sx[(r0+i)*260 + k];
            acc[i][0] += xv*w0; acc[i][1] += xv*w1;
            acc[i][2] += xv*w2; acc[i][3] += xv*w3;
        }
    }
    #pragma unroll
    for (int i = 0; i < 4; i++) {
        size_t r = (size_t)(row0 + r0 + i);
        #pragma unroll
        for (int j = 0; j < 4; j++) {
            int c = cb + j;
            if (c < 32) g_f [r*CKDIM + c]        = acc[i][j] + bf[c];
            else        g_gq[r*CKDIM + (c - 32)] = acc[i][j] + bg[c - 32];
        }
    }
}

// ---------------------------------------------------------------------------
// Kernel 2/4: 256x256 GEMM over 64-row tiles.
//   IS_OUT=false : g_h = x Wh + bh
//   IS_OUT=true  : out = gamma*(g_o Wo + bo) + x
// ---------------------------------------------------------------------------
template <bool IS_OUT>
__global__ void gemm256(const float* __restrict__ inExt,
                        const float* __restrict__ W,
                        const float* __restrict__ bias,
                        const float* __restrict__ gamma,
                        const float* __restrict__ xres,
                        float* __restrict__ outExt) {
    extern __shared__ float sm[];
    float* sx = sm;            // [64][260]
    float* sw = sm + 64*260;   // [64][272] : 4 groups of (64+4) per k-row
    const int tid  = threadIdx.x;
    const int row0 = blockIdx.x * TILE;

    const float* in = IS_OUT ? (const float*)g_o : inExt;

    for (int id = tid; id < 64*64; id += 256) {
        int r = id >> 6, c4 = (id & 63) << 2;
        *(float4*)(sx + r*260 + c4) = *(const float4*)(in + (size_t)(row0 + r)*CDIM + c4);
    }

    const int r0  = (tid >> 4) * 4;     // 4 rows
    const int cb  = (tid & 15) * 16;    // 16 cols
    const int grp = cb >> 6, win = cb & 63;
    float acc[4][16] = {};

    for (int kc = 0; kc < 4; kc++) {
        __syncthreads();   // covers sx store visibility & sw reuse
        for (int id = tid; id < 64*64; id += 256) {
            int k = id >> 6, c4 = (id & 63) << 2;
            *(float4*)(sw + k*272 + (c4 >> 6)*68 + (c4 & 63)) =
                *(const float4*)(W + (size_t)(kc*64 + k)*CDIM + c4);
        }
        __syncthreads();
        #pragma unroll 2
        for (int k = 0; k < 64; k++) {
            float xv0 = sx[(r0+0)*260 + kc*64 + k];
            float xv1 = sx[(r0+1)*260 + kc*64 + k];
            float xv2 = sx[(r0+2)*260 + kc*64 + k];
            float xv3 = sx[(r0+3)*260 + kc*64 + k];
            const float* wr = sw + k*272 + grp*68 + win;
            float4 w0 = *(const float4*)(wr + 0);
            float4 w1 = *(const float4*)(wr + 4);
            float4 w2 = *(const float4*)(wr + 8);
            float4 w3 = *(const float4*)(wr + 12);
            const float wv[16] = {w0.x,w0.y,w0.z,w0.w, w1.x,w1.y,w1.z,w1.w,
                                  w2.x,w2.y,w2.z,w2.w, w3.x,w3.y,w3.z,w3.w};
            #pragma unroll
            for (int j = 0; j < 16; j++) {
                acc[0][j] += xv0*wv[j]; acc[1][j] += xv1*wv[j];
                acc[2][j] += xv2*wv[j]; acc[3][j] += xv3*wv[j];
            }
        }
    }

    #pragma unroll
    for (int i = 0; i < 4; i++) {
        size_t r = (size_t)(row0 + r0 + i);
        #pragma unroll
        for (int j = 0; j < 16; j++) {
            int c = cb + j;
            float v = acc[i][j] + bias[c];
            if (IS_OUT) outExt[r*CDIM + c] = gamma[0]*v + xres[r*CDIM + c];
            else        g_h  [r*CDIM + c] = v;
        }
    }
}

// ---------------------------------------------------------------------------
// Kernel 3: flash attention.  Block = 64 query rows of one batch;
// streams 64 key tiles; online softmax; O reg-tile 4x16 per thread.
// ---------------------------------------------------------------------------
__global__ void attn_kernel() {
    extern __shared__ float sm[];
    float* sg = sm;                  // [64][33] queries
    float* sf = sg + 64*33;          // [64][33] keys
    float* sS = sf + 64*33;          // [64][68] probabilities
    float* sh = sS + 64*68;          // [64][272] values (4x68 groups)

    const int tid = threadIdx.x;
    const int b   = blockIdx.x >> 6;          // 64 query tiles per batch
    const int qt  = blockIdx.x & 63;
    const size_t qbase = (size_t)b*NPIX + qt*TILE;

    for (int id = tid; id < 64*32; id += 256) {
        int r = id >> 5, d = id & 31;
        sg[r*33 + d] = g_gq[(qbase + r)*CKDIM + d];
    }

    const int r0  = (tid >> 4) * 4;    // 4 rows
    const int sc  = (tid & 15) * 4;    // 4 score cols
    const int cb  = (tid & 15) * 16;   // 16 value cols
    const int grp = cb >> 6, win = cb & 63;

    float m[4] = {-3.0e38f, -3.0e38f, -3.0e38f, -3.0e38f};
    float l[4] = {0.f, 0.f, 0.f, 0.f};
    float acc[4][16] = {};

    for (int kt = 0; kt < 64; kt++) {
        __syncthreads();                              // prior tile fully consumed
        const size_t kbase = (size_t)b*NPIX + kt*TILE;
        for (int id = tid; id < 64*32; id += 256) {
            int r = id >> 5, d = id & 31;
            sf[r*33 + d] = g_f[(kbase + r)*CKDIM + d];
        }
        for (int id = tid; id < 64*64; id += 256) {
            int k = id >> 6, c4 = (id & 63) << 2;
            *(float4*)(sh + k*272 + (c4 >> 6)*68 + (c4 & 63)) =
                *(const float4*)(g_h + (kbase + k)*CDIM + c4);
        }
        __syncthreads();

        // ---- scores: s[4][4] = g[r0..r0+3] . f[sc..sc+3]
        float s[4][4] = {};
        #pragma unroll 4
        for (int d = 0; d < 32; d++) {
            float gv0 = sg[(r0+0)*33 + d], gv1 = sg[(r0+1)*33 + d];
            float gv2 = sg[(r0+2)*33 + d], gv3 = sg[(r0+3)*33 + d];
            #pragma unroll
            for (int j = 0; j < 4; j++) {
                float fv = sf[(sc+j)*33 + d];
                s[0][j] += gv0*fv; s[1][j] += gv1*fv;
                s[2][j] += gv2*fv; s[3][j] += gv3*fv;
            }
        }

        // ---- online softmax per row (16 lanes own one row-group)
        #pragma unroll
        for (int i = 0; i < 4; i++) {
            float mx = fmaxf(fmaxf(s[i][0], s[i][1]), fmaxf(s[i][2], s[i][3]));
            #pragma unroll
            for (int o = 1; o < 16; o <<= 1)
                mx = fmaxf(mx, __shfl_xor_sync(0xffffffffu, mx, o));
            float mnew  = fmaxf(m[i], mx);
            float scale = __expf(m[i] - mnew);
            float ps = 0.f;
            #pragma unroll
            for (int j = 0; j < 4; j++) {
                float p = __expf(s[i][j] - mnew);
                sS[(r0+i)*68 + sc + j] = p;
                ps += p;
            }
            #pragma unroll
            for (int o = 1; o < 16; o <<= 1)
                ps += __shfl_xor_sync(0xffffffffu, ps, o);
            l[i] = l[i]*scale + ps;
            m[i] = mnew;
            #pragma unroll
            for (int j = 0; j < 16; j++) acc[i][j] *= scale;
        }
        __syncthreads();

        // ---- accumulate O += P @ hh  (64 FMA per 8 shared loads)
        #pragma unroll 2
        for (int k = 0; k < 64; k++) {
            float p0 = sS[(r0+0)*68 + k];
            float p1 = sS[(r0+1)*68 + k];
            float p2 = sS[(r0+2)*68 + k];
            float p3 = sS[(r0+3)*68 + k];
            const float* wr = sh + k*272 + grp*68 + win;
            float4 w0 = *(const float4*)(wr + 0);
            float4 w1 = *(const float4*)(wr + 4);
            float4 w2 = *(const float4*)(wr + 8);
            float4 w3 = *(const float4*)(wr + 12);
            const float wv[16] = {w0.x,w0.y,w0.z,w0.w, w1.x,w1.y,w1.z,w1.w,
                                  w2.x,w2.y,w2.z,w2.w, w3.x,w3.y,w3.z,w3.w};
            #pragma unroll
            for (int j = 0; j < 16; j++) {
                acc[0][j] += p0*wv[j]; acc[1][j] += p1*wv[j];
                acc[2][j] += p2*wv[j]; acc[3][j] += p3*wv[j];
            }
        }
    }

    #pragma unroll
    for (int i = 0; i < 4; i++) {
        float inv = 1.0f / l[i];
        size_t r = qbase + r0 + i;
        #pragma unroll
        for (int j = 0; j < 16; j++)
            g_o[r*CDIM + cb + j] = acc[i][j]*inv;
    }
}

// ---------------------------------------------------------------------------
extern "C" void kernel_launch(void* const* d_in, const int* in_sizes, int n_in,
                              void* d_out, int out_size) {
    const float* x     = (const float*)d_in[0];
    const float* Wf    = (const float*)d_in[1];
    const float* bf    = (const float*)d_in[2];
    const float* Wg    = (const float*)d_in[3];
    const float* bg    = (const float*)d_in[4];
    const float* Wh    = (const float*)d_in[5];
    const float* bh    = (const float*)d_in[6];
    const float* Wo    = (const float*)d_in[7];
    const float* bo    = (const float*)d_in[8];
    const float* gamma = (const float*)d_in[9];
    float*       out   = (float*)d_out;

    const int smem_fg   = (64*260 + 256*68) * 4;   // 136192 B
    const int smem_gemm = (64*260 + 64*272) * 4;   // 136192 B
    const int smem_attn = (64*33*2 + 64*68 + 64*272) * 4;  // 103936 B

    cudaFuncSetAttribute(proj_fg,        cudaFuncAttributeMaxDynamicSharedMemorySize, smem_fg);
    cudaFuncSetAttribute(gemm256<false>, cudaFuncAttributeMaxDynamicSharedMemorySize, smem_gemm);
    cudaFuncSetAttribute(gemm256<true>,  cudaFuncAttributeMaxDynamicSharedMemorySize, smem_gemm);
    cudaFuncSetAttribute(attn_kernel,    cudaFuncAttributeMaxDynamicSharedMemorySize, smem_attn);

    const int nblk = ROWS / TILE;  // 512

    proj_fg<<<nblk, 256, smem_fg>>>(x, Wf, bf, Wg, bg);
    gemm256<false><<<nblk, 256, smem_gemm>>>(x, Wh, bh, nullptr, nullptr, nullptr);
    attn_kernel<<<nblk, 256, smem_attn>>>();
    gemm256<true><<<nblk, 256, smem_gemm>>>(nullptr, Wo, bo, gamma, x, out);
}

// round 3
// speedup vs baseline: 3.4776x; 3.4776x over previous
#include <cuda_runtime.h>
#include <cuda_bf16.h>
#include <cuda_fp16.h>
#include <cstdint>
#include <math.h>

#define BATCH 8
#define NPIX  4096
#define CDIM  256
#define CKDIM 32
#define ROWS  (BATCH*NPIX)   // 32768

// ---------------- scratch (allocation-free) ----------------
__device__ __align__(16) __nv_bfloat16 g_f_hi[ROWS*CKDIM];
__device__ __align__(16) __nv_bfloat16 g_f_lo[ROWS*CKDIM];
__device__ __align__(16) __nv_bfloat16 g_g_hi[ROWS*CKDIM];
__device__ __align__(16) __nv_bfloat16 g_g_lo[ROWS*CKDIM];
__device__ __align__(16) __half       g_hT  [ROWS*CDIM];   // V^T: [b][c][n], fp16
__device__ __align__(16) float        g_o   [ROWS*CDIM];

// ---------------- PTX helpers (all sm_80-level, no arch-'a' features) -------
__device__ __forceinline__ uint32_t smem_u32(const void* p) {
    uint32_t a;
    asm("{ .reg .u64 t; cvta.to.shared.u64 t, %1; cvt.u32.u64 %0, t; }" : "=r"(a) : "l"(p));
    return a;
}
#define CP_ASYNC16(dst, src) \
    asm volatile("cp.async.cg.shared.global [%0], [%1], 16;" :: "r"(dst), "l"(src))
#define CP_COMMIT() asm volatile("cp.async.commit_group;" ::: "memory")
#define CP_WAIT(n)  asm volatile("cp.async.wait_group %0;" :: "n"(n) : "memory")

__device__ __forceinline__ void ldm_x4(uint32_t r[4], uint32_t addr) {
    asm volatile("ldmatrix.sync.aligned.m8n8.x4.shared.b16 {%0,%1,%2,%3}, [%4];"
                 : "=r"(r[0]), "=r"(r[1]), "=r"(r[2]), "=r"(r[3]) : "r"(addr));
}
__device__ __forceinline__ void mma_bf16(float c[4], const uint32_t a[4], const uint32_t* b) {
    asm volatile("mma.sync.aligned.m16n8k16.row.col.f32.bf16.bf16.f32 "
                 "{%0,%1,%2,%3}, {%4,%5,%6,%7}, {%8,%9}, {%0,%1,%2,%3};"
                 : "+f"(c[0]), "+f"(c[1]), "+f"(c[2]), "+f"(c[3])
                 : "r"(a[0]), "r"(a[1]), "r"(a[2]), "r"(a[3]), "r"(b[0]), "r"(b[1]));
}
__device__ __forceinline__ void mma_f16(float c[4], const uint32_t a[4], const uint32_t* b) {
    asm volatile("mma.sync.aligned.m16n8k16.row.col.f32.f16.f16.f32 "
                 "{%0,%1,%2,%3}, {%4,%5,%6,%7}, {%8,%9}, {%0,%1,%2,%3};"
                 : "+f"(c[0]), "+f"(c[1]), "+f"(c[2]), "+f"(c[3])
                 : "r"(a[0]), "r"(a[1]), "r"(a[2]), "r"(a[3]), "r"(b[0]), "r"(b[1]));
}
// pack {low=lo, high=hi} fp16x2
__device__ __forceinline__ uint32_t pack_f16(float lo, float hi) {
    uint32_t d;
    asm("cvt.rn.f16x2.f32 %0, %1, %2;" : "=r"(d) : "f"(hi), "f"(lo));
    return d;
}
__device__ __forceinline__ uint32_t pack_bf16(__nv_bfloat16 a, __nv_bfloat16 b) {
    __nv_bfloat162 t(a, b);
    return *reinterpret_cast<uint32_t*>(&t);
}

// ---------------------------------------------------------------------------
// Kernel 1: f|g projection (fp32 SIMT, split-bf16 outputs).
// ---------------------------------------------------------------------------
__global__ __launch_bounds__(256) void proj_fg(const float* __restrict__ x,
                        const float* __restrict__ Wf, const float* __restrict__ bf,
                        const float* __restrict__ Wg, const float* __restrict__ bg) {
    extern __shared__ float smf[];
    float* sx = smf;            // [64][68] per k-chunk
    float* sw = smf + 64*68;    // [256][68]
    const int tid  = threadIdx.x;
    const int row0 = blockIdx.x * 64;

    for (int id = tid; id < 256*32; id += 256) {
        int k = id >> 5, c = id & 31;
        sw[k*68 + c]      = Wf[id];
        sw[k*68 + 32 + c] = Wg[id];
    }
    const int r0 = (tid >> 4) * 4;
    const int cb = (tid & 15) * 4;
    float acc[4][4] = {};
    for (int kc = 0; kc < 4; kc++) {
        __syncthreads();
        for (int id = tid; id < 64*16; id += 256) {
            int r = id >> 4, c4 = (id & 15) << 2;
            *(float4*)(sx + r*68 + c4) =
                *(const float4*)(x + (size_t)(row0 + r)*CDIM + kc*64 + c4);
        }
        __syncthreads();
        #pragma unroll 4
        for (int k = 0; k < 64; k++) {
            float w0 = sw[(kc*64+k)*68 + cb + 0], w1 = sw[(kc*64+k)*68 + cb + 1];
            float w2 = sw[(kc*64+k)*68 + cb + 2], w3 = sw[(kc*64+k)*68 + cb + 3];
            #pragma unroll
            for (int i = 0; i < 4; i++) {
                float xv = sx[(r0+i)*68 + k];
                acc[i][0] += xv*w0; acc[i][1] += xv*w1;
                acc[i][2] += xv*w2; acc[i][3] += xv*w3;
            }
        }
    }
    #pragma unroll
    for (int i = 0; i < 4; i++) {
        size_t r = (size_t)(row0 + r0 + i);
        #pragma unroll
        for (int j2 = 0; j2 < 4; j2 += 2) {
            int c0 = cb + j2;
            float v0, v1;
            if (c0 < 32) { v0 = acc[i][j2] + bf[c0];    v1 = acc[i][j2+1] + bf[c0+1]; }
            else         { v0 = acc[i][j2] + bg[c0-32]; v1 = acc[i][j2+1] + bg[c0-31]; }
            __nv_bfloat16 h0 = __float2bfloat16(v0), h1 = __float2bfloat16(v1);
            __nv_bfloat16 l0 = __float2bfloat16(v0 - __bfloat162float(h0));
            __nv_bfloat16 l1 = __float2bfloat16(v1 - __bfloat162float(h1));
            if (c0 < 32) {
                size_t idx = r*CKDIM + c0;
                *(uint32_t*)&g_f_hi[idx] = pack_bf16(h0, h1);
                *(uint32_t*)&g_f_lo[idx] = pack_bf16(l0, l1);
            } else {
                size_t idx = r*CKDIM + (c0 - 32);
                *(uint32_t*)&g_g_hi[idx] = pack_bf16(h0, h1);
                *(uint32_t*)&g_g_lo[idx] = pack_bf16(l0, l1);
            }
        }
    }
}

// ---------------------------------------------------------------------------
// Kernel 2/4: 256x256 GEMM (fp32 SIMT)
// ---------------------------------------------------------------------------
template <bool IS_OUT>
__global__ __launch_bounds__(256) void gemm256(const float* __restrict__ inExt,
                        const float* __restrict__ W,
                        const float* __restrict__ bias,
                        const float* __restrict__ gamma,
                        const float* __restrict__ xres,
                        float* __restrict__ outExt) {
    extern __shared__ float smf[];
    float* sx = smf;            // [64][68]
    float* sw = smf + 64*68;    // [64][272]
    const int tid  = threadIdx.x;
    const int row0 = blockIdx.x * 64;
    const float* in = IS_OUT ? (const float*)g_o : inExt;

    const int r0  = (tid >> 4) * 4;
    const int cb  = (tid & 15) * 16;
    const int grp = cb >> 6, win = cb & 63;
    float acc[4][16] = {};

    for (int kc = 0; kc < 4; kc++) {
        __syncthreads();
        for (int id = tid; id < 64*16; id += 256) {
            int r = id >> 4, c4 = (id & 15) << 2;
            *(float4*)(sx + r*68 + c4) =
                *(const float4*)(in + (size_t)(row0 + r)*CDIM + kc*64 + c4);
        }
        for (int id = tid; id < 64*64; id += 256) {
            int k = id >> 6, c4 = (id & 63) << 2;
            *(float4*)(sw + k*272 + (c4 >> 6)*68 + (c4 & 63)) =
                *(const float4*)(W + (size_t)(kc*64 + k)*CDIM + c4);
        }
        __syncthreads();
        #pragma unroll 2
        for (int k = 0; k < 64; k++) {
            float xv0 = sx[(r0+0)*68 + k];
            float xv1 = sx[(r0+1)*68 + k];
            float xv2 = sx[(r0+2)*68 + k];
            float xv3 = sx[(r0+3)*68 + k];
            const float* wr = sw + k*272 + grp*68 + win;
            float4 w0 = *(const float4*)(wr + 0);
            float4 w1 = *(const float4*)(wr + 4);
            float4 w2 = *(const float4*)(wr + 8);
            float4 w3 = *(const float4*)(wr + 12);
            const float wv[16] = {w0.x,w0.y,w0.z,w0.w, w1.x,w1.y,w1.z,w1.w,
                                  w2.x,w2.y,w2.z,w2.w, w3.x,w3.y,w3.z,w3.w};
            #pragma unroll
            for (int j = 0; j < 16; j++) {
                acc[0][j] += xv0*wv[j]; acc[1][j] += xv1*wv[j];
                acc[2][j] += xv2*wv[j]; acc[3][j] += xv3*wv[j];
            }
        }
    }

    if (IS_OUT) {
        #pragma unroll
        for (int i = 0; i < 4; i++) {
            size_t r = (size_t)(row0 + r0 + i);
            #pragma unroll
            for (int j = 0; j < 16; j++) {
                int c = cb + j;
                float v = acc[i][j] + bias[c];
                outExt[r*CDIM + c] = gamma[0]*v + xres[r*CDIM + c];
            }
        }
    } else {
        // write V^T [b][c][n], fp16
        const int batch = row0 >> 12;
        const int nbase = (row0 & 4095) + r0;
        #pragma unroll
        for (int j = 0; j < 16; j++) {
            int c = cb + j;
            float bval = bias[c];
            __half h[4];
            #pragma unroll
            for (int i = 0; i < 4; i++) h[i] = __float2half(acc[i][j] + bval);
            size_t idx = ((size_t)batch*CDIM + c)*NPIX + nbase;
            __half2 p0 = __halves2half2(h[0], h[1]);
            __half2 p1 = __halves2half2(h[2], h[3]);
            uint2 u; u.x = *(uint32_t*)&p0; u.y = *(uint32_t*)&p1;
            *(uint2*)&g_hT[idx] = u;
        }
    }
}

// ---------------------------------------------------------------------------
// Kernel 3: HMMA flash attention.
// CTA: 64 queries x 256 channels, 256 threads (8 warps).
// warp = (wq: 16 q-rows) x (wc: 128 c-cols). S split-bf16, PV fp16.
// ---------------------------------------------------------------------------
#define OFF_G  0                    // [64][80B] hi + [64][80B] lo = 10240
#define OFF_F  10240                // 2 bufs x (hi 5120 + lo 5120)
#define OFF_V  (OFF_F + 2*10240)    // 2 bufs x 256*144
#define SMEM_ATT (OFF_V + 2*36864)  // 104448 B

__device__ __forceinline__ void prefetch_tile(uint32_t sb, int bf, int b, int kt, int tid) {
    const size_t kbase = (size_t)b*NPIX + (size_t)kt*64;
    // F (bf16 hi/lo): 64 rows x 64B
    int fr = tid >> 2, fc = tid & 3;
    uint32_t fd = sb + OFF_F + bf*10240 + fr*80 + fc*16;
    CP_ASYNC16(fd,        (const char*)g_f_hi + ((kbase + fr)*CKDIM + fc*8)*2);
    CP_ASYNC16(fd + 5120, (const char*)g_f_lo + ((kbase + fr)*CKDIM + fc*8)*2);
    // V^T (fp16): 256 rows x 128B
    #pragma unroll
    for (int i = 0; i < 8; i++) {
        int chunk = tid + i*256;
        int vr = chunk >> 3, vc = chunk & 7;
        uint32_t vd = sb + OFF_V + bf*36864 + vr*144 + vc*16;
        CP_ASYNC16(vd, (const char*)g_hT + (((size_t)b*CDIM + vr)*NPIX + kt*64 + vc*8)*2);
    }
}

__global__ __launch_bounds__(256) void attn_hmma() {
    extern __shared__ char smc[];
    const uint32_t sb = smem_u32(smc);
    const int tid  = threadIdx.x;
    const int lane = tid & 31;
    const int wid  = tid >> 5;
    const int wq   = wid & 3;      // 16 q-rows
    const int wc   = wid >> 2;     // 128 c-cols
    const int b    = blockIdx.x >> 6;
    const int qt   = blockIdx.x & 63;
    const size_t qbase = (size_t)b*NPIX + qt*64;

    // stage G (queries, bf16 hi/lo) + tile 0, one commit group
    {
        int gr = tid >> 2, gc = tid & 3;
        uint32_t gd = sb + OFF_G + gr*80 + gc*16;
        CP_ASYNC16(gd,        (const char*)g_g_hi + ((qbase + gr)*CKDIM + gc*8)*2);
        CP_ASYNC16(gd + 5120, (const char*)g_g_lo + ((qbase + gr)*CKDIM + gc*8)*2);
        prefetch_tile(sb, 0, b, 0, tid);
        CP_COMMIT();
        prefetch_tile(sb, 1, b, 1, tid);
        CP_COMMIT();
    }
    CP_WAIT(1);
    __syncthreads();

    // address components (per-thread constants)
    const int aRow = lane & 15;              // A-frag row within 16
    const int aK   = (lane >> 4) * 16;       // A-frag k-chunk byte offset
    const int bR   = lane & 7;               // B-frag row within 8
    const int bHi8 = (lane >> 4) * 8;        // B-frag: second n-tile select
    const int bK   = ((lane >> 3) & 1) * 16; // B-frag k-chunk byte offset

    // G fragments (persistent): gh[ks][4], gl[ks][4]
    uint32_t gh[2][4], gl[2][4];
    #pragma unroll
    for (int ks = 0; ks < 2; ks++) {
        uint32_t ad = sb + OFF_G + (wq*16 + aRow)*80 + ks*32 + aK;
        ldm_x4(gh[ks], ad);
        ldm_x4(gl[ks], ad + 5120);
    }

    float accO[16][4];
    #pragma unroll
    for (int i = 0; i < 16; i++) { accO[i][0]=0.f; accO[i][1]=0.f; accO[i][2]=0.f; accO[i][3]=0.f; }
    float mA = -1e30f, mB = -1e30f, lA = 0.f, lB = 0.f;

    for (int kt = 0; kt < 64; kt++) {
        const int bf = kt & 1;

        // ---- S = G . F^T (split-bf16: Gh*Fh + Gh*Fl + Gl*Fh) ----
        float sc[8][4];
        #pragma unroll
        for (int i = 0; i < 8; i++) { sc[i][0]=0.f; sc[i][1]=0.f; sc[i][2]=0.f; sc[i][3]=0.f; }
        const uint32_t fbase = sb + OFF_F + bf*10240;
        #pragma unroll
        for (int pass = 0; pass < 3; pass++) {
            const uint32_t fb0 = fbase + (pass == 1 ? 5120 : 0);
            const uint32_t (*A)[4] = (pass == 2) ? gl : gh;
            #pragma unroll
            for (int ks = 0; ks < 2; ks++) {
                #pragma unroll
                for (int np = 0; np < 4; np++) {
                    uint32_t fr[4];
                    ldm_x4(fr, fb0 + (np*16 + bHi8 + bR)*80 + ks*32 + bK);
                    mma_bf16(sc[2*np],   A[ks], fr + 0);
                    mma_bf16(sc[2*np+1], A[ks], fr + 2);
                }
            }
        }

        // ---- online softmax ----
        float tmaxA = -1e30f, tmaxB = -1e30f;
        #pragma unroll
        for (int nt = 0; nt < 8; nt++) {
            tmaxA = fmaxf(tmaxA, fmaxf(sc[nt][0], sc[nt][1]));
            tmaxB = fmaxf(tmaxB, fmaxf(sc[nt][2], sc[nt][3]));
        }
        tmaxA = fmaxf(tmaxA, __shfl_xor_sync(0xffffffffu, tmaxA, 1));
        tmaxA = fmaxf(tmaxA, __shfl_xor_sync(0xffffffffu, tmaxA, 2));
        tmaxB = fmaxf(tmaxB, __shfl_xor_sync(0xffffffffu, tmaxB, 1));
        tmaxB = fmaxf(tmaxB, __shfl_xor_sync(0xffffffffu, tmaxB, 2));
        float mnA = fmaxf(mA, tmaxA), mnB = fmaxf(mB, tmaxB);
        float scA = __expf(mA - mnA), scB = __expf(mB - mnB);

        uint32_t pf[16];
        float sumA = 0.f, sumB = 0.f;
        #pragma unroll
        for (int nt = 0; nt < 8; nt++) {
            float p0 = __expf(sc[nt][0] - mnA);
            float p1 = __expf(sc[nt][1] - mnA);
            float p2 = __expf(sc[nt][2] - mnB);
            float p3 = __expf(sc[nt][3] - mnB);
            sumA += p0 + p1; sumB += p2 + p3;
            int ks = nt >> 1, j = (nt & 1) * 2;
            pf[ks*4 + j]     = pack_f16(p0, p1);
            pf[ks*4 + j + 1] = pack_f16(p2, p3);
        }
        sumA += __shfl_xor_sync(0xffffffffu, sumA, 1);
        sumA += __shfl_xor_sync(0xffffffffu, sumA, 2);
        sumB += __shfl_xor_sync(0xffffffffu, sumB, 1);
        sumB += __shfl_xor_sync(0xffffffffu, sumB, 2);
        lA = lA*scA + sumA;  lB = lB*scB + sumB;
        mA = mnA;  mB = mnB;
        #pragma unroll
        for (int nt = 0; nt < 16; nt++) {
            accO[nt][0] *= scA; accO[nt][1] *= scA;
            accO[nt][2] *= scB; accO[nt][3] *= scB;
        }

        // ---- O += P . V  (fp16 x fp16) ----
        const uint32_t vbase = sb + OFF_V + bf*36864 + (wc*128)*144;
        #pragma unroll
        for (int ks = 0; ks < 4; ks++) {
            #pragma unroll
            for (int np = 0; np < 8; np++) {
                uint32_t vr[4];
                ldm_x4(vr, vbase + (np*16 + bHi8 + bR)*144 + ks*32 + bK);
                mma_f16(accO[2*np],   pf + ks*4, vr + 0);
                mma_f16(accO[2*np+1], pf + ks*4, vr + 2);
            }
        }

        __syncthreads();          // everyone done reading buf bf
        if (kt < 62) {
            prefetch_tile(sb, bf, b, kt + 2, tid);
            CP_COMMIT();
            CP_WAIT(1);
        } else {
            CP_WAIT(0);
        }
        __syncthreads();          // next tile visible to all
    }

    // ---- epilogue ----
    const float invA = 1.0f / lA, invB = 1.0f / lB;
    const size_t rA = qbase + wq*16 + (lane >> 2);
    const size_t rB = rA + 8;
    #pragma unroll
    for (int nt = 0; nt < 16; nt++) {
        int c = wc*128 + nt*8 + (lane & 3)*2;
        float2 vA = { accO[nt][0]*invA, accO[nt][1]*invA };
        float2 vB = { accO[nt][2]*invB, accO[nt][3]*invB };
        *(float2*)(g_o + rA*CDIM + c) = vA;
        *(float2*)(g_o + rB*CDIM + c) = vB;
    }
}

// ---------------------------------------------------------------------------
extern "C" void kernel_launch(void* const* d_in, const int* in_sizes, int n_in,
                              void* d_out, int out_size) {
    const float* x     = (const float*)d_in[0];
    const float* Wf    = (const float*)d_in[1];
    const float* bf    = (const float*)d_in[2];
    const float* Wg    = (const float*)d_in[3];
    const float* bg    = (const float*)d_in[4];
    const float* Wh    = (const float*)d_in[5];
    const float* bh    = (const float*)d_in[6];
    const float* Wo    = (const float*)d_in[7];
    const float* bo    = (const float*)d_in[8];
    const float* gamma = (const float*)d_in[9];
    float*       out   = (float*)d_out;

    const int smem_proj = (64*68 + 256*68) * 4;  // 87040
    const int smem_gemm = (64*68 + 64*272) * 4;  // 87040

    cudaFuncSetAttribute(proj_fg,        cudaFuncAttributeMaxDynamicSharedMemorySize, smem_proj);
    cudaFuncSetAttribute(gemm256<false>, cudaFuncAttributeMaxDynamicSharedMemorySize, smem_gemm);
    cudaFuncSetAttribute(gemm256<true>,  cudaFuncAttributeMaxDynamicSharedMemorySize, smem_gemm);
    cudaFuncSetAttribute(attn_hmma,      cudaFuncAttributeMaxDynamicSharedMemorySize, SMEM_ATT);

    proj_fg<<<512, 256, smem_proj>>>(x, Wf, bf, Wg, bg);
    gemm256<false><<<512, 256, smem_gemm>>>(x, Wh, bh, nullptr, nullptr, nullptr);
    attn_hmma<<<512, 256, SMEM_ATT>>>();
    gemm256<true><<<512, 256, smem_gemm>>>(nullptr, Wo, bo, gamma, x, out);
}

// round 4
// speedup vs baseline: 4.9554x; 1.4250x over previous
#include <cuda_runtime.h>
#include <cuda_bf16.h>
#include <cuda_fp16.h>
#include <cstdint>
#include <math.h>

#define BATCH 8
#define NPIX  4096
#define CDIM  256
#define CKDIM 32
#define ROWS  (BATCH*NPIX)   // 32768
#define NPRE  320            // 32 f | 32 g | 256 h

// ---------------- scratch (allocation-free) ----------------
__device__ __align__(16) __nv_bfloat16 g_x_hi[ROWS*CDIM];
__device__ __align__(16) __nv_bfloat16 g_x_lo[ROWS*CDIM];
__device__ __align__(16) __nv_bfloat16 g_Wpre_hi[NPRE*CDIM];  // [n][k]
__device__ __align__(16) __nv_bfloat16 g_Wpre_lo[NPRE*CDIM];
__device__ __align__(16) __nv_bfloat16 g_Wo_hi[CDIM*CDIM];    // [n][k]
__device__ __align__(16) __nv_bfloat16 g_Wo_lo[CDIM*CDIM];
__device__ __align__(16) __nv_bfloat16 g_f_hi[ROWS*CKDIM];
__device__ __align__(16) __nv_bfloat16 g_f_lo[ROWS*CKDIM];
__device__ __align__(16) __nv_bfloat16 g_g_hi[ROWS*CKDIM];
__device__ __align__(16) __nv_bfloat16 g_g_lo[ROWS*CKDIM];
__device__ __align__(16) __half       g_hV [ROWS*CDIM];       // V: [row][c] fp16
__device__ __align__(16) __nv_bfloat16 g_o_hi[ROWS*CDIM];
__device__ __align__(16) __nv_bfloat16 g_o_lo[ROWS*CDIM];

// ---------------- PTX helpers ----------------
__device__ __forceinline__ uint32_t smem_u32(const void* p) {
    uint32_t a;
    asm("{ .reg .u64 t; cvta.to.shared.u64 t, %1; cvt.u32.u64 %0, t; }" : "=r"(a) : "l"(p));
    return a;
}
#define CP_ASYNC16(dst, src) \
    asm volatile("cp.async.cg.shared.global [%0], [%1], 16;" :: "r"(dst), "l"(src))
#define CP_COMMIT() asm volatile("cp.async.commit_group;" ::: "memory")
#define CP_WAIT(n)  asm volatile("cp.async.wait_group %0;" :: "n"(n) : "memory")

__device__ __forceinline__ void ldm_x4(uint32_t r[4], uint32_t addr) {
    asm volatile("ldmatrix.sync.aligned.m8n8.x4.shared.b16 {%0,%1,%2,%3}, [%4];"
                 : "=r"(r[0]), "=r"(r[1]), "=r"(r[2]), "=r"(r[3]) : "r"(addr));
}
__device__ __forceinline__ void ldm_x4_trans(uint32_t r[4], uint32_t addr) {
    asm volatile("ldmatrix.sync.aligned.m8n8.x4.trans.shared.b16 {%0,%1,%2,%3}, [%4];"
                 : "=r"(r[0]), "=r"(r[1]), "=r"(r[2]), "=r"(r[3]) : "r"(addr));
}
__device__ __forceinline__ void mma_bf16(float c[4], const uint32_t a[4], const uint32_t* b) {
    asm volatile("mma.sync.aligned.m16n8k16.row.col.f32.bf16.bf16.f32 "
                 "{%0,%1,%2,%3}, {%4,%5,%6,%7}, {%8,%9}, {%0,%1,%2,%3};"
                 : "+f"(c[0]), "+f"(c[1]), "+f"(c[2]), "+f"(c[3])
                 : "r"(a[0]), "r"(a[1]), "r"(a[2]), "r"(a[3]), "r"(b[0]), "r"(b[1]));
}
__device__ __forceinline__ void mma_f16(float c[4], const uint32_t a[4], const uint32_t* b) {
    asm volatile("mma.sync.aligned.m16n8k16.row.col.f32.f16.f16.f32 "
                 "{%0,%1,%2,%3}, {%4,%5,%6,%7}, {%8,%9}, {%0,%1,%2,%3};"
                 : "+f"(c[0]), "+f"(c[1]), "+f"(c[2]), "+f"(c[3])
                 : "r"(a[0]), "r"(a[1]), "r"(a[2]), "r"(a[3]), "r"(b[0]), "r"(b[1]));
}
__device__ __forceinline__ uint32_t pack_f16(float lo, float hi) {
    uint32_t d;
    asm("cvt.rn.f16x2.f32 %0, %1, %2;" : "=r"(d) : "f"(hi), "f"(lo));
    return d;
}
__device__ __forceinline__ uint32_t pack_bf16(__nv_bfloat16 a, __nv_bfloat16 b) {
    __nv_bfloat162 t(a, b);
    return *reinterpret_cast<uint32_t*>(&t);
}
__device__ __forceinline__ void split_bf16(float v, __nv_bfloat16& h, __nv_bfloat16& l) {
    h = __float2bfloat16(v);
    l = __float2bfloat16(v - __bfloat162float(h));
}

// ---------------------------------------------------------------------------
// Kernel 0: setup — split x, build transposed split weights
// ---------------------------------------------------------------------------
#define XPAIRS (ROWS*CDIM/2)       // 4194304
#define WPREN  (NPRE*CDIM)         // 81920
#define WON    (CDIM*CDIM)         // 65536
__global__ __launch_bounds__(256) void setup_k(const float* __restrict__ x,
        const float* __restrict__ Wf, const float* __restrict__ Wg,
        const float* __restrict__ Wh, const float* __restrict__ Wo) {
    int id = blockIdx.x*256 + threadIdx.x;
    if (id < XPAIRS) {
        float2 v = *(const float2*)(x + (size_t)id*2);
        __nv_bfloat16 h0, l0, h1, l1;
        split_bf16(v.x, h0, l0); split_bf16(v.y, h1, l1);
        *(uint32_t*)&g_x_hi[(size_t)id*2] = pack_bf16(h0, h1);
        *(uint32_t*)&g_x_lo[(size_t)id*2] = pack_bf16(l0, l1);
    } else if (id < XPAIRS + WPREN) {
        int i = id - XPAIRS;
        int n = i >> 8, k = i & 255;
        float v;
        if      (n < 32) v = Wf[k*CKDIM + n];
        else if (n < 64) v = Wg[k*CKDIM + (n-32)];
        else             v = Wh[k*CDIM + (n-64)];
        __nv_bfloat16 h, l; split_bf16(v, h, l);
        g_Wpre_hi[i] = h; g_Wpre_lo[i] = l;
    } else if (id < XPAIRS + WPREN + WON) {
        int i = id - XPAIRS - WPREN;
        int n = i >> 8, k = i & 255;
        __nv_bfloat16 h, l; split_bf16(Wo[k*CDIM + n], h, l);
        g_Wo_hi[i] = h; g_Wo_lo[i] = l;
    }
}

// ---------------------------------------------------------------------------
// Kernel 1: fused pre-projection HMMA GEMM.  M=32768 (CTA 64), N=320, K=256.
// 8 warps = 4M(16 rows) x 4N(80 cols).  3-pass split-bf16.
// Outputs: f/g split-bf16, V fp16 [row][c].
// ---------------------------------------------------------------------------
#define P1_AHI 0
#define P1_ALO 9216            // 64*144
#define P1_WHI 18432
#define P1_WLO 64512           // +320*144
#define P1_SMEM 110592

__global__ __launch_bounds__(256) void pre_gemm(
        const float* __restrict__ bfv, const float* __restrict__ bgv,
        const float* __restrict__ bhv) {
    extern __shared__ char smc[];
    const uint32_t sb = smem_u32(smc);
    const int tid  = threadIdx.x;
    const int lane = tid & 31;
    const int wid  = tid >> 5;
    const int wm   = wid & 3;       // 16-row group
    const int wn   = wid >> 2 ? 0 : 0;  // placeholder
    const int wN   = (wid >> 2) | ((wid & 3) & 0); // unused
    // warp mapping: wm = wid & 3 (M), wnn = wid >> 2 in {0,1}? Need 4 N groups:
    // use: wmm = wid >> 2 (0..1) * 32 rows?  -> redo: 8 warps = 2M(32) x 4N(80)
    const int wm2  = wid & 1;       // M half: 2 x 32 rows? no...
    // Final mapping: wM = wid % 4 -> rows wM*16 ; wNg = wid / 4 -> cols wNg*160
    const int wM  = wid & 3;
    const int wNg = wid >> 2;       // 0..1, each 160 cols (20 n8-tiles)
    const int row0 = blockIdx.x * 64;

    const int aRow = lane & 15;
    const int aK   = (lane >> 4) * 16;
    const int bR   = lane & 7;
    const int bHi8 = (lane >> 4) * 8;
    const int bK   = ((lane >> 3) & 1) * 16;

    float acc[20][4];
    #pragma unroll
    for (int i = 0; i < 20; i++) { acc[i][0]=0.f; acc[i][1]=0.f; acc[i][2]=0.f; acc[i][3]=0.f; }

    for (int kc = 0; kc < 4; kc++) {
        __syncthreads();
        // A: 64 rows x 128B (hi+lo)
        #pragma unroll
        for (int i = 0; i < 2; i++) {
            int chunk = tid + i*256;
            int r = chunk >> 3, c = chunk & 7;
            uint32_t d = sb + P1_AHI + r*144 + c*16;
            const char* s = (const char*)g_x_hi + ((size_t)(row0 + r)*CDIM + kc*64 + c*8)*2;
            CP_ASYNC16(d, s);
            CP_ASYNC16(d + P1_ALO, (const char*)g_x_lo + ((size_t)(row0 + r)*CDIM + kc*64 + c*8)*2);
        }
        // W: 320 rows x 128B (hi+lo)
        #pragma unroll
        for (int i = 0; i < 10; i++) {
            int chunk = tid + i*256;
            int r = chunk >> 3, c = chunk & 7;
            uint32_t d = sb + P1_WHI + r*144 + c*16;
            const char* s = (const char*)g_Wpre_hi + ((size_t)r*CDIM + kc*64 + c*8)*2;
            CP_ASYNC16(d, s);
            CP_ASYNC16(d + (P1_WLO - P1_WHI), (const char*)g_Wpre_lo + ((size_t)r*CDIM + kc*64 + c*8)*2);
        }
        CP_COMMIT(); CP_WAIT(0);
        __syncthreads();

        uint32_t ahi[4][4], alo[4][4];
        #pragma unroll
        for (int ks = 0; ks < 4; ks++) {
            uint32_t ad = sb + P1_AHI + (wM*16 + aRow)*144 + ks*32 + aK;
            ldm_x4(ahi[ks], ad);
            ldm_x4(alo[ks], ad + P1_ALO);
        }
        #pragma unroll
        for (int pass = 0; pass < 3; pass++) {
            const uint32_t wb = sb + (pass == 1 ? P1_WLO : P1_WHI);
            #pragma unroll
            for (int ks = 0; ks < 4; ks++) {
                const uint32_t* A = (pass == 2) ? alo[ks] : ahi[ks];
                #pragma unroll
                for (int np = 0; np < 10; np++) {
                    uint32_t wf[4];
                    ldm_x4(wf, wb + (wNg*160 + np*16 + bHi8 + bR)*144 + ks*32 + bK);
                    mma_bf16(acc[2*np],   A, wf + 0);
                    mma_bf16(acc[2*np+1], A, wf + 2);
                }
            }
        }
    }

    // epilogue
    const int r0 = row0 + wM*16 + (lane >> 2);
    #pragma unroll
    for (int nt = 0; nt < 20; nt++) {
        int n = wNg*160 + nt*8 + (lane & 3)*2;
        #pragma unroll
        for (int h = 0; h < 2; h++) {
            int r = r0 + h*8;
            float v0 = acc[nt][2*h], v1 = acc[nt][2*h+1];
            if (n < 32) {
                v0 += bfv[n]; v1 += bfv[n+1];
                __nv_bfloat16 h0,l0,h1,l1; split_bf16(v0,h0,l0); split_bf16(v1,h1,l1);
                *(uint32_t*)&g_f_hi[(size_t)r*CKDIM + n] = pack_bf16(h0,h1);
                *(uint32_t*)&g_f_lo[(size_t)r*CKDIM + n] = pack_bf16(l0,l1);
            } else if (n < 64) {
                v0 += bgv[n-32]; v1 += bgv[n-31];
                __nv_bfloat16 h0,l0,h1,l1; split_bf16(v0,h0,l0); split_bf16(v1,h1,l1);
                *(uint32_t*)&g_g_hi[(size_t)r*CKDIM + (n-32)] = pack_bf16(h0,h1);
                *(uint32_t*)&g_g_lo[(size_t)r*CKDIM + (n-32)] = pack_bf16(l0,l1);
            } else {
                int c = n - 64;
                v0 += bhv[c]; v1 += bhv[c+1];
                *(uint32_t*)&g_hV[(size_t)r*CDIM + c] = pack_f16(v0, v1);
            }
        }
    }
}

// ---------------------------------------------------------------------------
// Kernel 3: output HMMA GEMM.  M=32768 (CTA 64), N=256, K=256.
// A = o (pre-split bf16).  out = gamma*(o Wo + bo) + x
// ---------------------------------------------------------------------------
#define P3_AHI 0
#define P3_ALO 9216
#define P3_WHI 18432
#define P3_WLO 55296           // +256*144
#define P3_SMEM 92160

__global__ __launch_bounds__(256) void out_gemm(
        const float* __restrict__ bov, const float* __restrict__ gammav,
        const float* __restrict__ xres, float* __restrict__ outp) {
    extern __shared__ char smc[];
    const uint32_t sb = smem_u32(smc);
    const int tid  = threadIdx.x;
    const int lane = tid & 31;
    const int wid  = tid >> 5;
    const int wM   = wid & 3;
    const int wNg  = wid >> 2;      // 0..1, 128 cols each
    const int row0 = blockIdx.x * 64;

    const int aRow = lane & 15;
    const int aK   = (lane >> 4) * 16;
    const int bR   = lane & 7;
    const int bHi8 = (lane >> 4) * 8;
    const int bK   = ((lane >> 3) & 1) * 16;

    float acc[16][4];
    #pragma unroll
    for (int i = 0; i < 16; i++) { acc[i][0]=0.f; acc[i][1]=0.f; acc[i][2]=0.f; acc[i][3]=0.f; }

    for (int kc = 0; kc < 4; kc++) {
        __syncthreads();
        #pragma unroll
        for (int i = 0; i < 2; i++) {
            int chunk = tid + i*256;
            int r = chunk >> 3, c = chunk & 7;
            uint32_t d = sb + P3_AHI + r*144 + c*16;
            CP_ASYNC16(d, (const char*)g_o_hi + ((size_t)(row0 + r)*CDIM + kc*64 + c*8)*2);
            CP_ASYNC16(d + P3_ALO, (const char*)g_o_lo + ((size_t)(row0 + r)*CDIM + kc*64 + c*8)*2);
        }
        #pragma unroll
        for (int i = 0; i < 8; i++) {
            int chunk = tid + i*256;
            int r = chunk >> 3, c = chunk & 7;
            uint32_t d = sb + P3_WHI + r*144 + c*16;
            CP_ASYNC16(d, (const char*)g_Wo_hi + ((size_t)r*CDIM + kc*64 + c*8)*2);
            CP_ASYNC16(d + (P3_WLO - P3_WHI), (const char*)g_Wo_lo + ((size_t)r*CDIM + kc*64 + c*8)*2);
        }
        CP_COMMIT(); CP_WAIT(0);
        __syncthreads();

        uint32_t ahi[4][4], alo[4][4];
        #pragma unroll
        for (int ks = 0; ks < 4; ks++) {
            uint32_t ad = sb + P3_AHI + (wM*16 + aRow)*144 + ks*32 + aK;
            ldm_x4(ahi[ks], ad);
            ldm_x4(alo[ks], ad + P3_ALO);
        }
        #pragma unroll
        for (int pass = 0; pass < 3; pass++) {
            const uint32_t wb = sb + (pass == 1 ? P3_WLO : P3_WHI);
            #pragma unroll
            for (int ks = 0; ks < 4; ks++) {
                const uint32_t* A = (pass == 2) ? alo[ks] : ahi[ks];
                #pragma unroll
                for (int np = 0; np < 8; np++) {
                    uint32_t wf[4];
                    ldm_x4(wf, wb + (wNg*128 + np*16 + bHi8 + bR)*144 + ks*32 + bK);
                    mma_bf16(acc[2*np],   A, wf + 0);
                    mma_bf16(acc[2*np+1], A, wf + 2);
                }
            }
        }
    }

    const float gam = gammav[0];
    const int r0 = row0 + wM*16 + (lane >> 2);
    #pragma unroll
    for (int nt = 0; nt < 16; nt++) {
        int n = wNg*128 + nt*8 + (lane & 3)*2;
        #pragma unroll
        for (int h = 0; h < 2; h++) {
            int r = r0 + h*8;
            float2 xr = *(const float2*)(xres + (size_t)r*CDIM + n);
            float2 o;
            o.x = gam*(acc[nt][2*h]   + bov[n])   + xr.x;
            o.y = gam*(acc[nt][2*h+1] + bov[n+1]) + xr.y;
            *(float2*)(outp + (size_t)r*CDIM + n) = o;
        }
    }
}

// ---------------------------------------------------------------------------
// Kernel 2: HMMA flash attention.  V natural layout [row][c] fp16,
// PV B-frags via ldmatrix.trans.  Epilogue writes split-bf16 o.
// ---------------------------------------------------------------------------
#define OFF_G  0                     // 2x 5120 (hi/lo)
#define OFF_F  10240                 // 2 bufs x (hi 5120 + lo 5120)
#define OFF_V  (OFF_F + 2*10240)     // 2 bufs x 64*528
#define SMEM_ATT (OFF_V + 2*33792)   // 98304 B

__device__ __forceinline__ void prefetch_tile(uint32_t sb, int bf, int b, int kt, int tid) {
    const size_t kbase = (size_t)b*NPIX + (size_t)kt*64;
    // F (bf16 hi/lo): 64 rows x 64B
    int fr = tid >> 2, fc = tid & 3;
    uint32_t fd = sb + OFF_F + bf*10240 + fr*80 + fc*16;
    CP_ASYNC16(fd,        (const char*)g_f_hi + ((kbase + fr)*CKDIM + fc*8)*2);
    CP_ASYNC16(fd + 5120, (const char*)g_f_lo + ((kbase + fr)*CKDIM + fc*8)*2);
    // V (fp16): 64 rows x 512B, smem stride 528
    #pragma unroll
    for (int i = 0; i < 8; i++) {
        int chunk = tid + i*256;
        int vr = chunk >> 5, vc = chunk & 31;
        uint32_t vd = sb + OFF_V + bf*33792 + vr*528 + vc*16;
        CP_ASYNC16(vd, (const char*)g_hV + ((kbase + vr)*CDIM + vc*8)*2);
    }
}

__global__ __launch_bounds__(256) void attn_hmma() {
    extern __shared__ char smc[];
    const uint32_t sb = smem_u32(smc);
    const int tid  = threadIdx.x;
    const int lane = tid & 31;
    const int wid  = tid >> 5;
    const int wq   = wid & 3;      // 16 q-rows
    const int wc   = wid >> 2;     // 128 c-cols
    const int b    = blockIdx.x >> 6;
    const int qt   = blockIdx.x & 63;
    const size_t qbase = (size_t)b*NPIX + qt*64;

    {
        int gr = tid >> 2, gc = tid & 3;
        uint32_t gd = sb + OFF_G + gr*80 + gc*16;
        CP_ASYNC16(gd,        (const char*)g_g_hi + ((qbase + gr)*CKDIM + gc*8)*2);
        CP_ASYNC16(gd + 5120, (const char*)g_g_lo + ((qbase + gr)*CKDIM + gc*8)*2);
        prefetch_tile(sb, 0, b, 0, tid);
        CP_COMMIT();
        prefetch_tile(sb, 1, b, 1, tid);
        CP_COMMIT();
    }
    CP_WAIT(1);
    __syncthreads();

    const int aRow = lane & 15;
    const int aK   = (lane >> 4) * 16;
    const int bR   = lane & 7;
    const int bHi8 = (lane >> 4) * 8;
    const int bK   = ((lane >> 3) & 1) * 16;
    const int tR   = lane & 15;            // trans: k-row select
    const int tC   = (lane >> 4) * 16;     // trans: c-byte select

    uint32_t gh[2][4], gl[2][4];
    #pragma unroll
    for (int ks = 0; ks < 2; ks++) {
        uint32_t ad = sb + OFF_G + (wq*16 + aRow)*80 + ks*32 + aK;
        ldm_x4(gh[ks], ad);
        ldm_x4(gl[ks], ad + 5120);
    }

    float accO[16][4];
    #pragma unroll
    for (int i = 0; i < 16; i++) { accO[i][0]=0.f; accO[i][1]=0.f; accO[i][2]=0.f; accO[i][3]=0.f; }
    float mA = -1e30f, mB = -1e30f, lA = 0.f, lB = 0.f;

    for (int kt = 0; kt < 64; kt++) {
        const int bf = kt & 1;

        // ---- S = G . F^T (split-bf16) ----
        float sc[8][4];
        #pragma unroll
        for (int i = 0; i < 8; i++) { sc[i][0]=0.f; sc[i][1]=0.f; sc[i][2]=0.f; sc[i][3]=0.f; }
        const uint32_t fbase = sb + OFF_F + bf*10240;
        #pragma unroll
        for (int pass = 0; pass < 3; pass++) {
            const uint32_t fb0 = fbase + (pass == 1 ? 5120 : 0);
            const uint32_t (*A)[4] = (pass == 2) ? gl : gh;
            #pragma unroll
            for (int ks = 0; ks < 2; ks++) {
                #pragma unroll
                for (int np = 0; np < 4; np++) {
                    uint32_t fr[4];
                    ldm_x4(fr, fb0 + (np*16 + bHi8 + bR)*80 + ks*32 + bK);
                    mma_bf16(sc[2*np],   A[ks], fr + 0);
                    mma_bf16(sc[2*np+1], A[ks], fr + 2);
                }
            }
        }

        // ---- online softmax ----
        float tmaxA = -1e30f, tmaxB = -1e30f;
        #pragma unroll
        for (int nt = 0; nt < 8; nt++) {
            tmaxA = fmaxf(tmaxA, fmaxf(sc[nt][0], sc[nt][1]));
            tmaxB = fmaxf(tmaxB, fmaxf(sc[nt][2], sc[nt][3]));
        }
        tmaxA = fmaxf(tmaxA, __shfl_xor_sync(0xffffffffu, tmaxA, 1));
        tmaxA = fmaxf(tmaxA, __shfl_xor_sync(0xffffffffu, tmaxA, 2));
        tmaxB = fmaxf(tmaxB, __shfl_xor_sync(0xffffffffu, tmaxB, 1));
        tmaxB = fmaxf(tmaxB, __shfl_xor_sync(0xffffffffu, tmaxB, 2));
        float mnA = fmaxf(mA, tmaxA), mnB = fmaxf(mB, tmaxB);
        float scA = __expf(mA - mnA), scB = __expf(mB - mnB);

        uint32_t pf[16];
        float sumA = 0.f, sumB = 0.f;
        #pragma unroll
        for (int nt = 0; nt < 8; nt++) {
            float p0 = __expf(sc[nt][0] - mnA);
            float p1 = __expf(sc[nt][1] - mnA);
            float p2 = __expf(sc[nt][2] - mnB);
            float p3 = __expf(sc[nt][3] - mnB);
            sumA += p0 + p1; sumB += p2 + p3;
            int ks = nt >> 1, j = (nt & 1) * 2;
            pf[ks*4 + j]     = pack_f16(p0, p1);
            pf[ks*4 + j + 1] = pack_f16(p2, p3);
        }
        sumA += __shfl_xor_sync(0xffffffffu, sumA, 1);
        sumA += __shfl_xor_sync(0xffffffffu, sumA, 2);
        sumB += __shfl_xor_sync(0xffffffffu, sumB, 1);
        sumB += __shfl_xor_sync(0xffffffffu, sumB, 2);
        lA = lA*scA + sumA;  lB = lB*scB + sumB;
        mA = mnA;  mB = mnB;
        #pragma unroll
        for (int nt = 0; nt < 16; nt++) {
            accO[nt][0] *= scA; accO[nt][1] *= scA;
            accO[nt][2] *= scB; accO[nt][3] *= scB;
        }

        // ---- O += P . V  (fp16; B-frags via ldmatrix.trans over V[k][c]) ----
        const uint32_t vbase = sb + OFF_V + bf*33792 + wc*256;
        #pragma unroll
        for (int ks = 0; ks < 4; ks++) {
            #pragma unroll
            for (int np = 0; np < 8; np++) {
                uint32_t vr[4];
                ldm_x4_trans(vr, vbase + (ks*16 + tR)*528 + np*32 + tC);
                mma_f16(accO[2*np],   pf + ks*4, vr + 0);
                mma_f16(accO[2*np+1], pf + ks*4, vr + 2);
            }
        }

        __syncthreads();
        if (kt < 62) {
            prefetch_tile(sb, bf, b, kt + 2, tid);
            CP_COMMIT();
            CP_WAIT(1);
        } else {
            CP_WAIT(0);
        }
        __syncthreads();
    }

    // ---- epilogue: split-bf16 o ----
    const float invA = 1.0f / lA, invB = 1.0f / lB;
    const size_t rA = qbase + wq*16 + (lane >> 2);
    const size_t rB = rA + 8;
    #pragma unroll
    for (int nt = 0; nt < 16; nt++) {
        int c = wc*128 + nt*8 + (lane & 3)*2;
        float a0 = accO[nt][0]*invA, a1 = accO[nt][1]*invA;
        float b0 = accO[nt][2]*invB, b1 = accO[nt][3]*invB;
        __nv_bfloat16 h0,l0,h1,l1;
        split_bf16(a0,h0,l0); split_bf16(a1,h1,l1);
        *(uint32_t*)&g_o_hi[rA*CDIM + c] = pack_bf16(h0,h1);
        *(uint32_t*)&g_o_lo[rA*CDIM + c] = pack_bf16(l0,l1);
        split_bf16(b0,h0,l0); split_bf16(b1,h1,l1);
        *(uint32_t*)&g_o_hi[rB*CDIM + c] = pack_bf16(h0,h1);
        *(uint32_t*)&g_o_lo[rB*CDIM + c] = pack_bf16(l0,l1);
    }
}

// ---------------------------------------------------------------------------
extern "C" void kernel_launch(void* const* d_in, const int* in_sizes, int n_in,
                              void* d_out, int out_size) {
    const float* x     = (const float*)d_in[0];
    const float* Wf    = (const float*)d_in[1];
    const float* bf    = (const float*)d_in[2];
    const float* Wg    = (const float*)d_in[3];
    const float* bg    = (const float*)d_in[4];
    const float* Wh    = (const float*)d_in[5];
    const float* bh    = (const float*)d_in[6];
    const float* Wo    = (const float*)d_in[7];
    const float* bo    = (const float*)d_in[8];
    const float* gamma = (const float*)d_in[9];
    float*       out   = (float*)d_out;

    cudaFuncSetAttribute(pre_gemm,  cudaFuncAttributeMaxDynamicSharedMemorySize, P1_SMEM);
    cudaFuncSetAttribute(out_gemm,  cudaFuncAttributeMaxDynamicSharedMemorySize, P3_SMEM);
    cudaFuncSetAttribute(attn_hmma, cudaFuncAttributeMaxDynamicSharedMemorySize, SMEM_ATT);

    const int setup_blocks = (XPAIRS + WPREN + WON + 255) / 256;
    setup_k<<<setup_blocks, 256>>>(x, Wf, Wg, Wh, Wo);
    pre_gemm<<<ROWS/64, 256, P1_SMEM>>>(bf, bg, bh);
    attn_hmma<<<512, 256, SMEM_ATT>>>();
    out_gemm<<<ROWS/64, 256, P3_SMEM>>>(bo, gamma, x, out);
}

// round 5
// speedup vs baseline: 5.0779x; 1.0247x over previous
#include <cuda_runtime.h>
#include <cuda_bf16.h>
#include <cuda_fp16.h>
#include <cstdint>
#include <math.h>

#define BATCH 8
#define NPIX  4096
#define CDIM  256
#define CKDIM 32
#define ROWS  (BATCH*NPIX)   // 32768
#define NPRE  320            // 32 f | 32 g | 256 h

// ---------------- scratch (allocation-free) ----------------
__device__ __align__(16) __nv_bfloat16 g_x_hi[ROWS*CDIM];
__device__ __align__(16) __nv_bfloat16 g_x_lo[ROWS*CDIM];
__device__ __align__(16) __nv_bfloat16 g_Wpre_hi[NPRE*CDIM];  // [n][k]
__device__ __align__(16) __nv_bfloat16 g_Wpre_lo[NPRE*CDIM];
__device__ __align__(16) __nv_bfloat16 g_Wo_hi[CDIM*CDIM];    // [n][k]
__device__ __align__(16) __nv_bfloat16 g_Wo_lo[CDIM*CDIM];
__device__ __align__(16) __nv_bfloat16 g_f_hi[ROWS*CKDIM];
__device__ __align__(16) __nv_bfloat16 g_f_lo[ROWS*CKDIM];
__device__ __align__(16) __nv_bfloat16 g_g_hi[ROWS*CKDIM];
__device__ __align__(16) __nv_bfloat16 g_g_lo[ROWS*CKDIM];
__device__ __align__(16) __half       g_hV [ROWS*CDIM];       // V: [row][c] fp16
__device__ __align__(16) __nv_bfloat16 g_o_hi[ROWS*CDIM];
__device__ __align__(16) __nv_bfloat16 g_o_lo[ROWS*CDIM];

// ---------------- PTX helpers ----------------
__device__ __forceinline__ uint32_t smem_u32(const void* p) {
    uint32_t a;
    asm("{ .reg .u64 t; cvta.to.shared.u64 t, %1; cvt.u32.u64 %0, t; }" : "=r"(a) : "l"(p));
    return a;
}
#define CP_ASYNC16(dst, src) \
    asm volatile("cp.async.cg.shared.global [%0], [%1], 16;" :: "r"(dst), "l"(src))
#define CP_COMMIT() asm volatile("cp.async.commit_group;" ::: "memory")
#define CP_WAIT(n)  asm volatile("cp.async.wait_group %0;" :: "n"(n) : "memory")

__device__ __forceinline__ void ldm_x4(uint32_t r[4], uint32_t addr) {
    asm volatile("ldmatrix.sync.aligned.m8n8.x4.shared.b16 {%0,%1,%2,%3}, [%4];"
                 : "=r"(r[0]), "=r"(r[1]), "=r"(r[2]), "=r"(r[3]) : "r"(addr));
}
__device__ __forceinline__ void ldm_x4_trans(uint32_t r[4], uint32_t addr) {
    asm volatile("ldmatrix.sync.aligned.m8n8.x4.trans.shared.b16 {%0,%1,%2,%3}, [%4];"
                 : "=r"(r[0]), "=r"(r[1]), "=r"(r[2]), "=r"(r[3]) : "r"(addr));
}
__device__ __forceinline__ void mma_bf16(float c[4], const uint32_t a[4], const uint32_t* b) {
    asm volatile("mma.sync.aligned.m16n8k16.row.col.f32.bf16.bf16.f32 "
                 "{%0,%1,%2,%3}, {%4,%5,%6,%7}, {%8,%9}, {%0,%1,%2,%3};"
                 : "+f"(c[0]), "+f"(c[1]), "+f"(c[2]), "+f"(c[3])
                 : "r"(a[0]), "r"(a[1]), "r"(a[2]), "r"(a[3]), "r"(b[0]), "r"(b[1]));
}
__device__ __forceinline__ void mma_f16(float c[4], const uint32_t a[4], const uint32_t* b) {
    asm volatile("mma.sync.aligned.m16n8k16.row.col.f32.f16.f16.f32 "
                 "{%0,%1,%2,%3}, {%4,%5,%6,%7}, {%8,%9}, {%0,%1,%2,%3};"
                 : "+f"(c[0]), "+f"(c[1]), "+f"(c[2]), "+f"(c[3])
                 : "r"(a[0]), "r"(a[1]), "r"(a[2]), "r"(a[3]), "r"(b[0]), "r"(b[1]));
}
__device__ __forceinline__ uint32_t pack_f16(float lo, float hi) {
    uint32_t d;
    asm("cvt.rn.f16x2.f32 %0, %1, %2;" : "=r"(d) : "f"(hi), "f"(lo));
    return d;
}
__device__ __forceinline__ uint32_t pack_bf16(__nv_bfloat16 a, __nv_bfloat16 b) {
    __nv_bfloat162 t(a, b);
    return *reinterpret_cast<uint32_t*>(&t);
}
__device__ __forceinline__ void split_bf16(float v, __nv_bfloat16& h, __nv_bfloat16& l) {
    h = __float2bfloat16(v);
    l = __float2bfloat16(v - __bfloat162float(h));
}

// ---------------------------------------------------------------------------
// Kernel 0: setup — split x, build transposed split weights
// ---------------------------------------------------------------------------
#define XPAIRS (ROWS*CDIM/2)       // 4194304
#define WPREN  (NPRE*CDIM)         // 81920
#define WON    (CDIM*CDIM)         // 65536
__global__ __launch_bounds__(256) void setup_k(const float* __restrict__ x,
        const float* __restrict__ Wf, const float* __restrict__ Wg,
        const float* __restrict__ Wh, const float* __restrict__ Wo) {
    int id = blockIdx.x*256 + threadIdx.x;
    if (id < XPAIRS) {
        float2 v = *(const float2*)(x + (size_t)id*2);
        __nv_bfloat16 h0, l0, h1, l1;
        split_bf16(v.x, h0, l0); split_bf16(v.y, h1, l1);
        *(uint32_t*)&g_x_hi[(size_t)id*2] = pack_bf16(h0, h1);
        *(uint32_t*)&g_x_lo[(size_t)id*2] = pack_bf16(l0, l1);
    } else if (id < XPAIRS + WPREN) {
        int i = id - XPAIRS;
        int n = i >> 8, k = i & 255;
        float v;
        if      (n < 32) v = Wf[k*CKDIM + n];
        else if (n < 64) v = Wg[k*CKDIM + (n-32)];
        else             v = Wh[k*CDIM + (n-64)];
        __nv_bfloat16 h, l; split_bf16(v, h, l);
        g_Wpre_hi[i] = h; g_Wpre_lo[i] = l;
    } else if (id < XPAIRS + WPREN + WON) {
        int i = id - XPAIRS - WPREN;
        int n = i >> 8, k = i & 255;
        __nv_bfloat16 h, l; split_bf16(Wo[k*CDIM + n], h, l);
        g_Wo_hi[i] = h; g_Wo_lo[i] = l;
    }
}

// ---------------------------------------------------------------------------
// Kernel 1: fused pre-projection HMMA GEMM.  M=32768 (CTA 64), N=320, K=256.
// ---------------------------------------------------------------------------
#define P1_AHI 0
#define P1_ALO 9216            // 64*144
#define P1_WHI 18432
#define P1_WLO 64512           // +320*144
#define P1_SMEM 110592

__global__ __launch_bounds__(256) void pre_gemm(
        const float* __restrict__ bfv, const float* __restrict__ bgv,
        const float* __restrict__ bhv) {
    extern __shared__ char smc[];
    const uint32_t sb = smem_u32(smc);
    const int tid  = threadIdx.x;
    const int lane = tid & 31;
    const int wid  = tid >> 5;
    const int wM  = wid & 3;
    const int wNg = wid >> 2;       // 0..1, each 160 cols
    const int row0 = blockIdx.x * 64;

    const int aRow = lane & 15;
    const int aK   = (lane >> 4) * 16;
    const int bR   = lane & 7;
    const int bHi8 = (lane >> 4) * 8;
    const int bK   = ((lane >> 3) & 1) * 16;

    float acc[20][4];
    #pragma unroll
    for (int i = 0; i < 20; i++) { acc[i][0]=0.f; acc[i][1]=0.f; acc[i][2]=0.f; acc[i][3]=0.f; }

    for (int kc = 0; kc < 4; kc++) {
        __syncthreads();
        #pragma unroll
        for (int i = 0; i < 2; i++) {
            int chunk = tid + i*256;
            int r = chunk >> 3, c = chunk & 7;
            uint32_t d = sb + P1_AHI + r*144 + c*16;
            CP_ASYNC16(d, (const char*)g_x_hi + ((size_t)(row0 + r)*CDIM + kc*64 + c*8)*2);
            CP_ASYNC16(d + P1_ALO, (const char*)g_x_lo + ((size_t)(row0 + r)*CDIM + kc*64 + c*8)*2);
        }
        #pragma unroll
        for (int i = 0; i < 10; i++) {
            int chunk = tid + i*256;
            int r = chunk >> 3, c = chunk & 7;
            uint32_t d = sb + P1_WHI + r*144 + c*16;
            CP_ASYNC16(d, (const char*)g_Wpre_hi + ((size_t)r*CDIM + kc*64 + c*8)*2);
            CP_ASYNC16(d + (P1_WLO - P1_WHI), (const char*)g_Wpre_lo + ((size_t)r*CDIM + kc*64 + c*8)*2);
        }
        CP_COMMIT(); CP_WAIT(0);
        __syncthreads();

        uint32_t ahi[4][4], alo[4][4];
        #pragma unroll
        for (int ks = 0; ks < 4; ks++) {
            uint32_t ad = sb + P1_AHI + (wM*16 + aRow)*144 + ks*32 + aK;
            ldm_x4(ahi[ks], ad);
            ldm_x4(alo[ks], ad + P1_ALO);
        }
        #pragma unroll
        for (int pass = 0; pass < 3; pass++) {
            const uint32_t wb = sb + (pass == 1 ? P1_WLO : P1_WHI);
            #pragma unroll
            for (int ks = 0; ks < 4; ks++) {
                const uint32_t* A = (pass == 2) ? alo[ks] : ahi[ks];
                #pragma unroll
                for (int np = 0; np < 10; np++) {
                    uint32_t wf[4];
                    ldm_x4(wf, wb + (wNg*160 + np*16 + bHi8 + bR)*144 + ks*32 + bK);
                    mma_bf16(acc[2*np],   A, wf + 0);
                    mma_bf16(acc[2*np+1], A, wf + 2);
                }
            }
        }
    }

    const int r0 = row0 + wM*16 + (lane >> 2);
    #pragma unroll
    for (int nt = 0; nt < 20; nt++) {
        int n = wNg*160 + nt*8 + (lane & 3)*2;
        #pragma unroll
        for (int h = 0; h < 2; h++) {
            int r = r0 + h*8;
            float v0 = acc[nt][2*h], v1 = acc[nt][2*h+1];
            if (n < 32) {
                v0 += bfv[n]; v1 += bfv[n+1];
                __nv_bfloat16 h0,l0,h1,l1; split_bf16(v0,h0,l0); split_bf16(v1,h1,l1);
                *(uint32_t*)&g_f_hi[(size_t)r*CKDIM + n] = pack_bf16(h0,h1);
                *(uint32_t*)&g_f_lo[(size_t)r*CKDIM + n] = pack_bf16(l0,l1);
            } else if (n < 64) {
                v0 += bgv[n-32]; v1 += bgv[n-31];
                __nv_bfloat16 h0,l0,h1,l1; split_bf16(v0,h0,l0); split_bf16(v1,h1,l1);
                *(uint32_t*)&g_g_hi[(size_t)r*CKDIM + (n-32)] = pack_bf16(h0,h1);
                *(uint32_t*)&g_g_lo[(size_t)r*CKDIM + (n-32)] = pack_bf16(l0,l1);
            } else {
                int c = n - 64;
                v0 += bhv[c]; v1 += bhv[c+1];
                *(uint32_t*)&g_hV[(size_t)r*CDIM + c] = pack_f16(v0, v1);
            }
        }
    }
}

// ---------------------------------------------------------------------------
// Kernel 3: output HMMA GEMM.  out = gamma*(o Wo + bo) + x
// ---------------------------------------------------------------------------
#define P3_AHI 0
#define P3_ALO 9216
#define P3_WHI 18432
#define P3_WLO 55296
#define P3_SMEM 92160

__global__ __launch_bounds__(256) void out_gemm(
        const float* __restrict__ bov, const float* __restrict__ gammav,
        const float* __restrict__ xres, float* __restrict__ outp) {
    extern __shared__ char smc[];
    const uint32_t sb = smem_u32(smc);
    const int tid  = threadIdx.x;
    const int lane = tid & 31;
    const int wid  = tid >> 5;
    const int wM   = wid & 3;
    const int wNg  = wid >> 2;
    const int row0 = blockIdx.x * 64;

    const int aRow = lane & 15;
    const int aK   = (lane >> 4) * 16;
    const int bR   = lane & 7;
    const int bHi8 = (lane >> 4) * 8;
    const int bK   = ((lane >> 3) & 1) * 16;

    float acc[16][4];
    #pragma unroll
    for (int i = 0; i < 16; i++) { acc[i][0]=0.f; acc[i][1]=0.f; acc[i][2]=0.f; acc[i][3]=0.f; }

    for (int kc = 0; kc < 4; kc++) {
        __syncthreads();
        #pragma unroll
        for (int i = 0; i < 2; i++) {
            int chunk = tid + i*256;
            int r = chunk >> 3, c = chunk & 7;
            uint32_t d = sb + P3_AHI + r*144 + c*16;
            CP_ASYNC16(d, (const char*)g_o_hi + ((size_t)(row0 + r)*CDIM + kc*64 + c*8)*2);
            CP_ASYNC16(d + P3_ALO, (const char*)g_o_lo + ((size_t)(row0 + r)*CDIM + kc*64 + c*8)*2);
        }
        #pragma unroll
        for (int i = 0; i < 8; i++) {
            int chunk = tid + i*256;
            int r = chunk >> 3, c = chunk & 7;
            uint32_t d = sb + P3_WHI + r*144 + c*16;
            CP_ASYNC16(d, (const char*)g_Wo_hi + ((size_t)r*CDIM + kc*64 + c*8)*2);
            CP_ASYNC16(d + (P3_WLO - P3_WHI), (const char*)g_Wo_lo + ((size_t)r*CDIM + kc*64 + c*8)*2);
        }
        CP_COMMIT(); CP_WAIT(0);
        __syncthreads();

        uint32_t ahi[4][4], alo[4][4];
        #pragma unroll
        for (int ks = 0; ks < 4; ks++) {
            uint32_t ad = sb + P3_AHI + (wM*16 + aRow)*144 + ks*32 + aK;
            ldm_x4(ahi[ks], ad);
            ldm_x4(alo[ks], ad + P3_ALO);
        }
        #pragma unroll
        for (int pass = 0; pass < 3; pass++) {
            const uint32_t wb = sb + (pass == 1 ? P3_WLO : P3_WHI);
            #pragma unroll
            for (int ks = 0; ks < 4; ks++) {
                const uint32_t* A = (pass == 2) ? alo[ks] : ahi[ks];
                #pragma unroll
                for (int np = 0; np < 8; np++) {
                    uint32_t wf[4];
                    ldm_x4(wf, wb + (wNg*128 + np*16 + bHi8 + bR)*144 + ks*32 + bK);
                    mma_bf16(acc[2*np],   A, wf + 0);
                    mma_bf16(acc[2*np+1], A, wf + 2);
                }
            }
        }
    }

    const float gam = gammav[0];
    const int r0 = row0 + wM*16 + (lane >> 2);
    #pragma unroll
    for (int nt = 0; nt < 16; nt++) {
        int n = wNg*128 + nt*8 + (lane & 3)*2;
        #pragma unroll
        for (int h = 0; h < 2; h++) {
            int r = r0 + h*8;
            float2 xr = *(const float2*)(xres + (size_t)r*CDIM + n);
            float2 o;
            o.x = gam*(acc[nt][2*h]   + bov[n])   + xr.x;
            o.y = gam*(acc[nt][2*h+1] + bov[n+1]) + xr.y;
            *(float2*)(outp + (size_t)r*CDIM + n) = o;
        }
    }
}

// ---------------------------------------------------------------------------
// Kernel 2: HMMA flash attention with DEFERRED PV.
// At tile t: issue S-MMA(t); then PV-MMA(t-1) interleaved with softmax(t).
// Tensor pipe stays busy during softmax ALU/MUFU work.
// ---------------------------------------------------------------------------
#define OFF_G  0                     // 2x 5120 (hi/lo)
#define OFF_F  10240                 // 2 bufs x (hi 5120 + lo 5120)
#define OFF_V  (OFF_F + 2*10240)     // 2 bufs x 64*528
#define SMEM_ATT (OFF_V + 2*33792)   // 98304 B

__device__ __forceinline__ void prefetch_F(uint32_t sb, int buf, int b, int kt, int tid) {
    const size_t kbase = (size_t)b*NPIX + (size_t)kt*64;
    int fr = tid >> 2, fc = tid & 3;
    uint32_t fd = sb + OFF_F + buf*10240 + fr*80 + fc*16;
    CP_ASYNC16(fd,        (const char*)g_f_hi + ((kbase + fr)*CKDIM + fc*8)*2);
    CP_ASYNC16(fd + 5120, (const char*)g_f_lo + ((kbase + fr)*CKDIM + fc*8)*2);
}
__device__ __forceinline__ void prefetch_V(uint32_t sb, int buf, int b, int kt, int tid) {
    const size_t kbase = (size_t)b*NPIX + (size_t)kt*64;
    #pragma unroll
    for (int i = 0; i < 8; i++) {
        int chunk = tid + i*256;
        int vr = chunk >> 5, vc = chunk & 31;
        uint32_t vd = sb + OFF_V + buf*33792 + vr*528 + vc*16;
        CP_ASYNC16(vd, (const char*)g_hV + ((kbase + vr)*CDIM + vc*8)*2);
    }
}

__global__ __launch_bounds__(256) void attn_hmma() {
    extern __shared__ char smc[];
    const uint32_t sb = smem_u32(smc);
    const int tid  = threadIdx.x;
    const int lane = tid & 31;
    const int wid  = tid >> 5;
    const int wq   = wid & 3;      // 16 q-rows
    const int wc   = wid >> 2;     // 128 c-cols
    const int b    = blockIdx.x >> 6;
    const int qt   = blockIdx.x & 63;
    const size_t qbase = (size_t)b*NPIX + qt*64;

    // prologue: stage G + tile 0 (F0, V0), single group; hard wait
    {
        int gr = tid >> 2, gc = tid & 3;
        uint32_t gd = sb + OFF_G + gr*80 + gc*16;
        CP_ASYNC16(gd,        (const char*)g_g_hi + ((qbase + gr)*CKDIM + gc*8)*2);
        CP_ASYNC16(gd + 5120, (const char*)g_g_lo + ((qbase + gr)*CKDIM + gc*8)*2);
        prefetch_F(sb, 0, b, 0, tid);
        prefetch_V(sb, 0, b, 0, tid);
        CP_COMMIT();
    }
    CP_WAIT(0);
    __syncthreads();

    const int aRow = lane & 15;
    const int aK   = (lane >> 4) * 16;
    const int bR   = lane & 7;
    const int bHi8 = (lane >> 4) * 8;
    const int bK   = ((lane >> 3) & 1) * 16;
    const int tR   = lane & 15;            // trans: k-row select
    const int tC   = (lane >> 4) * 16;     // trans: c-byte select

    uint32_t gh[2][4], gl[2][4];
    #pragma unroll
    for (int ks = 0; ks < 2; ks++) {
        uint32_t ad = sb + OFF_G + (wq*16 + aRow)*80 + ks*32 + aK;
        ldm_x4(gh[ks], ad);
        ldm_x4(gl[ks], ad + 5120);
    }

    float accO[16][4];
    #pragma unroll
    for (int i = 0; i < 16; i++) { accO[i][0]=0.f; accO[i][1]=0.f; accO[i][2]=0.f; accO[i][3]=0.f; }
    float mA = -1e30f, mB = -1e30f, lA = 0.f, lB = 0.f;
    float scPrevA = 1.f, scPrevB = 1.f;
    uint32_t pfPrev[16];

    for (int kt = 0; kt < 64; kt++) {
        const int bf = kt & 1;
        if (kt > 0) { CP_WAIT(1); __syncthreads(); }   // F(kt) ready; V(kt-1) long done

        // ---- S(kt) = G . F^T (split-bf16; Fhi frags shared across gh/gl passes)
        float sc[8][4];
        #pragma unroll
        for (int i = 0; i < 8; i++) { sc[i][0]=0.f; sc[i][1]=0.f; sc[i][2]=0.f; sc[i][3]=0.f; }
        const uint32_t fbase = sb + OFF_F + bf*10240;
        #pragma unroll
        for (int ks = 0; ks < 2; ks++) {
            #pragma unroll
            for (int np = 0; np < 4; np++) {
                uint32_t fr[4];
                ldm_x4(fr, fbase + (np*16 + bHi8 + bR)*80 + ks*32 + bK);
                mma_bf16(sc[2*np],   gh[ks], fr + 0);
                mma_bf16(sc[2*np+1], gh[ks], fr + 2);
                mma_bf16(sc[2*np],   gl[ks], fr + 0);
                mma_bf16(sc[2*np+1], gl[ks], fr + 2);
            }
        }
        #pragma unroll
        for (int ks = 0; ks < 2; ks++) {
            #pragma unroll
            for (int np = 0; np < 4; np++) {
                uint32_t fr[4];
                ldm_x4(fr, fbase + 5120 + (np*16 + bHi8 + bR)*80 + ks*32 + bK);
                mma_bf16(sc[2*np],   gh[ks], fr + 0);
                mma_bf16(sc[2*np+1], gh[ks], fr + 2);
            }
        }

        // ---- prefetch F(kt+1) into the other F buffer (no barrier needed)
        if (kt < 63) { prefetch_F(sb, bf ^ 1, b, kt + 1, tid); CP_COMMIT(); }

        // ---- deferred: rescale accO + PV(kt-1)  [independent of sc(kt)]
        if (kt > 0) {
            #pragma unroll
            for (int nt = 0; nt < 16; nt++) {
                accO[nt][0] *= scPrevA; accO[nt][1] *= scPrevA;
                accO[nt][2] *= scPrevB; accO[nt][3] *= scPrevB;
            }
            const uint32_t vbase = sb + OFF_V + (bf ^ 1)*33792 + wc*256;
            #pragma unroll
            for (int ks = 0; ks < 4; ks++) {
                #pragma unroll
                for (int np = 0; np < 8; np++) {
                    uint32_t vr[4];
                    ldm_x4_trans(vr, vbase + (ks*16 + tR)*528 + np*32 + tC);
                    mma_f16(accO[2*np],   pfPrev + ks*4, vr + 0);
                    mma_f16(accO[2*np+1], pfPrev + ks*4, vr + 2);
                }
            }
        }

        // ---- softmax(kt) — interleaves with the PV MMAs above
        float tmaxA = -1e30f, tmaxB = -1e30f;
        #pragma unroll
        for (int nt = 0; nt < 8; nt++) {
            tmaxA = fmaxf(tmaxA, fmaxf(sc[nt][0], sc[nt][1]));
            tmaxB = fmaxf(tmaxB, fmaxf(sc[nt][2], sc[nt][3]));
        }
        tmaxA = fmaxf(tmaxA, __shfl_xor_sync(0xffffffffu, tmaxA, 1));
        tmaxA = fmaxf(tmaxA, __shfl_xor_sync(0xffffffffu, tmaxA, 2));
        tmaxB = fmaxf(tmaxB, __shfl_xor_sync(0xffffffffu, tmaxB, 1));
        tmaxB = fmaxf(tmaxB, __shfl_xor_sync(0xffffffffu, tmaxB, 2));
        float mnA = fmaxf(mA, tmaxA), mnB = fmaxf(mB, tmaxB);
        float scA = __expf(mA - mnA), scB = __expf(mB - mnB);

        uint32_t pf[16];
        float sumA = 0.f, sumB = 0.f;
        #pragma unroll
        for (int nt = 0; nt < 8; nt++) {
            float p0 = __expf(sc[nt][0] - mnA);
            float p1 = __expf(sc[nt][1] - mnA);
            float p2 = __expf(sc[nt][2] - mnB);
            float p3 = __expf(sc[nt][3] - mnB);
            sumA += p0 + p1; sumB += p2 + p3;
            int ks = nt >> 1, j = (nt & 1) * 2;
            pf[ks*4 + j]     = pack_f16(p0, p1);
            pf[ks*4 + j + 1] = pack_f16(p2, p3);
        }
        sumA += __shfl_xor_sync(0xffffffffu, sumA, 1);
        sumA += __shfl_xor_sync(0xffffffffu, sumA, 2);
        sumB += __shfl_xor_sync(0xffffffffu, sumB, 1);
        sumB += __shfl_xor_sync(0xffffffffu, sumB, 2);
        lA = lA*scA + sumA;  lB = lB*scB + sumB;
        mA = mnA;  mB = mnB;
        scPrevA = scA;  scPrevB = scB;
        #pragma unroll
        for (int i = 0; i < 16; i++) pfPrev[i] = pf[i];

        __syncthreads();   // all warps finished PV reads of V[(kt-1)&1]
        if (kt < 63) { prefetch_V(sb, bf ^ 1, b, kt + 1, tid); CP_COMMIT(); }
    }

    // ---- epilogue: final rescale + PV(63)
    CP_WAIT(0);
    __syncthreads();
    #pragma unroll
    for (int nt = 0; nt < 16; nt++) {
        accO[nt][0] *= scPrevA; accO[nt][1] *= scPrevA;
        accO[nt][2] *= scPrevB; accO[nt][3] *= scPrevB;
    }
    {
        const uint32_t vbase = sb + OFF_V + 1*33792 + wc*256;   // tile 63 -> buf 1
        #pragma unroll
        for (int ks = 0; ks < 4; ks++) {
            #pragma unroll
            for (int np = 0; np < 8; np++) {
                uint32_t vr[4];
                ldm_x4_trans(vr, vbase + (ks*16 + tR)*528 + np*32 + tC);
                mma_f16(accO[2*np],   pfPrev + ks*4, vr + 0);
                mma_f16(accO[2*np+1], pfPrev + ks*4, vr + 2);
            }
        }
    }

    // ---- write split-bf16 o ----
    const float invA = 1.0f / lA, invB = 1.0f / lB;
    const size_t rA = qbase + wq*16 + (lane >> 2);
    const size_t rB = rA + 8;
    #pragma unroll
    for (int nt = 0; nt < 16; nt++) {
        int c = wc*128 + nt*8 + (lane & 3)*2;
        float a0 = accO[nt][0]*invA, a1 = accO[nt][1]*invA;
        float b0 = accO[nt][2]*invB, b1 = accO[nt][3]*invB;
        __nv_bfloat16 h0,l0,h1,l1;
        split_bf16(a0,h0,l0); split_bf16(a1,h1,l1);
        *(uint32_t*)&g_o_hi[rA*CDIM + c] = pack_bf16(h0,h1);
        *(uint32_t*)&g_o_lo[rA*CDIM + c] = pack_bf16(l0,l1);
        split_bf16(b0,h0,l0); split_bf16(b1,h1,l1);
        *(uint32_t*)&g_o_hi[rB*CDIM + c] = pack_bf16(h0,h1);
        *(uint32_t*)&g_o_lo[rB*CDIM + c] = pack_bf16(l0,l1);
    }
}

// ---------------------------------------------------------------------------
extern "C" void kernel_launch(void* const* d_in, const int* in_sizes, int n_in,
                              void* d_out, int out_size) {
    const float* x     = (const float*)d_in[0];
    const float* Wf    = (const float*)d_in[1];
    const float* bf    = (const float*)d_in[2];
    const float* Wg    = (const float*)d_in[3];
    const float* bg    = (const float*)d_in[4];
    const float* Wh    = (const float*)d_in[5];
    const float* bh    = (const float*)d_in[6];
    const float* Wo    = (const float*)d_in[7];
    const float* bo    = (const float*)d_in[8];
    const float* gamma = (const float*)d_in[9];
    float*       out   = (float*)d_out;

    cudaFuncSetAttribute(pre_gemm,  cudaFuncAttributeMaxDynamicSharedMemorySize, P1_SMEM);
    cudaFuncSetAttribute(out_gemm,  cudaFuncAttributeMaxDynamicSharedMemorySize, P3_SMEM);
    cudaFuncSetAttribute(attn_hmma, cudaFuncAttributeMaxDynamicSharedMemorySize, SMEM_ATT);

    const int setup_blocks = (XPAIRS + WPREN + WON + 255) / 256;
    setup_k<<<setup_blocks, 256>>>(x, Wf, Wg, Wh, Wo);
    pre_gemm<<<ROWS/64, 256, P1_SMEM>>>(bf, bg, bh);
    attn_hmma<<<512, 256, SMEM_ATT>>>();
    out_gemm<<<ROWS/64, 256, P3_SMEM>>>(bo, gamma, x, out);
}

// round 6
// speedup vs baseline: 5.7261x; 1.1276x over previous
#include <cuda_runtime.h>
#include <cuda_bf16.h>
#include <cuda_fp16.h>
#include <cstdint>
#include <math.h>

#define BATCH 8
#define NPIX  4096
#define CDIM  256
#define CKDIM 32
#define ROWS  (BATCH*NPIX)   // 32768
#define NPRE  320            // 32 f | 32 g | 256 h

// ---------------- scratch (allocation-free) ----------------
__device__ __align__(16) __nv_bfloat16 g_x_hi[ROWS*CDIM];
__device__ __align__(16) __nv_bfloat16 g_x_lo[ROWS*CDIM];
__device__ __align__(16) __nv_bfloat16 g_Wpre_hi[NPRE*CDIM];  // [n][k]
__device__ __align__(16) __nv_bfloat16 g_Wpre_lo[NPRE*CDIM];
__device__ __align__(16) __nv_bfloat16 g_Wo_hi[CDIM*CDIM];    // [n][k]
__device__ __align__(16) __nv_bfloat16 g_Wo_lo[CDIM*CDIM];
__device__ __align__(16) __nv_bfloat16 g_f_hi[ROWS*CKDIM];
__device__ __align__(16) __nv_bfloat16 g_f_lo[ROWS*CKDIM];
__device__ __align__(16) __nv_bfloat16 g_g_hi[ROWS*CKDIM];
__device__ __align__(16) __nv_bfloat16 g_g_lo[ROWS*CKDIM];
__device__ __align__(16) __half       g_hV [ROWS*CDIM];       // V: [row][c] fp16
__device__ __align__(16) __nv_bfloat16 g_o_hi[ROWS*CDIM];
__device__ __align__(16) __nv_bfloat16 g_o_lo[ROWS*CDIM];

// ---------------- PTX helpers ----------------
__device__ __forceinline__ uint32_t smem_u32(const void* p) {
    uint32_t a;
    asm("{ .reg .u64 t; cvta.to.shared.u64 t, %1; cvt.u32.u64 %0, t; }" : "=r"(a) : "l"(p));
    return a;
}
#define CP_ASYNC16(dst, src) \
    asm volatile("cp.async.cg.shared.global [%0], [%1], 16;" :: "r"(dst), "l"(src))
#define CP_COMMIT() asm volatile("cp.async.commit_group;" ::: "memory")
#define CP_WAIT(n)  asm volatile("cp.async.wait_group %0;" :: "n"(n) : "memory")

__device__ __forceinline__ void ldm_x4(uint32_t r[4], uint32_t addr) {
    asm volatile("ldmatrix.sync.aligned.m8n8.x4.shared.b16 {%0,%1,%2,%3}, [%4];"
                 : "=r"(r[0]), "=r"(r[1]), "=r"(r[2]), "=r"(r[3]) : "r"(addr));
}
__device__ __forceinline__ void ldm_x4_trans(uint32_t r[4], uint32_t addr) {
    asm volatile("ldmatrix.sync.aligned.m8n8.x4.trans.shared.b16 {%0,%1,%2,%3}, [%4];"
                 : "=r"(r[0]), "=r"(r[1]), "=r"(r[2]), "=r"(r[3]) : "r"(addr));
}
__device__ __forceinline__ void mma_bf16(float c[4], const uint32_t a[4], const uint32_t* b) {
    asm volatile("mma.sync.aligned.m16n8k16.row.col.f32.bf16.bf16.f32 "
                 "{%0,%1,%2,%3}, {%4,%5,%6,%7}, {%8,%9}, {%0,%1,%2,%3};"
                 : "+f"(c[0]), "+f"(c[1]), "+f"(c[2]), "+f"(c[3])
                 : "r"(a[0]), "r"(a[1]), "r"(a[2]), "r"(a[3]), "r"(b[0]), "r"(b[1]));
}
__device__ __forceinline__ void mma_f16(float c[4], const uint32_t a[4], const uint32_t* b) {
    asm volatile("mma.sync.aligned.m16n8k16.row.col.f32.f16.f16.f32 "
                 "{%0,%1,%2,%3}, {%4,%5,%6,%7}, {%8,%9}, {%0,%1,%2,%3};"
                 : "+f"(c[0]), "+f"(c[1]), "+f"(c[2]), "+f"(c[3])
                 : "r"(a[0]), "r"(a[1]), "r"(a[2]), "r"(a[3]), "r"(b[0]), "r"(b[1]));
}
__device__ __forceinline__ uint32_t pack_f16(float lo, float hi) {
    uint32_t d;
    asm("cvt.rn.f16x2.f32 %0, %1, %2;" : "=r"(d) : "f"(hi), "f"(lo));
    return d;
}
__device__ __forceinline__ uint32_t pack_bf16(__nv_bfloat16 a, __nv_bfloat16 b) {
    __nv_bfloat162 t(a, b);
    return *reinterpret_cast<uint32_t*>(&t);
}
__device__ __forceinline__ void split_bf16(float v, __nv_bfloat16& h, __nv_bfloat16& l) {
    h = __float2bfloat16(v);
    l = __float2bfloat16(v - __bfloat162float(h));
}

// ---------------------------------------------------------------------------
// Kernel 0: setup — split x, build transposed split weights
// ---------------------------------------------------------------------------
#define XPAIRS (ROWS*CDIM/2)       // 4194304
#define WPREN  (NPRE*CDIM)         // 81920
#define WON    (CDIM*CDIM)         // 65536
__global__ __launch_bounds__(256) void setup_k(const float* __restrict__ x,
        const float* __restrict__ Wf, const float* __restrict__ Wg,
        const float* __restrict__ Wh, const float* __restrict__ Wo) {
    int id = blockIdx.x*256 + threadIdx.x;
    if (id < XPAIRS) {
        float2 v = *(const float2*)(x + (size_t)id*2);
        __nv_bfloat16 h0, l0, h1, l1;
        split_bf16(v.x, h0, l0); split_bf16(v.y, h1, l1);
        *(uint32_t*)&g_x_hi[(size_t)id*2] = pack_bf16(h0, h1);
        *(uint32_t*)&g_x_lo[(size_t)id*2] = pack_bf16(l0, l1);
    } else if (id < XPAIRS + WPREN) {
        int i = id - XPAIRS;
        int n = i >> 8, k = i & 255;
        float v;
        if      (n < 32) v = Wf[k*CKDIM + n];
        else if (n < 64) v = Wg[k*CKDIM + (n-32)];
        else             v = Wh[k*CDIM + (n-64)];
        __nv_bfloat16 h, l; split_bf16(v, h, l);
        g_Wpre_hi[i] = h; g_Wpre_lo[i] = l;
    } else if (id < XPAIRS + WPREN + WON) {
        int i = id - XPAIRS - WPREN;
        int n = i >> 8, k = i & 255;
        __nv_bfloat16 h, l; split_bf16(Wo[k*CDIM + n], h, l);
        g_Wo_hi[i] = h; g_Wo_lo[i] = l;
    }
}

// ---------------------------------------------------------------------------
// Kernel 1: fused pre-projection HMMA GEMM.  M=32768 (CTA 64), N=320, K=256.
// ---------------------------------------------------------------------------
#define P1_AHI 0
#define P1_ALO 9216            // 64*144
#define P1_WHI 18432
#define P1_WLO 64512           // +320*144
#define P1_SMEM 110592

__global__ __launch_bounds__(256, 2) void pre_gemm(
        const float* __restrict__ bfv, const float* __restrict__ bgv,
        const float* __restrict__ bhv) {
    extern __shared__ char smc[];
    const uint32_t sb = smem_u32(smc);
    const int tid  = threadIdx.x;
    const int lane = tid & 31;
    const int wid  = tid >> 5;
    const int wM  = wid & 3;
    const int wNg = wid >> 2;       // 0..1, each 160 cols
    const int row0 = blockIdx.x * 64;

    const int aRow = lane & 15;
    const int aK   = (lane >> 4) * 16;
    const int bR   = lane & 7;
    const int bHi8 = (lane >> 4) * 8;
    const int bK   = ((lane >> 3) & 1) * 16;

    float acc[20][4];
    #pragma unroll
    for (int i = 0; i < 20; i++) { acc[i][0]=0.f; acc[i][1]=0.f; acc[i][2]=0.f; acc[i][3]=0.f; }

    for (int kc = 0; kc < 4; kc++) {
        __syncthreads();
        #pragma unroll
        for (int i = 0; i < 2; i++) {
            int chunk = tid + i*256;
            int r = chunk >> 3, c = chunk & 7;
            uint32_t d = sb + P1_AHI + r*144 + c*16;
            CP_ASYNC16(d, (const char*)g_x_hi + ((size_t)(row0 + r)*CDIM + kc*64 + c*8)*2);
            CP_ASYNC16(d + P1_ALO, (const char*)g_x_lo + ((size_t)(row0 + r)*CDIM + kc*64 + c*8)*2);
        }
        #pragma unroll
        for (int i = 0; i < 10; i++) {
            int chunk = tid + i*256;
            int r = chunk >> 3, c = chunk & 7;
            uint32_t d = sb + P1_WHI + r*144 + c*16;
            CP_ASYNC16(d, (const char*)g_Wpre_hi + ((size_t)r*CDIM + kc*64 + c*8)*2);
            CP_ASYNC16(d + (P1_WLO - P1_WHI), (const char*)g_Wpre_lo + ((size_t)r*CDIM + kc*64 + c*8)*2);
        }
        CP_COMMIT(); CP_WAIT(0);
        __syncthreads();

        uint32_t ahi[4][4], alo[4][4];
        #pragma unroll
        for (int ks = 0; ks < 4; ks++) {
            uint32_t ad = sb + P1_AHI + (wM*16 + aRow)*144 + ks*32 + aK;
            ldm_x4(ahi[ks], ad);
            ldm_x4(alo[ks], ad + P1_ALO);
        }
        #pragma unroll
        for (int pass = 0; pass < 3; pass++) {
            const uint32_t wb = sb + (pass == 1 ? P1_WLO : P1_WHI);
            #pragma unroll
            for (int ks = 0; ks < 4; ks++) {
                const uint32_t* A = (pass == 2) ? alo[ks] : ahi[ks];
                #pragma unroll
                for (int np = 0; np < 10; np++) {
                    uint32_t wf[4];
                    ldm_x4(wf, wb + (wNg*160 + np*16 + bHi8 + bR)*144 + ks*32 + bK);
                    mma_bf16(acc[2*np],   A, wf + 0);
                    mma_bf16(acc[2*np+1], A, wf + 2);
                }
            }
        }
    }

    const int r0 = row0 + wM*16 + (lane >> 2);
    #pragma unroll
    for (int nt = 0; nt < 20; nt++) {
        int n = wNg*160 + nt*8 + (lane & 3)*2;
        #pragma unroll
        for (int h = 0; h < 2; h++) {
            int r = r0 + h*8;
            float v0 = acc[nt][2*h], v1 = acc[nt][2*h+1];
            if (n < 32) {
                v0 += bfv[n]; v1 += bfv[n+1];
                __nv_bfloat16 h0,l0,h1,l1; split_bf16(v0,h0,l0); split_bf16(v1,h1,l1);
                *(uint32_t*)&g_f_hi[(size_t)r*CKDIM + n] = pack_bf16(h0,h1);
                *(uint32_t*)&g_f_lo[(size_t)r*CKDIM + n] = pack_bf16(l0,l1);
            } else if (n < 64) {
                v0 += bgv[n-32]; v1 += bgv[n-31];
                __nv_bfloat16 h0,l0,h1,l1; split_bf16(v0,h0,l0); split_bf16(v1,h1,l1);
                *(uint32_t*)&g_g_hi[(size_t)r*CKDIM + (n-32)] = pack_bf16(h0,h1);
                *(uint32_t*)&g_g_lo[(size_t)r*CKDIM + (n-32)] = pack_bf16(l0,l1);
            } else {
                int c = n - 64;
                v0 += bhv[c]; v1 += bhv[c+1];
                *(uint32_t*)&g_hV[(size_t)r*CDIM + c] = pack_f16(v0, v1);
            }
        }
    }
}

// ---------------------------------------------------------------------------
// Kernel 3: output HMMA GEMM.  out = gamma*(o Wo + bo) + x
// ---------------------------------------------------------------------------
#define P3_AHI 0
#define P3_ALO 9216
#define P3_WHI 18432
#define P3_WLO 55296
#define P3_SMEM 92160

__global__ __launch_bounds__(256, 2) void out_gemm(
        const float* __restrict__ bov, const float* __restrict__ gammav,
        const float* __restrict__ xres, float* __restrict__ outp) {
    extern __shared__ char smc[];
    const uint32_t sb = smem_u32(smc);
    const int tid  = threadIdx.x;
    const int lane = tid & 31;
    const int wid  = tid >> 5;
    const int wM   = wid & 3;
    const int wNg  = wid >> 2;
    const int row0 = blockIdx.x * 64;

    const int aRow = lane & 15;
    const int aK   = (lane >> 4) * 16;
    const int bR   = lane & 7;
    const int bHi8 = (lane >> 4) * 8;
    const int bK   = ((lane >> 3) & 1) * 16;

    float acc[16][4];
    #pragma unroll
    for (int i = 0; i < 16; i++) { acc[i][0]=0.f; acc[i][1]=0.f; acc[i][2]=0.f; acc[i][3]=0.f; }

    for (int kc = 0; kc < 4; kc++) {
        __syncthreads();
        #pragma unroll
        for (int i = 0; i < 2; i++) {
            int chunk = tid + i*256;
            int r = chunk >> 3, c = chunk & 7;
            uint32_t d = sb + P3_AHI + r*144 + c*16;
            CP_ASYNC16(d, (const char*)g_o_hi + ((size_t)(row0 + r)*CDIM + kc*64 + c*8)*2);
            CP_ASYNC16(d + P3_ALO, (const char*)g_o_lo + ((size_t)(row0 + r)*CDIM + kc*64 + c*8)*2);
        }
        #pragma unroll
        for (int i = 0; i < 8; i++) {
            int chunk = tid + i*256;
            int r = chunk >> 3, c = chunk & 7;
            uint32_t d = sb + P3_WHI + r*144 + c*16;
            CP_ASYNC16(d, (const char*)g_Wo_hi + ((size_t)r*CDIM + kc*64 + c*8)*2);
            CP_ASYNC16(d + (P3_WLO - P3_WHI), (const char*)g_Wo_lo + ((size_t)r*CDIM + kc*64 + c*8)*2);
        }
        CP_COMMIT(); CP_WAIT(0);
        __syncthreads();

        uint32_t ahi[4][4], alo[4][4];
        #pragma unroll
        for (int ks = 0; ks < 4; ks++) {
            uint32_t ad = sb + P3_AHI + (wM*16 + aRow)*144 + ks*32 + aK;
            ldm_x4(ahi[ks], ad);
            ldm_x4(alo[ks], ad + P3_ALO);
        }
        #pragma unroll
        for (int pass = 0; pass < 3; pass++) {
            const uint32_t wb = sb + (pass == 1 ? P3_WLO : P3_WHI);
            #pragma unroll
            for (int ks = 0; ks < 4; ks++) {
                const uint32_t* A = (pass == 2) ? alo[ks] : ahi[ks];
                #pragma unroll
                for (int np = 0; np < 8; np++) {
                    uint32_t wf[4];
                    ldm_x4(wf, wb + (wNg*128 + np*16 + bHi8 + bR)*144 + ks*32 + bK);
                    mma_bf16(acc[2*np],   A, wf + 0);
                    mma_bf16(acc[2*np+1], A, wf + 2);
                }
            }
        }
    }

    const float gam = gammav[0];
    const int r0 = row0 + wM*16 + (lane >> 2);
    #pragma unroll
    for (int nt = 0; nt < 16; nt++) {
        int n = wNg*128 + nt*8 + (lane & 3)*2;
        #pragma unroll
        for (int h = 0; h < 2; h++) {
            int r = r0 + h*8;
            float2 xr = *(const float2*)(xres + (size_t)r*CDIM + n);
            float2 o;
            o.x = gam*(acc[nt][2*h]   + bov[n])   + xr.x;
            o.y = gam*(acc[nt][2*h+1] + bov[n+1]) + xr.y;
            *(float2*)(outp + (size_t)r*CDIM + n) = o;
        }
    }
}

// ---------------------------------------------------------------------------
// Kernel 2: HMMA flash attention, 2 CTAs/SM (register-capped).
// Immediate PV; V-wait deferred to mid-tile so V loads overlap S+softmax.
// ---------------------------------------------------------------------------
#define OFF_G  0                     // 2x 5120 (hi/lo)
#define OFF_F  10240                 // 2 bufs x (hi 5120 + lo 5120)
#define OFF_V  (OFF_F + 2*10240)     // 2 bufs x 64*528
#define SMEM_ATT (OFF_V + 2*33792)   // 98304 B

__device__ __forceinline__ void prefetch_F(uint32_t sb, int buf, int b, int kt, int tid) {
    const size_t kbase = (size_t)b*NPIX + (size_t)kt*64;
    int fr = tid >> 2, fc = tid & 3;
    uint32_t fd = sb + OFF_F + buf*10240 + fr*80 + fc*16;
    CP_ASYNC16(fd,        (const char*)g_f_hi + ((kbase + fr)*CKDIM + fc*8)*2);
    CP_ASYNC16(fd + 5120, (const char*)g_f_lo + ((kbase + fr)*CKDIM + fc*8)*2);
}
__device__ __forceinline__ void prefetch_V(uint32_t sb, int buf, int b, int kt, int tid) {
    const size_t kbase = (size_t)b*NPIX + (size_t)kt*64;
    #pragma unroll
    for (int i = 0; i < 8; i++) {
        int chunk = tid + i*256;
        int vr = chunk >> 5, vc = chunk & 31;
        uint32_t vd = sb + OFF_V + buf*33792 + vr*528 + vc*16;
        CP_ASYNC16(vd, (const char*)g_hV + ((kbase + vr)*CDIM + vc*8)*2);
    }
}

__global__ __launch_bounds__(256, 2) void attn_hmma() {
    extern __shared__ char smc[];
    const uint32_t sb = smem_u32(smc);
    const int tid  = threadIdx.x;
    const int lane = tid & 31;
    const int wid  = tid >> 5;
    const int wq   = wid & 3;      // 16 q-rows
    const int wc   = wid >> 2;     // 128 c-cols
    const int b    = blockIdx.x >> 6;
    const int qt   = blockIdx.x & 63;
    const size_t qbase = (size_t)b*NPIX + qt*64;

    // prologue: stage G + tile 0 (F0, V0); hard wait
    {
        int gr = tid >> 2, gc = tid & 3;
        uint32_t gd = sb + OFF_G + gr*80 + gc*16;
        CP_ASYNC16(gd,        (const char*)g_g_hi + ((qbase + gr)*CKDIM + gc*8)*2);
        CP_ASYNC16(gd + 5120, (const char*)g_g_lo + ((qbase + gr)*CKDIM + gc*8)*2);
        prefetch_F(sb, 0, b, 0, tid);
        prefetch_V(sb, 0, b, 0, tid);
        CP_COMMIT();
    }
    CP_WAIT(0);
    __syncthreads();

    const int aRow = lane & 15;
    const int aK   = (lane >> 4) * 16;
    const int bR   = lane & 7;
    const int bHi8 = (lane >> 4) * 8;
    const int bK   = ((lane >> 3) & 1) * 16;
    const int tR   = lane & 15;            // trans: k-row select
    const int tC   = (lane >> 4) * 16;     // trans: c-byte select

    uint32_t gh[2][4], gl[2][4];
    #pragma unroll
    for (int ks = 0; ks < 2; ks++) {
        uint32_t ad = sb + OFF_G + (wq*16 + aRow)*80 + ks*32 + aK;
        ldm_x4(gh[ks], ad);
        ldm_x4(gl[ks], ad + 5120);
    }

    float accO[16][4];
    #pragma unroll
    for (int i = 0; i < 16; i++) { accO[i][0]=0.f; accO[i][1]=0.f; accO[i][2]=0.f; accO[i][3]=0.f; }
    float mA = -1e30f, mB = -1e30f, lA = 0.f, lB = 0.f;

    for (int kt = 0; kt < 64; kt++) {
        const int bf = kt & 1;
        if (kt > 0) { CP_WAIT(1); __syncthreads(); }   // F(kt) ready; V(kt) still in flight

        // ---- S(kt) = G . F^T (split-bf16; F-hi frags shared across gh/gl)
        float sc[8][4];
        #pragma unroll
        for (int i = 0; i < 8; i++) { sc[i][0]=0.f; sc[i][1]=0.f; sc[i][2]=0.f; sc[i][3]=0.f; }
        const uint32_t fbase = sb + OFF_F + bf*10240;
        #pragma unroll
        for (int ks = 0; ks < 2; ks++) {
            #pragma unroll
            for (int np = 0; np < 4; np++) {
                uint32_t fr[4];
                ldm_x4(fr, fbase + (np*16 + bHi8 + bR)*80 + ks*32 + bK);
                mma_bf16(sc[2*np],   gh[ks], fr + 0);
                mma_bf16(sc[2*np+1], gh[ks], fr + 2);
                mma_bf16(sc[2*np],   gl[ks], fr + 0);
                mma_bf16(sc[2*np+1], gl[ks], fr + 2);
            }
        }
        #pragma unroll
        for (int ks = 0; ks < 2; ks++) {
            #pragma unroll
            for (int np = 0; np < 4; np++) {
                uint32_t fr[4];
                ldm_x4(fr, fbase + 5120 + (np*16 + bHi8 + bR)*80 + ks*32 + bK);
                mma_bf16(sc[2*np],   gh[ks], fr + 0);
                mma_bf16(sc[2*np+1], gh[ks], fr + 2);
            }
        }

        // ---- softmax(kt)
        float tmaxA = -1e30f, tmaxB = -1e30f;
        #pragma unroll
        for (int nt = 0; nt < 8; nt++) {
            tmaxA = fmaxf(tmaxA, fmaxf(sc[nt][0], sc[nt][1]));
            tmaxB = fmaxf(tmaxB, fmaxf(sc[nt][2], sc[nt][3]));
        }
        tmaxA = fmaxf(tmaxA, __shfl_xor_sync(0xffffffffu, tmaxA, 1));
        tmaxA = fmaxf(tmaxA, __shfl_xor_sync(0xffffffffu, tmaxA, 2));
        tmaxB = fmaxf(tmaxB, __shfl_xor_sync(0xffffffffu, tmaxB, 1));
        tmaxB = fmaxf(tmaxB, __shfl_xor_sync(0xffffffffu, tmaxB, 2));
        float mnA = fmaxf(mA, tmaxA), mnB = fmaxf(mB, tmaxB);
        float scA = __expf(mA - mnA), scB = __expf(mB - mnB);

        uint32_t pf[16];
        float sumA = 0.f, sumB = 0.f;
        #pragma unroll
        for (int nt = 0; nt < 8; nt++) {
            float p0 = __expf(sc[nt][0] - mnA);
            float p1 = __expf(sc[nt][1] - mnA);
            float p2 = __expf(sc[nt][2] - mnB);
            float p3 = __expf(sc[nt][3] - mnB);
            sumA += p0 + p1; sumB += p2 + p3;
            int ks = nt >> 1, j = (nt & 1) * 2;
            pf[ks*4 + j]     = pack_f16(p0, p1);
            pf[ks*4 + j + 1] = pack_f16(p2, p3);
        }
        sumA += __shfl_xor_sync(0xffffffffu, sumA, 1);
        sumA += __shfl_xor_sync(0xffffffffu, sumA, 2);
        sumB += __shfl_xor_sync(0xffffffffu, sumB, 1);
        sumB += __shfl_xor_sync(0xffffffffu, sumB, 2);
        lA = lA*scA + sumA;  lB = lB*scB + sumB;
        mA = mnA;  mB = mnB;

        // ---- V(kt) must now be resident; sync also fences prior V-buf reads
        CP_WAIT(0);
        __syncthreads();

        // ---- prefetch tile kt+1 (two groups: F first, then V)
        if (kt < 63) {
            prefetch_F(sb, bf ^ 1, b, kt + 1, tid); CP_COMMIT();
            prefetch_V(sb, bf ^ 1, b, kt + 1, tid); CP_COMMIT();
        }

        // ---- rescale + PV(kt)
        #pragma unroll
        for (int nt = 0; nt < 16; nt++) {
            accO[nt][0] *= scA; accO[nt][1] *= scA;
            accO[nt][2] *= scB; accO[nt][3] *= scB;
        }
        const uint32_t vbase = sb + OFF_V + bf*33792 + wc*256;
        #pragma unroll
        for (int ks = 0; ks < 4; ks++) {
            #pragma unroll
            for (int np = 0; np < 8; np++) {
                uint32_t vr[4];
                ldm_x4_trans(vr, vbase + (ks*16 + tR)*528 + np*32 + tC);
                mma_f16(accO[2*np],   pf + ks*4, vr + 0);
                mma_f16(accO[2*np+1], pf + ks*4, vr + 2);
            }
        }
    }

    // ---- write split-bf16 o ----
    const float invA = 1.0f / lA, invB = 1.0f / lB;
    const size_t rA = qbase + wq*16 + (lane >> 2);
    const size_t rB = rA + 8;
    #pragma unroll
    for (int nt = 0; nt < 16; nt++) {
        int c = wc*128 + nt*8 + (lane & 3)*2;
        float a0 = accO[nt][0]*invA, a1 = accO[nt][1]*invA;
        float b0 = accO[nt][2]*invB, b1 = accO[nt][3]*invB;
        __nv_bfloat16 h0,l0,h1,l1;
        split_bf16(a0,h0,l0); split_bf16(a1,h1,l1);
        *(uint32_t*)&g_o_hi[rA*CDIM + c] = pack_bf16(h0,h1);
        *(uint32_t*)&g_o_lo[rA*CDIM + c] = pack_bf16(l0,l1);
        split_bf16(b0,h0,l0); split_bf16(b1,h1,l1);
        *(uint32_t*)&g_o_hi[rB*CDIM + c] = pack_bf16(h0,h1);
        *(uint32_t*)&g_o_lo[rB*CDIM + c] = pack_bf16(l0,l1);
    }
}

// ---------------------------------------------------------------------------
extern "C" void kernel_launch(void* const* d_in, const int* in_sizes, int n_in,
                              void* d_out, int out_size) {
    const float* x     = (const float*)d_in[0];
    const float* Wf    = (const float*)d_in[1];
    const float* bf    = (const float*)d_in[2];
    const float* Wg    = (const float*)d_in[3];
    const float* bg    = (const float*)d_in[4];
    const float* Wh    = (const float*)d_in[5];
    const float* bh    = (const float*)d_in[6];
    const float* Wo    = (const float*)d_in[7];
    const float* bo    = (const float*)d_in[8];
    const float* gamma = (const float*)d_in[9];
    float*       out   = (float*)d_out;

    cudaFuncSetAttribute(pre_gemm,  cudaFuncAttributeMaxDynamicSharedMemorySize, P1_SMEM);
    cudaFuncSetAttribute(out_gemm,  cudaFuncAttributeMaxDynamicSharedMemorySize, P3_SMEM);
    cudaFuncSetAttribute(attn_hmma, cudaFuncAttributeMaxDynamicSharedMemorySize, SMEM_ATT);

    const int setup_blocks = (XPAIRS + WPREN + WON + 255) / 256;
    setup_k<<<setup_blocks, 256>>>(x, Wf, Wg, Wh, Wo);
    pre_gemm<<<ROWS/64, 256, P1_SMEM>>>(bf, bg, bh);
    attn_hmma<<<512, 256, SMEM_ATT>>>();
    out_gemm<<<ROWS/64, 256, P3_SMEM>>>(bo, gamma, x, out);
}

// round 7
// speedup vs baseline: 6.0966x; 1.0647x over previous
#include <cuda_runtime.h>
#include <cuda_bf16.h>
#include <cuda_fp16.h>
#include <cstdint>
#include <math.h>

#define BATCH 8
#define NPIX  4096
#define CDIM  256
#define CKDIM 32
#define ROWS  (BATCH*NPIX)   // 32768
#define NPRE  320            // 32 f | 32 g | 256 h

// ---------------- scratch (allocation-free) ----------------
__device__ __align__(16) __nv_bfloat16 g_x_hi[ROWS*CDIM];
__device__ __align__(16) __nv_bfloat16 g_x_lo[ROWS*CDIM];
__device__ __align__(16) __nv_bfloat16 g_Wpre_hi[NPRE*CDIM];  // [n][k]
__device__ __align__(16) __nv_bfloat16 g_Wpre_lo[NPRE*CDIM];
__device__ __align__(16) __nv_bfloat16 g_Wo_hi[CDIM*CDIM];    // [n][k]
__device__ __align__(16) __nv_bfloat16 g_Wo_lo[CDIM*CDIM];
__device__ __align__(16) __nv_bfloat16 g_f_hi[ROWS*CKDIM];
__device__ __align__(16) __nv_bfloat16 g_f_lo[ROWS*CKDIM];
__device__ __align__(16) __nv_bfloat16 g_g_hi[ROWS*CKDIM];
__device__ __align__(16) __nv_bfloat16 g_g_lo[ROWS*CKDIM];
__device__ __align__(16) __half       g_hV [ROWS*CDIM];       // V: [row][c] fp16
__device__ __align__(16) __nv_bfloat16 g_o_hi[ROWS*CDIM];
__device__ __align__(16) __nv_bfloat16 g_o_lo[ROWS*CDIM];

// ---------------- PTX helpers ----------------
__device__ __forceinline__ uint32_t smem_u32(const void* p) {
    uint32_t a;
    asm("{ .reg .u64 t; cvta.to.shared.u64 t, %1; cvt.u32.u64 %0, t; }" : "=r"(a) : "l"(p));
    return a;
}
#define CP_ASYNC16(dst, src) \
    asm volatile("cp.async.cg.shared.global [%0], [%1], 16;" :: "r"(dst), "l"(src))
#define CP_COMMIT() asm volatile("cp.async.commit_group;" ::: "memory")
#define CP_WAIT(n)  asm volatile("cp.async.wait_group %0;" :: "n"(n) : "memory")

__device__ __forceinline__ void ldm_x4(uint32_t r[4], uint32_t addr) {
    asm volatile("ldmatrix.sync.aligned.m8n8.x4.shared.b16 {%0,%1,%2,%3}, [%4];"
                 : "=r"(r[0]), "=r"(r[1]), "=r"(r[2]), "=r"(r[3]) : "r"(addr));
}
__device__ __forceinline__ void ldm_x4_trans(uint32_t r[4], uint32_t addr) {
    asm volatile("ldmatrix.sync.aligned.m8n8.x4.trans.shared.b16 {%0,%1,%2,%3}, [%4];"
                 : "=r"(r[0]), "=r"(r[1]), "=r"(r[2]), "=r"(r[3]) : "r"(addr));
}
__device__ __forceinline__ void mma_bf16(float c[4], const uint32_t a[4], const uint32_t* b) {
    asm volatile("mma.sync.aligned.m16n8k16.row.col.f32.bf16.bf16.f32 "
                 "{%0,%1,%2,%3}, {%4,%5,%6,%7}, {%8,%9}, {%0,%1,%2,%3};"
                 : "+f"(c[0]), "+f"(c[1]), "+f"(c[2]), "+f"(c[3])
                 : "r"(a[0]), "r"(a[1]), "r"(a[2]), "r"(a[3]), "r"(b[0]), "r"(b[1]));
}
__device__ __forceinline__ void mma_f16(float c[4], const uint32_t a[4], const uint32_t* b) {
    asm volatile("mma.sync.aligned.m16n8k16.row.col.f32.f16.f16.f32 "
                 "{%0,%1,%2,%3}, {%4,%5,%6,%7}, {%8,%9}, {%0,%1,%2,%3};"
                 : "+f"(c[0]), "+f"(c[1]), "+f"(c[2]), "+f"(c[3])
                 : "r"(a[0]), "r"(a[1]), "r"(a[2]), "r"(a[3]), "r"(b[0]), "r"(b[1]));
}
__device__ __forceinline__ uint32_t pack_f16(float lo, float hi) {
    uint32_t d;
    asm("cvt.rn.f16x2.f32 %0, %1, %2;" : "=r"(d) : "f"(hi), "f"(lo));
    return d;
}
__device__ __forceinline__ uint32_t pack_bf16(__nv_bfloat16 a, __nv_bfloat16 b) {
    __nv_bfloat162 t(a, b);
    return *reinterpret_cast<uint32_t*>(&t);
}
__device__ __forceinline__ void split_bf16(float v, __nv_bfloat16& h, __nv_bfloat16& l) {
    h = __float2bfloat16(v);
    l = __float2bfloat16(v - __bfloat162float(h));
}

// ---------------------------------------------------------------------------
// Kernel 0: setup — split x, build transposed split weights
// ---------------------------------------------------------------------------
#define XPAIRS (ROWS*CDIM/2)       // 4194304
#define WPREN  (NPRE*CDIM)         // 81920
#define WON    (CDIM*CDIM)         // 65536
__global__ __launch_bounds__(256) void setup_k(const float* __restrict__ x,
        const float* __restrict__ Wf, const float* __restrict__ Wg,
        const float* __restrict__ Wh, const float* __restrict__ Wo) {
    int id = blockIdx.x*256 + threadIdx.x;
    if (id < XPAIRS) {
        float2 v = *(const float2*)(x + (size_t)id*2);
        __nv_bfloat16 h0, l0, h1, l1;
        split_bf16(v.x, h0, l0); split_bf16(v.y, h1, l1);
        *(uint32_t*)&g_x_hi[(size_t)id*2] = pack_bf16(h0, h1);
        *(uint32_t*)&g_x_lo[(size_t)id*2] = pack_bf16(l0, l1);
    } else if (id < XPAIRS + WPREN) {
        int i = id - XPAIRS;
        int n = i >> 8, k = i & 255;
        float v;
        if      (n < 32) v = Wf[k*CKDIM + n];
        else if (n < 64) v = Wg[k*CKDIM + (n-32)];
        else             v = Wh[k*CDIM + (n-64)];
        __nv_bfloat16 h, l; split_bf16(v, h, l);
        g_Wpre_hi[i] = h; g_Wpre_lo[i] = l;
    } else if (id < XPAIRS + WPREN + WON) {
        int i = id - XPAIRS - WPREN;
        int n = i >> 8, k = i & 255;
        __nv_bfloat16 h, l; split_bf16(Wo[k*CDIM + n], h, l);
        g_Wo_hi[i] = h; g_Wo_lo[i] = l;
    }
}

// ---------------------------------------------------------------------------
// Kernel 1: fused pre-projection HMMA GEMM.  M=32768 (CTA 64), N=320, K=256.
// ---------------------------------------------------------------------------
#define P1_AHI 0
#define P1_ALO 9216            // 64*144
#define P1_WHI 18432
#define P1_WLO 64512           // +320*144
#define P1_SMEM 110592

__global__ __launch_bounds__(256, 2) void pre_gemm(
        const float* __restrict__ bfv, const float* __restrict__ bgv,
        const float* __restrict__ bhv) {
    extern __shared__ char smc[];
    const uint32_t sb = smem_u32(smc);
    const int tid  = threadIdx.x;
    const int lane = tid & 31;
    const int wid  = tid >> 5;
    const int wM  = wid & 3;
    const int wNg = wid >> 2;       // 0..1, each 160 cols
    const int row0 = blockIdx.x * 64;

    const int aRow = lane & 15;
    const int aK   = (lane >> 4) * 16;
    const int bR   = lane & 7;
    const int bHi8 = (lane >> 4) * 8;
    const int bK   = ((lane >> 3) & 1) * 16;

    float acc[20][4];
    #pragma unroll
    for (int i = 0; i < 20; i++) { acc[i][0]=0.f; acc[i][1]=0.f; acc[i][2]=0.f; acc[i][3]=0.f; }

    for (int kc = 0; kc < 4; kc++) {
        __syncthreads();
        #pragma unroll
        for (int i = 0; i < 2; i++) {
            int chunk = tid + i*256;
            int r = chunk >> 3, c = chunk & 7;
            uint32_t d = sb + P1_AHI + r*144 + c*16;
            CP_ASYNC16(d, (const char*)g_x_hi + ((size_t)(row0 + r)*CDIM + kc*64 + c*8)*2);
            CP_ASYNC16(d + P1_ALO, (const char*)g_x_lo + ((size_t)(row0 + r)*CDIM + kc*64 + c*8)*2);
        }
        #pragma unroll
        for (int i = 0; i < 10; i++) {
            int chunk = tid + i*256;
            int r = chunk >> 3, c = chunk & 7;
            uint32_t d = sb + P1_WHI + r*144 + c*16;
            CP_ASYNC16(d, (const char*)g_Wpre_hi + ((size_t)r*CDIM + kc*64 + c*8)*2);
            CP_ASYNC16(d + (P1_WLO - P1_WHI), (const char*)g_Wpre_lo + ((size_t)r*CDIM + kc*64 + c*8)*2);
        }
        CP_COMMIT(); CP_WAIT(0);
        __syncthreads();

        uint32_t ahi[4][4], alo[4][4];
        #pragma unroll
        for (int ks = 0; ks < 4; ks++) {
            uint32_t ad = sb + P1_AHI + (wM*16 + aRow)*144 + ks*32 + aK;
            ldm_x4(ahi[ks], ad);
            ldm_x4(alo[ks], ad + P1_ALO);
        }
        #pragma unroll
        for (int pass = 0; pass < 3; pass++) {
            const uint32_t wb = sb + (pass == 1 ? P1_WLO : P1_WHI);
            #pragma unroll
            for (int ks = 0; ks < 4; ks++) {
                const uint32_t* A = (pass == 2) ? alo[ks] : ahi[ks];
                #pragma unroll
                for (int np = 0; np < 10; np++) {
                    uint32_t wf[4];
                    ldm_x4(wf, wb + (wNg*160 + np*16 + bHi8 + bR)*144 + ks*32 + bK);
                    mma_bf16(acc[2*np],   A, wf + 0);
                    mma_bf16(acc[2*np+1], A, wf + 2);
                }
            }
        }
    }

    const int r0 = row0 + wM*16 + (lane >> 2);
    #pragma unroll
    for (int nt = 0; nt < 20; nt++) {
        int n = wNg*160 + nt*8 + (lane & 3)*2;
        #pragma unroll
        for (int h = 0; h < 2; h++) {
            int r = r0 + h*8;
            float v0 = acc[nt][2*h], v1 = acc[nt][2*h+1];
            if (n < 32) {
                v0 += bfv[n]; v1 += bfv[n+1];
                __nv_bfloat16 h0,l0,h1,l1; split_bf16(v0,h0,l0); split_bf16(v1,h1,l1);
                *(uint32_t*)&g_f_hi[(size_t)r*CKDIM + n] = pack_bf16(h0,h1);
                *(uint32_t*)&g_f_lo[(size_t)r*CKDIM + n] = pack_bf16(l0,l1);
            } else if (n < 64) {
                v0 += bgv[n-32]; v1 += bgv[n-31];
                __nv_bfloat16 h0,l0,h1,l1; split_bf16(v0,h0,l0); split_bf16(v1,h1,l1);
                *(uint32_t*)&g_g_hi[(size_t)r*CKDIM + (n-32)] = pack_bf16(h0,h1);
                *(uint32_t*)&g_g_lo[(size_t)r*CKDIM + (n-32)] = pack_bf16(l0,l1);
            } else {
                int c = n - 64;
                v0 += bhv[c]; v1 += bhv[c+1];
                *(uint32_t*)&g_hV[(size_t)r*CDIM + c] = pack_f16(v0, v1);
            }
        }
    }
}

// ---------------------------------------------------------------------------
// Kernel 3: output HMMA GEMM.  out = gamma*(o Wo + bo) + x
// ---------------------------------------------------------------------------
#define P3_AHI 0
#define P3_ALO 9216
#define P3_WHI 18432
#define P3_WLO 55296
#define P3_SMEM 92160

__global__ __launch_bounds__(256, 2) void out_gemm(
        const float* __restrict__ bov, const float* __restrict__ gammav,
        const float* __restrict__ xres, float* __restrict__ outp) {
    extern __shared__ char smc[];
    const uint32_t sb = smem_u32(smc);
    const int tid  = threadIdx.x;
    const int lane = tid & 31;
    const int wid  = tid >> 5;
    const int wM   = wid & 3;
    const int wNg  = wid >> 2;
    const int row0 = blockIdx.x * 64;

    const int aRow = lane & 15;
    const int aK   = (lane >> 4) * 16;
    const int bR   = lane & 7;
    const int bHi8 = (lane >> 4) * 8;
    const int bK   = ((lane >> 3) & 1) * 16;

    float acc[16][4];
    #pragma unroll
    for (int i = 0; i < 16; i++) { acc[i][0]=0.f; acc[i][1]=0.f; acc[i][2]=0.f; acc[i][3]=0.f; }

    for (int kc = 0; kc < 4; kc++) {
        __syncthreads();
        #pragma unroll
        for (int i = 0; i < 2; i++) {
            int chunk = tid + i*256;
            int r = chunk >> 3, c = chunk & 7;
            uint32_t d = sb + P3_AHI + r*144 + c*16;
            CP_ASYNC16(d, (const char*)g_o_hi + ((size_t)(row0 + r)*CDIM + kc*64 + c*8)*2);
            CP_ASYNC16(d + P3_ALO, (const char*)g_o_lo + ((size_t)(row0 + r)*CDIM + kc*64 + c*8)*2);
        }
        #pragma unroll
        for (int i = 0; i < 8; i++) {
            int chunk = tid + i*256;
            int r = chunk >> 3, c = chunk & 7;
            uint32_t d = sb + P3_WHI + r*144 + c*16;
            CP_ASYNC16(d, (const char*)g_Wo_hi + ((size_t)r*CDIM + kc*64 + c*8)*2);
            CP_ASYNC16(d + (P3_WLO - P3_WHI), (const char*)g_Wo_lo + ((size_t)r*CDIM + kc*64 + c*8)*2);
        }
        CP_COMMIT(); CP_WAIT(0);
        __syncthreads();

        uint32_t ahi[4][4], alo[4][4];
        #pragma unroll
        for (int ks = 0; ks < 4; ks++) {
            uint32_t ad = sb + P3_AHI + (wM*16 + aRow)*144 + ks*32 + aK;
            ldm_x4(ahi[ks], ad);
            ldm_x4(alo[ks], ad + P3_ALO);
        }
        #pragma unroll
        for (int pass = 0; pass < 3; pass++) {
            const uint32_t wb = sb + (pass == 1 ? P3_WLO : P3_WHI);
            #pragma unroll
            for (int ks = 0; ks < 4; ks++) {
                const uint32_t* A = (pass == 2) ? alo[ks] : ahi[ks];
                #pragma unroll
                for (int np = 0; np < 8; np++) {
                    uint32_t wf[4];
                    ldm_x4(wf, wb + (wNg*128 + np*16 + bHi8 + bR)*144 + ks*32 + bK);
                    mma_bf16(acc[2*np],   A, wf + 0);
                    mma_bf16(acc[2*np+1], A, wf + 2);
                }
            }
        }
    }

    const float gam = gammav[0];
    const int r0 = row0 + wM*16 + (lane >> 2);
    #pragma unroll
    for (int nt = 0; nt < 16; nt++) {
        int n = wNg*128 + nt*8 + (lane & 3)*2;
        #pragma unroll
        for (int h = 0; h < 2; h++) {
            int r = r0 + h*8;
            float2 xr = *(const float2*)(xres + (size_t)r*CDIM + n);
            float2 o;
            o.x = gam*(acc[nt][2*h]   + bov[n])   + xr.x;
            o.y = gam*(acc[nt][2*h+1] + bov[n+1]) + xr.y;
            *(float2*)(outp + (size_t)r*CDIM + n) = o;
        }
    }
}

// ---------------------------------------------------------------------------
// Kernel 2: HMMA flash attention, pair-split (no duplicated S/softmax).
// pair = wid>>1 owns 16 q-rows; half = wid&1 owns 32 keys (S) / 128 ch (PV).
// P exchanged via per-pair smem tile; stats via tiny smem arrays.
// ---------------------------------------------------------------------------
#define OFF_G   0                     // 2x 5120 (hi/lo)
#define OFF_F   10240                 // 2 bufs x (hi 5120 + lo 5120)
#define OFF_V   (OFF_F + 2*10240)     // 2 bufs x 64*528 = 67584
#define OFF_P   (OFF_V + 2*33792)     // 4 pairs x 16 rows x 144B = 9216
#define OFF_MAX (OFF_P + 9216)        // 4 pairs x 2 half x 2 x 16 floats = 1024
#define OFF_SUM (OFF_MAX + 1024)      // 1024
#define SMEM_ATT (OFF_SUM + 1024)     // 109568 B

__device__ __forceinline__ void prefetch_F(uint32_t sb, int buf, int b, int kt, int tid) {
    const size_t kbase = (size_t)b*NPIX + (size_t)kt*64;
    int fr = tid >> 2, fc = tid & 3;
    uint32_t fd = sb + OFF_F + buf*10240 + fr*80 + fc*16;
    CP_ASYNC16(fd,        (const char*)g_f_hi + ((kbase + fr)*CKDIM + fc*8)*2);
    CP_ASYNC16(fd + 5120, (const char*)g_f_lo + ((kbase + fr)*CKDIM + fc*8)*2);
}
__device__ __forceinline__ void prefetch_V(uint32_t sb, int buf, int b, int kt, int tid) {
    const size_t kbase = (size_t)b*NPIX + (size_t)kt*64;
    #pragma unroll
    for (int i = 0; i < 8; i++) {
        int chunk = tid + i*256;
        int vr = chunk >> 5, vc = chunk & 31;
        uint32_t vd = sb + OFF_V + buf*33792 + vr*528 + vc*16;
        CP_ASYNC16(vd, (const char*)g_hV + ((kbase + vr)*CDIM + vc*8)*2);
    }
}

__global__ __launch_bounds__(256, 2) void attn_hmma() {
    extern __shared__ char smc[];
    const uint32_t sb = smem_u32(smc);
    const int tid  = threadIdx.x;
    const int lane = tid & 31;
    const int wid  = tid >> 5;
    const int pair = wid >> 1;     // 0..3 : q-rows pair*16
    const int half = wid & 1;      // 0..1 : keys half*32 (S), ch half*128 (PV)
    const int b    = blockIdx.x >> 6;
    const int qt   = blockIdx.x & 63;
    const size_t qbase = (size_t)b*NPIX + qt*64;

    float* sMax = (float*)(smc + OFF_MAX);   // [pair][half][2][16]
    float* sSum = (float*)(smc + OFF_SUM);   // [pair][half][2][16]

    // prologue: stage G + tile 0 (F0, V0); hard wait
    {
        int gr = tid >> 2, gc = tid & 3;
        uint32_t gd = sb + OFF_G + gr*80 + gc*16;
        CP_ASYNC16(gd,        (const char*)g_g_hi + ((qbase + gr)*CKDIM + gc*8)*2);
        CP_ASYNC16(gd + 5120, (const char*)g_g_lo + ((qbase + gr)*CKDIM + gc*8)*2);
        prefetch_F(sb, 0, b, 0, tid);
        prefetch_V(sb, 0, b, 0, tid);
        CP_COMMIT();
    }
    CP_WAIT(0);
    __syncthreads();

    const int aRow = lane & 15;
    const int aK   = (lane >> 4) * 16;
    const int bR   = lane & 7;
    const int bHi8 = (lane >> 4) * 8;
    const int bK   = ((lane >> 3) & 1) * 16;
    const int tR   = lane & 15;            // trans: k-row select
    const int tC   = (lane >> 4) * 16;     // trans: c-byte select
    const int rq   = lane >> 2;            // local row within 16 (A rows; B = +8)

    uint32_t gh[2][4], gl[2][4];
    #pragma unroll
    for (int ks = 0; ks < 2; ks++) {
        uint32_t ad = sb + OFF_G + (pair*16 + aRow)*80 + ks*32 + aK;
        ldm_x4(gh[ks], ad);
        ldm_x4(gl[ks], ad + 5120);
    }

    float accO[16][4];
    #pragma unroll
    for (int i = 0; i < 16; i++) { accO[i][0]=0.f; accO[i][1]=0.f; accO[i][2]=0.f; accO[i][3]=0.f; }
    float mA = -1e30f, mB = -1e30f, lA = 0.f, lB = 0.f;

    const uint32_t pTile = sb + OFF_P + pair*2304;   // [16][144B]
    float* myMax  = sMax + (pair*2 + half)*32;
    float* sibMax = sMax + (pair*2 + (half^1))*32;
    float* mySum  = sSum + (pair*2 + half)*32;
    float* sibSum = sSum + (pair*2 + (half^1))*32;

    for (int kt = 0; kt < 64; kt++) {
        const int bf = kt & 1;
        if (kt > 0) { CP_WAIT(1); __syncthreads(); }   // F(kt) ready; fences PV(kt-1) & P reads

        // ---- S(kt): 16 q-rows x 32 keys (this half), split-bf16 3-pass
        float sc[4][4];
        #pragma unroll
        for (int i = 0; i < 4; i++) { sc[i][0]=0.f; sc[i][1]=0.f; sc[i][2]=0.f; sc[i][3]=0.f; }
        const uint32_t fbase = sb + OFF_F + bf*10240;
        #pragma unroll
        for (int ks = 0; ks < 2; ks++) {
            #pragma unroll
            for (int np = 0; np < 2; np++) {
                uint32_t fr[4];
                ldm_x4(fr, fbase + (half*32 + np*16 + bHi8 + bR)*80 + ks*32 + bK);
                mma_bf16(sc[2*np],   gh[ks], fr + 0);
                mma_bf16(sc[2*np+1], gh[ks], fr + 2);
                mma_bf16(sc[2*np],   gl[ks], fr + 0);
                mma_bf16(sc[2*np+1], gl[ks], fr + 2);
            }
        }
        #pragma unroll
        for (int ks = 0; ks < 2; ks++) {
            #pragma unroll
            for (int np = 0; np < 2; np++) {
                uint32_t fr[4];
                ldm_x4(fr, fbase + 5120 + (half*32 + np*16 + bHi8 + bR)*80 + ks*32 + bK);
                mma_bf16(sc[2*np],   gh[ks], fr + 0);
                mma_bf16(sc[2*np+1], gh[ks], fr + 2);
            }
        }

        // ---- own-half max, quad-reduced
        float tmaxA = -1e30f, tmaxB = -1e30f;
        #pragma unroll
        for (int nt = 0; nt < 4; nt++) {
            tmaxA = fmaxf(tmaxA, fmaxf(sc[nt][0], sc[nt][1]));
            tmaxB = fmaxf(tmaxB, fmaxf(sc[nt][2], sc[nt][3]));
        }
        tmaxA = fmaxf(tmaxA, __shfl_xor_sync(0xffffffffu, tmaxA, 1));
        tmaxA = fmaxf(tmaxA, __shfl_xor_sync(0xffffffffu, tmaxA, 2));
        tmaxB = fmaxf(tmaxB, __shfl_xor_sync(0xffffffffu, tmaxB, 1));
        tmaxB = fmaxf(tmaxB, __shfl_xor_sync(0xffffffffu, tmaxB, 2));
        if ((lane & 3) == 0) { myMax[rq] = tmaxA; myMax[16 + rq] = tmaxB; }
        __syncthreads();
        float mnA = fmaxf(mA, fmaxf(tmaxA, sibMax[rq]));
        float mnB = fmaxf(mB, fmaxf(tmaxB, sibMax[16 + rq]));
        float scA = __expf(mA - mnA), scB = __expf(mB - mnB);

        // ---- exp, partial sums, write P half into pair tile
        float sumA = 0.f, sumB = 0.f;
        #pragma unroll
        for (int nt = 0; nt < 4; nt++) {
            float p0 = __expf(sc[nt][0] - mnA);
            float p1 = __expf(sc[nt][1] - mnA);
            float p2 = __expf(sc[nt][2] - mnB);
            float p3 = __expf(sc[nt][3] - mnB);
            sumA += p0 + p1; sumB += p2 + p3;
            uint32_t cOff = (half*32 + nt*8 + (lane & 3)*2)*2;
            *(uint32_t*)(smc + (pTile - sb) + rq*144 + cOff)       = pack_f16(p0, p1);
            *(uint32_t*)(smc + (pTile - sb) + (rq + 8)*144 + cOff) = pack_f16(p2, p3);
        }
        sumA += __shfl_xor_sync(0xffffffffu, sumA, 1);
        sumA += __shfl_xor_sync(0xffffffffu, sumA, 2);
        sumB += __shfl_xor_sync(0xffffffffu, sumB, 1);
        sumB += __shfl_xor_sync(0xffffffffu, sumB, 2);
        if ((lane & 3) == 0) { mySum[rq] = sumA; mySum[16 + rq] = sumB; }

        CP_WAIT(0);          // V(kt) resident
        __syncthreads();     // P tile + sums visible; V ready

        lA = lA*scA + sumA + sibSum[rq];
        lB = lB*scB + sumB + sibSum[16 + rq];
        mA = mnA;  mB = mnB;

        // ---- prefetch tile kt+1 (buf^1 reads all fenced by top barrier)
        if (kt < 63) {
            prefetch_F(sb, bf ^ 1, b, kt + 1, tid); CP_COMMIT();
            prefetch_V(sb, bf ^ 1, b, kt + 1, tid); CP_COMMIT();
        }

        // ---- rescale + PV(kt): A-frags from pair P tile (full 64 keys)
        #pragma unroll
        for (int nt = 0; nt < 16; nt++) {
            accO[nt][0] *= scA; accO[nt][1] *= scA;
            accO[nt][2] *= scB; accO[nt][3] *= scB;
        }
        uint32_t pa[4][4];
        #pragma unroll
        for (int ks = 0; ks < 4; ks++)
            ldm_x4(pa[ks], pTile + aRow*144 + ks*32 + aK);
        const uint32_t vbase = sb + OFF_V + bf*33792 + half*256;
        #pragma unroll
        for (int ks = 0; ks < 4; ks++) {
            #pragma unroll
            for (int np = 0; np < 8; np++) {
                uint32_t vr[4];
                ldm_x4_trans(vr, vbase + (ks*16 + tR)*528 + np*32 + tC);
                mma_f16(accO[2*np],   pa[ks], vr + 0);
                mma_f16(accO[2*np+1], pa[ks], vr + 2);
            }
        }
    }

    // ---- write split-bf16 o ----
    const float invA = 1.0f / lA, invB = 1.0f / lB;
    const size_t rA = qbase + pair*16 + rq;
    const size_t rB = rA + 8;
    #pragma unroll
    for (int nt = 0; nt < 16; nt++) {
        int c = half*128 + nt*8 + (lane & 3)*2;
        float a0 = accO[nt][0]*invA, a1 = accO[nt][1]*invA;
        float b0 = accO[nt][2]*invB, b1 = accO[nt][3]*invB;
        __nv_bfloat16 h0,l0,h1,l1;
        split_bf16(a0,h0,l0); split_bf16(a1,h1,l1);
        *(uint32_t*)&g_o_hi[rA*CDIM + c] = pack_bf16(h0,h1);
        *(uint32_t*)&g_o_lo[rA*CDIM + c] = pack_bf16(l0,l1);
        split_bf16(b0,h0,l0); split_bf16(b1,h1,l1);
        *(uint32_t*)&g_o_hi[rB*CDIM + c] = pack_bf16(h0,h1);
        *(uint32_t*)&g_o_lo[rB*CDIM + c] = pack_bf16(l0,l1);
    }
}

// ---------------------------------------------------------------------------
extern "C" void kernel_launch(void* const* d_in, const int* in_sizes, int n_in,
                              void* d_out, int out_size) {
    const float* x     = (const float*)d_in[0];
    const float* Wf    = (const float*)d_in[1];
    const float* bf    = (const float*)d_in[2];
    const float* Wg    = (const float*)d_in[3];
    const float* bg    = (const float*)d_in[4];
    const float* Wh    = (const float*)d_in[5];
    const float* bh    = (const float*)d_in[6];
    const float* Wo    = (const float*)d_in[7];
    const float* bo    = (const float*)d_in[8];
    const float* gamma = (const float*)d_in[9];
    float*       out   = (float*)d_out;

    cudaFuncSetAttribute(pre_gemm,  cudaFuncAttributeMaxDynamicSharedMemorySize, P1_SMEM);
    cudaFuncSetAttribute(out_gemm,  cudaFuncAttributeMaxDynamicSharedMemorySize, P3_SMEM);
    cudaFuncSetAttribute(attn_hmma, cudaFuncAttributeMaxDynamicSharedMemorySize, SMEM_ATT);

    const int setup_blocks = (XPAIRS + WPREN + WON + 255) / 256;
    setup_k<<<setup_blocks, 256>>>(x, Wf, Wg, Wh, Wo);
    pre_gemm<<<ROWS/64, 256, P1_SMEM>>>(bf, bg, bh);
    attn_hmma<<<512, 256, SMEM_ATT>>>();
    out_gemm<<<ROWS/64, 256, P3_SMEM>>>(bo, gamma, x, out);
}

// round 11
// speedup vs baseline: 6.5823x; 1.0797x over previous
#include <cuda_runtime.h>
#include <cuda_bf16.h>
#include <cuda_fp16.h>
#include <cstdint>
#include <math.h>

#define BATCH 8
#define NPIX  4096
#define CDIM  256
#define CKDIM 32
#define ROWS  (BATCH*NPIX)   // 32768
#define NPRE  320            // 32 f | 32 g | 256 h

// ---------------- scratch (allocation-free) ----------------
__device__ __align__(16) __nv_bfloat16 g_x_hi[ROWS*CDIM];
__device__ __align__(16) __nv_bfloat16 g_x_lo[ROWS*CDIM];
__device__ __align__(16) __nv_bfloat16 g_Wpre_hi[NPRE*CDIM];  // [n][k]
__device__ __align__(16) __nv_bfloat16 g_Wpre_lo[NPRE*CDIM];
__device__ __align__(16) __nv_bfloat16 g_Wo_hi[CDIM*CDIM];    // [n][k]
__device__ __align__(16) __nv_bfloat16 g_Wo_lo[CDIM*CDIM];
__device__ __align__(16) __nv_bfloat16 g_f_hi[ROWS*CKDIM];
__device__ __align__(16) __nv_bfloat16 g_f_lo[ROWS*CKDIM];
__device__ __align__(16) __nv_bfloat16 g_g_hi[ROWS*CKDIM];
__device__ __align__(16) __nv_bfloat16 g_g_lo[ROWS*CKDIM];
__device__ __align__(16) __half       g_hV [ROWS*CDIM];       // V: [row][c] fp16
__device__ __align__(16) __nv_bfloat16 g_o_hi[ROWS*CDIM];
__device__ __align__(16) __nv_bfloat16 g_o_lo[ROWS*CDIM];

// ---------------- PTX helpers ----------------
__device__ __forceinline__ uint32_t smem_u32(const void* p) {
    uint32_t a;
    asm("{ .reg .u64 t; cvta.to.shared.u64 t, %1; cvt.u32.u64 %0, t; }" : "=r"(a) : "l"(p));
    return a;
}
#define CP_ASYNC16(dst, src) \
    asm volatile("cp.async.cg.shared.global [%0], [%1], 16;" :: "r"(dst), "l"(src))
#define CP_COMMIT() asm volatile("cp.async.commit_group;" ::: "memory")
#define CP_WAIT(n)  asm volatile("cp.async.wait_group %0;" :: "n"(n) : "memory")

__device__ __forceinline__ void ldm_x4(uint32_t r[4], uint32_t addr) {
    asm volatile("ldmatrix.sync.aligned.m8n8.x4.shared.b16 {%0,%1,%2,%3}, [%4];"
                 : "=r"(r[0]), "=r"(r[1]), "=r"(r[2]), "=r"(r[3]) : "r"(addr));
}
__device__ __forceinline__ void ldm_x4_trans(uint32_t r[4], uint32_t addr) {
    asm volatile("ldmatrix.sync.aligned.m8n8.x4.trans.shared.b16 {%0,%1,%2,%3}, [%4];"
                 : "=r"(r[0]), "=r"(r[1]), "=r"(r[2]), "=r"(r[3]) : "r"(addr));
}
__device__ __forceinline__ void mma_bf16(float c[4], const uint32_t a[4], const uint32_t* b) {
    asm volatile("mma.sync.aligned.m16n8k16.row.col.f32.bf16.bf16.f32 "
                 "{%0,%1,%2,%3}, {%4,%5,%6,%7}, {%8,%9}, {%0,%1,%2,%3};"
                 : "+f"(c[0]), "+f"(c[1]), "+f"(c[2]), "+f"(c[3])
                 : "r"(a[0]), "r"(a[1]), "r"(a[2]), "r"(a[3]), "r"(b[0]), "r"(b[1]));
}
__device__ __forceinline__ void mma_f16(float c[4], const uint32_t a[4], const uint32_t* b) {
    asm volatile("mma.sync.aligned.m16n8k16.row.col.f32.f16.f16.f32 "
                 "{%0,%1,%2,%3}, {%4,%5,%6,%7}, {%8,%9}, {%0,%1,%2,%3};"
                 : "+f"(c[0]), "+f"(c[1]), "+f"(c[2]), "+f"(c[3])
                 : "r"(a[0]), "r"(a[1]), "r"(a[2]), "r"(a[3]), "r"(b[0]), "r"(b[1]));
}
__device__ __forceinline__ uint32_t pack_f16(float lo, float hi) {
    uint32_t d;
    asm("cvt.rn.f16x2.f32 %0, %1, %2;" : "=r"(d) : "f"(hi), "f"(lo));
    return d;
}
__device__ __forceinline__ uint32_t pack_bf16(__nv_bfloat16 a, __nv_bfloat16 b) {
    __nv_bfloat162 t(a, b);
    return *reinterpret_cast<uint32_t*>(&t);
}
__device__ __forceinline__ void split_bf16(float v, __nv_bfloat16& h, __nv_bfloat16& l) {
    h = __float2bfloat16(v);
    l = __float2bfloat16(v - __bfloat162float(h));
}

// ---------------------------------------------------------------------------
// Kernel 0: setup — split x, build transposed split weights
// ---------------------------------------------------------------------------
#define XPAIRS (ROWS*CDIM/2)       // 4194304
#define WPREN  (NPRE*CDIM)         // 81920
#define WON    (CDIM*CDIM)         // 65536
__global__ __launch_bounds__(256) void setup_k(const float* __restrict__ x,
        const float* __restrict__ Wf, const float* __restrict__ Wg,
        const float* __restrict__ Wh, const float* __restrict__ Wo) {
    int id = blockIdx.x*256 + threadIdx.x;
    if (id < XPAIRS) {
        float2 v = *(const float2*)(x + (size_t)id*2);
        __nv_bfloat16 h0, l0, h1, l1;
        split_bf16(v.x, h0, l0); split_bf16(v.y, h1, l1);
        *(uint32_t*)&g_x_hi[(size_t)id*2] = pack_bf16(h0, h1);
        *(uint32_t*)&g_x_lo[(size_t)id*2] = pack_bf16(l0, l1);
    } else if (id < XPAIRS + WPREN) {
        int i = id - XPAIRS;
        int n = i >> 8, k = i & 255;
        float v;
        if      (n < 32) v = Wf[k*CKDIM + n];
        else if (n < 64) v = Wg[k*CKDIM + (n-32)];
        else             v = Wh[k*CDIM + (n-64)];
        __nv_bfloat16 h, l; split_bf16(v, h, l);
        g_Wpre_hi[i] = h; g_Wpre_lo[i] = l;
    } else if (id < XPAIRS + WPREN + WON) {
        int i = id - XPAIRS - WPREN;
        int n = i >> 8, k = i & 255;
        __nv_bfloat16 h, l; split_bf16(Wo[k*CDIM + n], h, l);
        g_Wo_hi[i] = h; g_Wo_lo[i] = l;
    }
}

// ---------------------------------------------------------------------------
// Kernel 1: pre-projection GEMM, double-buffered 32-k chunks.
// grid = 1024: CTA = 64 rows x 160 cols (nhalf).  8 chunks.
// buf: A hi/lo 64x80B = 10240, W hi/lo 160x80B = 25600 -> 35840; x2 = 71680.
// ---------------------------------------------------------------------------
#define P1_A    0
#define P1_ALO  5120
#define P1_W    10240
#define P1_WLO  23040
#define P1_BUF  35840
#define P1_SMEM (2*P1_BUF)

__device__ __forceinline__ void p1_load(uint32_t sb, int buf, int row0, int nbase,
                                        int kc, int tid) {
    const uint32_t bb = sb + buf*P1_BUF;
    {   // A: 64 rows x 64B, hi+lo
        int r = tid >> 2, c = tid & 3;
        uint32_t d = bb + P1_A + r*80 + c*16;
        CP_ASYNC16(d,          (const char*)g_x_hi + ((size_t)(row0 + r)*CDIM + kc*32 + c*8)*2);
        CP_ASYNC16(d + P1_ALO, (const char*)g_x_lo + ((size_t)(row0 + r)*CDIM + kc*32 + c*8)*2);
    }
    // W: 160 rows x 64B, hi then lo (1280 x 16B total, 5 per thread)
    #pragma unroll
    for (int i = 0; i < 5; i++) {
        int chunk = tid + i*256;
        int hi = chunk < 640;
        int cc = hi ? chunk : chunk - 640;
        int r = cc >> 2, c = cc & 3;
        uint32_t d = bb + (hi ? P1_W : P1_WLO) + r*80 + c*16;
        const __nv_bfloat16* src = hi ? g_Wpre_hi : g_Wpre_lo;
        CP_ASYNC16(d, (const char*)src + ((size_t)(nbase + r)*CDIM + kc*32 + c*8)*2);
    }
}

__global__ __launch_bounds__(256, 2) void pre_gemm(
        const float* __restrict__ bfv, const float* __restrict__ bgv,
        const float* __restrict__ bhv) {
    extern __shared__ char smc[];
    const uint32_t sb = smem_u32(smc);
    const int tid  = threadIdx.x;
    const int lane = tid & 31;
    const int wid  = tid >> 5;
    const int wM   = wid & 3;       // 16-row group
    const int wNg  = wid >> 2;      // 0..1, 80 cols each
    const int row0  = (blockIdx.x >> 1) * 64;
    const int nbase = (blockIdx.x & 1) * 160;

    const int aRow = lane & 15;
    const int aK   = (lane >> 4) * 16;
    const int bR   = lane & 7;
    const int bHi8 = (lane >> 4) * 8;
    const int bK   = ((lane >> 3) & 1) * 16;

    float acc[10][4];
    #pragma unroll
    for (int i = 0; i < 10; i++) { acc[i][0]=0.f; acc[i][1]=0.f; acc[i][2]=0.f; acc[i][3]=0.f; }

    p1_load(sb, 0, row0, nbase, 0, tid);
    CP_COMMIT();

    for (int kc = 0; kc < 8; kc++) {
        CP_WAIT(0);
        __syncthreads();
        if (kc < 7) { p1_load(sb, (kc+1)&1, row0, nbase, kc+1, tid); CP_COMMIT(); }

        const uint32_t bb = sb + (kc&1)*P1_BUF;
        uint32_t ahi[2][4], alo[2][4];
        #pragma unroll
        for (int ks = 0; ks < 2; ks++) {
            uint32_t ad = bb + P1_A + (wM*16 + aRow)*80 + ks*32 + aK;
            ldm_x4(ahi[ks], ad);
            ldm_x4(alo[ks], ad + P1_ALO);
        }
        #pragma unroll
        for (int pass = 0; pass < 3; pass++) {
            const uint32_t wb = bb + (pass == 1 ? P1_WLO : P1_W);
            #pragma unroll
            for (int ks = 0; ks < 2; ks++) {
                const uint32_t* A = (pass == 2) ? alo[ks] : ahi[ks];
                #pragma unroll
                for (int np = 0; np < 5; np++) {
                    uint32_t wf[4];
                    ldm_x4(wf, wb + (wNg*80 + np*16 + bHi8 + bR)*80 + ks*32 + bK);
                    mma_bf16(acc[2*np],   A, wf + 0);
                    mma_bf16(acc[2*np+1], A, wf + 2);
                }
            }
        }
        __syncthreads();
    }

    const int r0 = row0 + wM*16 + (lane >> 2);
    #pragma unroll
    for (int nt = 0; nt < 10; nt++) {
        int n = nbase + wNg*80 + nt*8 + (lane & 3)*2;
        #pragma unroll
        for (int h = 0; h < 2; h++) {
            int r = r0 + h*8;
            float v0 = acc[nt][2*h], v1 = acc[nt][2*h+1];
            if (n < 32) {
                v0 += bfv[n]; v1 += bfv[n+1];
                __nv_bfloat16 h0,l0,h1,l1; split_bf16(v0,h0,l0); split_bf16(v1,h1,l1);
                *(uint32_t*)&g_f_hi[(size_t)r*CKDIM + n] = pack_bf16(h0,h1);
                *(uint32_t*)&g_f_lo[(size_t)r*CKDIM + n] = pack_bf16(l0,l1);
            } else if (n < 64) {
                v0 += bgv[n-32]; v1 += bgv[n-31];
                __nv_bfloat16 h0,l0,h1,l1; split_bf16(v0,h0,l0); split_bf16(v1,h1,l1);
                *(uint32_t*)&g_g_hi[(size_t)r*CKDIM + (n-32)] = pack_bf16(h0,h1);
                *(uint32_t*)&g_g_lo[(size_t)r*CKDIM + (n-32)] = pack_bf16(l0,l1);
            } else {
                int c = n - 64;
                v0 += bhv[c]; v1 += bhv[c+1];
                *(uint32_t*)&g_hV[(size_t)r*CDIM + c] = pack_f16(v0, v1);
            }
        }
    }
}

// ---------------------------------------------------------------------------
// Kernel 3: output GEMM, double-buffered 32-k chunks.
// grid = 1024: CTA = 64 rows x 128 cols.  buf: A 10240 + W 128x80Bx2 = 20480
// -> 30720; x2 = 61440.
// ---------------------------------------------------------------------------
#define P3_A    0
#define P3_ALO  5120
#define P3_W    10240
#define P3_WLO  20480
#define P3_BUF  30720
#define P3_SMEM (2*P3_BUF)

__device__ __forceinline__ void p3_load(uint32_t sb, int buf, int row0, int nbase,
                                        int kc, int tid) {
    const uint32_t bb = sb + buf*P3_BUF;
    {
        int r = tid >> 2, c = tid & 3;
        uint32_t d = bb + P3_A + r*80 + c*16;
        CP_ASYNC16(d,          (const char*)g_o_hi + ((size_t)(row0 + r)*CDIM + kc*32 + c*8)*2);
        CP_ASYNC16(d + P3_ALO, (const char*)g_o_lo + ((size_t)(row0 + r)*CDIM + kc*32 + c*8)*2);
    }
    // W: 128 rows x 64B hi+lo = 1024 x 16B, 4 per thread
    #pragma unroll
    for (int i = 0; i < 4; i++) {
        int chunk = tid + i*256;
        int hi = chunk < 512;
        int cc = hi ? chunk : chunk - 512;
        int r = cc >> 2, c = cc & 3;
        uint32_t d = bb + (hi ? P3_W : P3_WLO) + r*80 + c*16;
        const __nv_bfloat16* src = hi ? g_Wo_hi : g_Wo_lo;
        CP_ASYNC16(d, (const char*)src + ((size_t)(nbase + r)*CDIM + kc*32 + c*8)*2);
    }
}

__global__ __launch_bounds__(256, 2) void out_gemm(
        const float* __restrict__ bov, const float* __restrict__ gammav,
        const float* __restrict__ xres, float* __restrict__ outp) {
    extern __shared__ char smc[];
    const uint32_t sb = smem_u32(smc);
    const int tid  = threadIdx.x;
    const int lane = tid & 31;
    const int wid  = tid >> 5;
    const int wM   = wid & 3;
    const int wNg  = wid >> 2;      // 0..1, 64 cols each
    const int row0  = (blockIdx.x >> 1) * 64;
    const int nbase = (blockIdx.x & 1) * 128;

    const int aRow = lane & 15;
    const int aK   = (lane >> 4) * 16;
    const int bR   = lane & 7;
    const int bHi8 = (lane >> 4) * 8;
    const int bK   = ((lane >> 3) & 1) * 16;

    float acc[8][4];
    #pragma unroll
    for (int i = 0; i < 8; i++) { acc[i][0]=0.f; acc[i][1]=0.f; acc[i][2]=0.f; acc[i][3]=0.f; }

    p3_load(sb, 0, row0, nbase, 0, tid);
    CP_COMMIT();

    for (int kc = 0; kc < 8; kc++) {
        CP_WAIT(0);
        __syncthreads();
        if (kc < 7) { p3_load(sb, (kc+1)&1, row0, nbase, kc+1, tid); CP_COMMIT(); }

        const uint32_t bb = sb + (kc&1)*P3_BUF;
        uint32_t ahi[2][4], alo[2][4];
        #pragma unroll
        for (int ks = 0; ks < 2; ks++) {
            uint32_t ad = bb + P3_A + (wM*16 + aRow)*80 + ks*32 + aK;
            ldm_x4(ahi[ks], ad);
            ldm_x4(alo[ks], ad + P3_ALO);
        }
        #pragma unroll
        for (int pass = 0; pass < 3; pass++) {
            const uint32_t wb = bb + (pass == 1 ? P3_WLO : P3_W);
            #pragma unroll
            for (int ks = 0; ks < 2; ks++) {
                const uint32_t* A = (pass == 2) ? alo[ks] : ahi[ks];
                #pragma unroll
                for (int np = 0; np < 4; np++) {
                    uint32_t wf[4];
                    ldm_x4(wf, wb + (wNg*64 + np*16 + bHi8 + bR)*80 + ks*32 + bK);
                    mma_bf16(acc[2*np],   A, wf + 0);
                    mma_bf16(acc[2*np+1], A, wf + 2);
                }
            }
        }
        __syncthreads();
    }

    const float gam = gammav[0];
    const int r0 = row0 + wM*16 + (lane >> 2);
    #pragma unroll
    for (int nt = 0; nt < 8; nt++) {
        int n = nbase + wNg*64 + nt*8 + (lane & 3)*2;
        #pragma unroll
        for (int h = 0; h < 2; h++) {
            int r = r0 + h*8;
            float2 xr = *(const float2*)(xres + (size_t)r*CDIM + n);
            float2 o;
            o.x = gam*(acc[nt][2*h]   + bov[n])   + xr.x;
            o.y = gam*(acc[nt][2*h+1] + bov[n+1]) + xr.y;
            *(float2*)(outp + (size_t)r*CDIM + n) = o;
        }
    }
}

// ---------------------------------------------------------------------------
// Kernel 2: HMMA flash attention, pair-split, 2 barriers/tile.
// Pipeline: exp/P(kt) | B1 | PV(kt)+S(kt+1) | prefetch | B2
// ---------------------------------------------------------------------------
#define OFF_G   0                     // 2x 5120 (hi/lo)
#define OFF_F   10240                 // 2 bufs x (hi 5120 + lo 5120)
#define OFF_V   (OFF_F + 2*10240)     // 2 bufs x 64*528 = 67584
#define OFF_P   (OFF_V + 2*33792)     // 4 pairs x 16 rows x 144B = 9216
#define OFF_MAX (OFF_P + 9216)        // 4 pairs x 2 half x 2 x 16 floats = 1024
#define OFF_SUM (OFF_MAX + 1024)      // 1024
#define SMEM_ATT (OFF_SUM + 1024)     // 109568 B

__device__ __forceinline__ void prefetch_F(uint32_t sb, int buf, int b, int kt, int tid) {
    const size_t kbase = (size_t)b*NPIX + (size_t)kt*64;
    int fr = tid >> 2, fc = tid & 3;
    uint32_t fd = sb + OFF_F + buf*10240 + fr*80 + fc*16;
    CP_ASYNC16(fd,        (const char*)g_f_hi + ((kbase + fr)*CKDIM + fc*8)*2);
    CP_ASYNC16(fd + 5120, (const char*)g_f_lo + ((kbase + fr)*CKDIM + fc*8)*2);
}
__device__ __forceinline__ void prefetch_V(uint32_t sb, int buf, int b, int kt, int tid) {
    const size_t kbase = (size_t)b*NPIX + (size_t)kt*64;
    #pragma unroll
    for (int i = 0; i < 8; i++) {
        int chunk = tid + i*256;
        int vr = chunk >> 5, vc = chunk & 31;
        uint32_t vd = sb + OFF_V + buf*33792 + vr*528 + vc*16;
        CP_ASYNC16(vd, (const char*)g_hV + ((kbase + vr)*CDIM + vc*8)*2);
    }
}

__global__ __launch_bounds__(256, 2) void attn_hmma() {
    extern __shared__ char smc[];
    const uint32_t sb = smem_u32(smc);
    const int tid  = threadIdx.x;
    const int lane = tid & 31;
    const int wid  = tid >> 5;
    const int pair = wid >> 1;     // 0..3 : q-rows pair*16
    const int half = wid & 1;      // 0..1 : keys half*32 (S), ch half*128 (PV)
    const int b    = blockIdx.x >> 6;
    const int qt   = blockIdx.x & 63;
    const size_t qbase = (size_t)b*NPIX + qt*64;

    float* sMax = (float*)(smc + OFF_MAX);   // [pair][half][2][16]
    float* sSum = (float*)(smc + OFF_SUM);

    const int aRow = lane & 15;
    const int aK   = (lane >> 4) * 16;
    const int bR   = lane & 7;
    const int bHi8 = (lane >> 4) * 8;
    const int bK   = ((lane >> 3) & 1) * 16;
    const int tR   = lane & 15;
    const int tC   = (lane >> 4) * 16;
    const int rq   = lane >> 2;

    const uint32_t pTile = sb + OFF_P + pair*2304;
    float* myMax  = sMax + (pair*2 + half)*32;
    float* sibMax = sMax + (pair*2 + (half^1))*32;
    float* mySum  = sSum + (pair*2 + half)*32;
    float* sibSum = sSum + (pair*2 + (half^1))*32;

    // ---- prologue: stage G + F0 + V0
    {
        int gr = tid >> 2, gc = tid & 3;
        uint32_t gd = sb + OFF_G + gr*80 + gc*16;
        CP_ASYNC16(gd,        (const char*)g_g_hi + ((qbase + gr)*CKDIM + gc*8)*2);
        CP_ASYNC16(gd + 5120, (const char*)g_g_lo + ((qbase + gr)*CKDIM + gc*8)*2);
        prefetch_F(sb, 0, b, 0, tid);
        prefetch_V(sb, 0, b, 0, tid);
        CP_COMMIT();
    }
    CP_WAIT(0);
    __syncthreads();

    uint32_t gh[2][4], gl[2][4];
    #pragma unroll
    for (int ks = 0; ks < 2; ks++) {
        uint32_t ad = sb + OFF_G + (pair*16 + aRow)*80 + ks*32 + aK;
        ldm_x4(gh[ks], ad);
        ldm_x4(gl[ks], ad + 5120);
    }

    float accO[16][4];
    #pragma unroll
    for (int i = 0; i < 16; i++) { accO[i][0]=0.f; accO[i][1]=0.f; accO[i][2]=0.f; accO[i][3]=0.f; }
    float mA = -1e30f, mB = -1e30f, lA = 0.f, lB = 0.f;
    float sc[4][4];
    float tmaxA, tmaxB;

    // ---- S(0) + own max + max write
    {
        #pragma unroll
        for (int i = 0; i < 4; i++) { sc[i][0]=0.f; sc[i][1]=0.f; sc[i][2]=0.f; sc[i][3]=0.f; }
        const uint32_t fbase = sb + OFF_F;
        #pragma unroll
        for (int ks = 0; ks < 2; ks++) {
            #pragma unroll
            for (int np = 0; np < 2; np++) {
                uint32_t fr[4];
                ldm_x4(fr, fbase + (half*32 + np*16 + bHi8 + bR)*80 + ks*32 + bK);
                mma_bf16(sc[2*np],   gh[ks], fr + 0);
                mma_bf16(sc[2*np+1], gh[ks], fr + 2);
                mma_bf16(sc[2*np],   gl[ks], fr + 0);
                mma_bf16(sc[2*np+1], gl[ks], fr + 2);
            }
        }
        #pragma unroll
        for (int ks = 0; ks < 2; ks++) {
            #pragma unroll
            for (int np = 0; np < 2; np++) {
                uint32_t fr[4];
                ldm_x4(fr, fbase + 5120 + (half*32 + np*16 + bHi8 + bR)*80 + ks*32 + bK);
                mma_bf16(sc[2*np],   gh[ks], fr + 0);
                mma_bf16(sc[2*np+1], gh[ks], fr + 2);
            }
        }
        tmaxA = -1e30f; tmaxB = -1e30f;
        #pragma unroll
        for (int nt = 0; nt < 4; nt++) {
            tmaxA = fmaxf(tmaxA, fmaxf(sc[nt][0], sc[nt][1]));
            tmaxB = fmaxf(tmaxB, fmaxf(sc[nt][2], sc[nt][3]));
        }
        tmaxA = fmaxf(tmaxA, __shfl_xor_sync(0xffffffffu, tmaxA, 1));
        tmaxA = fmaxf(tmaxA, __shfl_xor_sync(0xffffffffu, tmaxA, 2));
        tmaxB = fmaxf(tmaxB, __shfl_xor_sync(0xffffffffu, tmaxB, 1));
        tmaxB = fmaxf(tmaxB, __shfl_xor_sync(0xffffffffu, tmaxB, 2));
        if ((lane & 3) == 0) { myMax[rq] = tmaxA; myMax[16 + rq] = tmaxB; }
    }
    prefetch_F(sb, 1, b, 1, tid);
    CP_COMMIT();
    __syncthreads();   // maxes(0) visible

    for (int kt = 0; kt < 64; kt++) {
        const int bf = kt & 1;

        // ---- step1: exp(kt) + P write + sums
        float mnA = fmaxf(mA, fmaxf(tmaxA, sibMax[rq]));
        float mnB = fmaxf(mB, fmaxf(tmaxB, sibMax[16 + rq]));
        float scA = __expf(mA - mnA), scB = __expf(mB - mnB);
        float sumA = 0.f, sumB = 0.f;
        #pragma unroll
        for (int nt = 0; nt < 4; nt++) {
            float p0 = __expf(sc[nt][0] - mnA);
            float p1 = __expf(sc[nt][1] - mnA);
            float p2 = __expf(sc[nt][2] - mnB);
            float p3 = __expf(sc[nt][3] - mnB);
            sumA += p0 + p1; sumB += p2 + p3;
            uint32_t cOff = (half*32 + nt*8 + (lane & 3)*2)*2;
            *(uint32_t*)(smc + (pTile - sb) + rq*144 + cOff)       = pack_f16(p0, p1);
            *(uint32_t*)(smc + (pTile - sb) + (rq + 8)*144 + cOff) = pack_f16(p2, p3);
        }
        sumA += __shfl_xor_sync(0xffffffffu, sumA, 1);
        sumA += __shfl_xor_sync(0xffffffffu, sumA, 2);
        sumB += __shfl_xor_sync(0xffffffffu, sumB, 1);
        sumB += __shfl_xor_sync(0xffffffffu, sumB, 2);
        if ((lane & 3) == 0) { mySum[rq] = sumA; mySum[16 + rq] = sumB; }

        // ---- step2: V(kt), F(kt+1) arrived; P/sums visible
        CP_WAIT(0);
        __syncthreads();   // B1

        // ---- step3: stats merge + rescale + PV(kt)
        lA = lA*scA + sumA + sibSum[rq];
        lB = lB*scB + sumB + sibSum[16 + rq];
        mA = mnA;  mB = mnB;
        #pragma unroll
        for (int nt = 0; nt < 16; nt++) {
            accO[nt][0] *= scA; accO[nt][1] *= scA;
            accO[nt][2] *= scB; accO[nt][3] *= scB;
        }
        uint32_t pa[4][4];
        #pragma unroll
        for (int ks = 0; ks < 4; ks++)
            ldm_x4(pa[ks], pTile + aRow*144 + ks*32 + aK);
        const uint32_t vbase = sb + OFF_V + bf*33792 + half*256;
        #pragma unroll
        for (int ks = 0; ks < 4; ks++) {
            #pragma unroll
            for (int np = 0; np < 8; np++) {
                uint32_t vr[4];
                ldm_x4_trans(vr, vbase + (ks*16 + tR)*528 + np*32 + tC);
                mma_f16(accO[2*np],   pa[ks], vr + 0);
                mma_f16(accO[2*np+1], pa[ks], vr + 2);
            }
        }

        // ---- step4: S(kt+1) + own max + max write
        if (kt < 63) {
            #pragma unroll
            for (int i = 0; i < 4; i++) { sc[i][0]=0.f; sc[i][1]=0.f; sc[i][2]=0.f; sc[i][3]=0.f; }
            const uint32_t fbase = sb + OFF_F + (bf^1)*10240;
            #pragma unroll
            for (int ks = 0; ks < 2; ks++) {
                #pragma unroll
                for (int np = 0; np < 2; np++) {
                    uint32_t fr[4];
                    ldm_x4(fr, fbase + (half*32 + np*16 + bHi8 + bR)*80 + ks*32 + bK);
                    mma_bf16(sc[2*np],   gh[ks], fr + 0);
                    mma_bf16(sc[2*np+1], gh[ks], fr + 2);
                    mma_bf16(sc[2*np],   gl[ks], fr + 0);
                    mma_bf16(sc[2*np+1], gl[ks], fr + 2);
                }
            }
            #pragma unroll
            for (int ks = 0; ks < 2; ks++) {
                #pragma unroll
                for (int np = 0; np < 2; np++) {
                    uint32_t fr[4];
                    ldm_x4(fr, fbase + 5120 + (half*32 + np*16 + bHi8 + bR)*80 + ks*32 + bK);
                    mma_bf16(sc[2*np],   gh[ks], fr + 0);
                    mma_bf16(sc[2*np+1], gh[ks], fr + 2);
                }
            }
            tmaxA = -1e30f; tmaxB = -1e30f;
            #pragma unroll
            for (int nt = 0; nt < 4; nt++) {
                tmaxA = fmaxf(tmaxA, fmaxf(sc[nt][0], sc[nt][1]));
                tmaxB = fmaxf(tmaxB, fmaxf(sc[nt][2], sc[nt][3]));
            }
            tmaxA = fmaxf(tmaxA, __shfl_xor_sync(0xffffffffu, tmaxA, 1));
            tmaxA = fmaxf(tmaxA, __shfl_xor_sync(0xffffffffu, tmaxA, 2));
            tmaxB = fmaxf(tmaxB, __shfl_xor_sync(0xffffffffu, tmaxB, 1));
            tmaxB = fmaxf(tmaxB, __shfl_xor_sync(0xffffffffu, tmaxB, 2));
            if ((lane & 3) == 0) { myMax[rq] = tmaxA; myMax[16 + rq] = tmaxB; }

            // ---- step5: prefetch V(kt+1), F(kt+2)
            prefetch_V(sb, bf ^ 1, b, kt + 1, tid); CP_COMMIT();
            if (kt < 62) { prefetch_F(sb, bf, b, kt + 2, tid); CP_COMMIT(); }
        }

        __syncthreads();   // B2: max(kt+1) visible; P tile consumed
    }

    // ---- epilogue: write split-bf16 o ----
    const float invA = 1.0f / lA, invB = 1.0f / lB;
    const size_t rA = qbase + pair*16 + rq;
    const size_t rB = rA + 8;
    #pragma unroll
    for (int nt = 0; nt < 16; nt++) {
        int c = half*128 + nt*8 + (lane & 3)*2;
        float a0 = accO[nt][0]*invA, a1 = accO[nt][1]*invA;
        float b0 = accO[nt][2]*invB, b1 = accO[nt][3]*invB;
        __nv_bfloat16 h0,l0,h1,l1;
        split_bf16(a0,h0,l0); split_bf16(a1,h1,l1);
        *(uint32_t*)&g_o_hi[rA*CDIM + c] = pack_bf16(h0,h1);
        *(uint32_t*)&g_o_lo[rA*CDIM + c] = pack_bf16(l0,l1);
        split_bf16(b0,h0,l0); split_bf16(b1,h1,l1);
        *(uint32_t*)&g_o_hi[rB*CDIM + c] = pack_bf16(h0,h1);
        *(uint32_t*)&g_o_lo[rB*CDIM + c] = pack_bf16(l0,l1);
    }
}

// ---------------------------------------------------------------------------
extern "C" void kernel_launch(void* const* d_in, const int* in_sizes, int n_in,
                              void* d_out, int out_size) {
    const float* x     = (const float*)d_in[0];
    const float* Wf    = (const float*)d_in[1];
    const float* bf    = (const float*)d_in[2];
    const float* Wg    = (const float*)d_in[3];
    const float* bg    = (const float*)d_in[4];
    const float* Wh    = (const float*)d_in[5];
    const float* bh    = (const float*)d_in[6];
    const float* Wo    = (const float*)d_in[7];
    const float* bo    = (const float*)d_in[8];
    const float* gamma = (const float*)d_in[9];
    float*       out   = (float*)d_out;

    cudaFuncSetAttribute(pre_gemm,  cudaFuncAttributeMaxDynamicSharedMemorySize, P1_SMEM);
    cudaFuncSetAttribute(out_gemm,  cudaFuncAttributeMaxDynamicSharedMemorySize, P3_SMEM);
    cudaFuncSetAttribute(attn_hmma, cudaFuncAttributeMaxDynamicSharedMemorySize, SMEM_ATT);

    const int setup_blocks = (XPAIRS + WPREN + WON + 255) / 256;
    setup_k<<<setup_blocks, 256>>>(x, Wf, Wg, Wh, Wo);
    pre_gemm<<<ROWS/64*2, 256, P1_SMEM>>>(bf, bg, bh);
    attn_hmma<<<512, 256, SMEM_ATT>>>();
    out_gemm<<<ROWS/64*2, 256, P3_SMEM>>>(bo, gamma, x, out);
}

// round 12
// speedup vs baseline: 6.6041x; 1.0033x over previous
#include <cuda_runtime.h>
#include <cuda_bf16.h>
#include <cuda_fp16.h>
#include <cstdint>
#include <math.h>

#define BATCH 8
#define NPIX  4096
#define CDIM  256
#define CKDIM 32
#define ROWS  (BATCH*NPIX)   // 32768
#define NPRE  320            // 32 f | 32 g | 256 h

// ---------------- scratch (allocation-free) ----------------
__device__ __align__(16) __nv_bfloat16 g_Wpre_hi[NPRE*CDIM];  // [n][k]
__device__ __align__(16) __nv_bfloat16 g_Wpre_lo[NPRE*CDIM];
__device__ __align__(16) __nv_bfloat16 g_Wo_hi[CDIM*CDIM];    // [n][k]
__device__ __align__(16) __nv_bfloat16 g_Wo_lo[CDIM*CDIM];
__device__ __align__(16) __nv_bfloat16 g_f_hi[ROWS*CKDIM];
__device__ __align__(16) __nv_bfloat16 g_f_lo[ROWS*CKDIM];
__device__ __align__(16) __nv_bfloat16 g_g_hi[ROWS*CKDIM];
__device__ __align__(16) __nv_bfloat16 g_g_lo[ROWS*CKDIM];
__device__ __align__(16) __half       g_hV [ROWS*CDIM];       // V: [row][c] fp16
__device__ __align__(16) __nv_bfloat16 g_o_hi[ROWS*CDIM];
__device__ __align__(16) __nv_bfloat16 g_o_lo[ROWS*CDIM];

// ---------------- PTX helpers ----------------
__device__ __forceinline__ uint32_t smem_u32(const void* p) {
    uint32_t a;
    asm("{ .reg .u64 t; cvta.to.shared.u64 t, %1; cvt.u32.u64 %0, t; }" : "=r"(a) : "l"(p));
    return a;
}
#define CP_ASYNC16(dst, src) \
    asm volatile("cp.async.cg.shared.global [%0], [%1], 16;" :: "r"(dst), "l"(src))
#define CP_COMMIT() asm volatile("cp.async.commit_group;" ::: "memory")
#define CP_WAIT(n)  asm volatile("cp.async.wait_group %0;" :: "n"(n) : "memory")

__device__ __forceinline__ void ldm_x4(uint32_t r[4], uint32_t addr) {
    asm volatile("ldmatrix.sync.aligned.m8n8.x4.shared.b16 {%0,%1,%2,%3}, [%4];"
                 : "=r"(r[0]), "=r"(r[1]), "=r"(r[2]), "=r"(r[3]) : "r"(addr));
}
__device__ __forceinline__ void ldm_x4_trans(uint32_t r[4], uint32_t addr) {
    asm volatile("ldmatrix.sync.aligned.m8n8.x4.trans.shared.b16 {%0,%1,%2,%3}, [%4];"
                 : "=r"(r[0]), "=r"(r[1]), "=r"(r[2]), "=r"(r[3]) : "r"(addr));
}
__device__ __forceinline__ void mma_bf16(float c[4], const uint32_t a[4], const uint32_t* b) {
    asm volatile("mma.sync.aligned.m16n8k16.row.col.f32.bf16.bf16.f32 "
                 "{%0,%1,%2,%3}, {%4,%5,%6,%7}, {%8,%9}, {%0,%1,%2,%3};"
                 : "+f"(c[0]), "+f"(c[1]), "+f"(c[2]), "+f"(c[3])
                 : "r"(a[0]), "r"(a[1]), "r"(a[2]), "r"(a[3]), "r"(b[0]), "r"(b[1]));
}
__device__ __forceinline__ void mma_f16(float c[4], const uint32_t a[4], const uint32_t* b) {
    asm volatile("mma.sync.aligned.m16n8k16.row.col.f32.f16.f16.f32 "
                 "{%0,%1,%2,%3}, {%4,%5,%6,%7}, {%8,%9}, {%0,%1,%2,%3};"
                 : "+f"(c[0]), "+f"(c[1]), "+f"(c[2]), "+f"(c[3])
                 : "r"(a[0]), "r"(a[1]), "r"(a[2]), "r"(a[3]), "r"(b[0]), "r"(b[1]));
}
__device__ __forceinline__ uint32_t pack_f16(float lo, float hi) {
    uint32_t d;
    asm("cvt.rn.f16x2.f32 %0, %1, %2;" : "=r"(d) : "f"(hi), "f"(lo));
    return d;
}
__device__ __forceinline__ uint32_t pack_bf16(__nv_bfloat16 a, __nv_bfloat16 b) {
    __nv_bfloat162 t(a, b);
    return *reinterpret_cast<uint32_t*>(&t);
}
__device__ __forceinline__ void split_bf16(float v, __nv_bfloat16& h, __nv_bfloat16& l) {
    h = __float2bfloat16(v);
    l = __float2bfloat16(v - __bfloat162float(h));
}

// ---------------------------------------------------------------------------
// Kernel 0: setup — split weights only (x split is fused into pre_gemm)
// ---------------------------------------------------------------------------
#define WPREN  (NPRE*CDIM)         // 81920
#define WON    (CDIM*CDIM)         // 65536
__global__ __launch_bounds__(256) void setup_k(
        const float* __restrict__ Wf, const float* __restrict__ Wg,
        const float* __restrict__ Wh, const float* __restrict__ Wo) {
    int id = blockIdx.x*256 + threadIdx.x;
    if (id < WPREN) {
        int n = id >> 8, k = id & 255;
        float v;
        if      (n < 32) v = Wf[k*CKDIM + n];
        else if (n < 64) v = Wg[k*CKDIM + (n-32)];
        else             v = Wh[k*CDIM + (n-64)];
        __nv_bfloat16 h, l; split_bf16(v, h, l);
        g_Wpre_hi[id] = h; g_Wpre_lo[id] = l;
    } else if (id < WPREN + WON) {
        int i = id - WPREN;
        int n = i >> 8, k = i & 255;
        __nv_bfloat16 h, l; split_bf16(Wo[k*CDIM + n], h, l);
        g_Wo_hi[i] = h; g_Wo_lo[i] = l;
    }
}

// ---------------------------------------------------------------------------
// Kernel 1: pre-projection GEMM.  CTA = 128 rows x 160 cols, 512 thr, 8 chunks.
// x read fp32 directly (reg-prefetched), split to bf16 hi/lo in-kernel.
// buf: A hi/lo 128x80B = 20480, W hi/lo 160x80B = 25600 -> 46080; x2 = 92160.
// ---------------------------------------------------------------------------
#define P1_A    0
#define P1_ALO  10240
#define P1_W    20480
#define P1_WLO  33280
#define P1_BUF  46080
#define P1_SMEM (2*P1_BUF)

__device__ __forceinline__ void p1_loadW(uint32_t sb, int buf, int nbase,
                                         int kc, int tid) {
    const uint32_t bb = sb + buf*P1_BUF;
    #pragma unroll
    for (int i = 0; i < 3; i++) {
        int c = tid + i*512;
        if (c < 1280) {
            int hi = c < 640;
            int cc = hi ? c : c - 640;
            int r = cc >> 2, col = cc & 3;
            const __nv_bfloat16* src = hi ? g_Wpre_hi : g_Wpre_lo;
            CP_ASYNC16(bb + (hi ? P1_W : P1_WLO) + r*80 + col*16,
                       (const char*)src + ((size_t)(nbase + r)*CDIM + kc*32 + col*8)*2);
        }
    }
}

__global__ __launch_bounds__(512, 1) void pre_gemm(
        const float* __restrict__ x,
        const float* __restrict__ bfv, const float* __restrict__ bgv,
        const float* __restrict__ bhv) {
    extern __shared__ char smc[];
    const uint32_t sb = smem_u32(smc);
    const int tid  = threadIdx.x;
    const int lane = tid & 31;
    const int wid  = tid >> 5;
    const int wM   = wid & 7;       // 8 x 16 rows
    const int wNg  = wid >> 3;      // 0..1, 80 cols each
    const int row0  = (blockIdx.x >> 1) * 128;
    const int nbase = (blockIdx.x & 1) * 160;

    const int aRow = lane & 15;
    const int aK   = (lane >> 4) * 16;
    const int bR   = lane & 7;
    const int bHi8 = (lane >> 4) * 8;
    const int bK   = ((lane >> 3) & 1) * 16;

    const int xRow = tid >> 2;        // 0..127
    const int xC4  = (tid & 3);       // 16B column group

    float acc[10][4];
    #pragma unroll
    for (int i = 0; i < 10; i++) { acc[i][0]=0.f; acc[i][1]=0.f; acc[i][2]=0.f; acc[i][3]=0.f; }

    const float* xrow = x + (size_t)(row0 + xRow)*CDIM + xC4*8;
    float4 xa = *(const float4*)(xrow + 0);
    float4 xb = *(const float4*)(xrow + 4);
    p1_loadW(sb, 0, nbase, 0, tid);
    CP_COMMIT();

    for (int kc = 0; kc < 8; kc++) {
        const int p = kc & 1;
        const uint32_t bb = sb + p*P1_BUF;

        // split x regs -> A hi/lo smem
        {
            float v[8] = {xa.x, xa.y, xa.z, xa.w, xb.x, xb.y, xb.z, xb.w};
            uint4 uh, ul;
            uint32_t* ph = (uint32_t*)&uh;
            uint32_t* pl = (uint32_t*)&ul;
            #pragma unroll
            for (int j = 0; j < 4; j++) {
                __nv_bfloat16 h0,l0,h1,l1;
                split_bf16(v[2*j], h0, l0);
                split_bf16(v[2*j+1], h1, l1);
                ph[j] = pack_bf16(h0, h1);
                pl[j] = pack_bf16(l0, l1);
            }
            *(uint4*)(smc + p*P1_BUF + P1_A   + xRow*80 + xC4*16) = uh;
            *(uint4*)(smc + p*P1_BUF + P1_ALO + xRow*80 + xC4*16) = ul;
        }
        CP_WAIT(0);
        __syncthreads();

        if (kc < 7) {
            const float* xn = x + (size_t)(row0 + xRow)*CDIM + (kc+1)*32 + xC4*8;
            xa = *(const float4*)(xn + 0);
            xb = *(const float4*)(xn + 4);
            p1_loadW(sb, p ^ 1, nbase, kc + 1, tid);
            CP_COMMIT();
        }

        uint32_t ahi[2][4], alo[2][4];
        #pragma unroll
        for (int ks = 0; ks < 2; ks++) {
            uint32_t ad = bb + P1_A + (wM*16 + aRow)*80 + ks*32 + aK;
            ldm_x4(ahi[ks], ad);
            ldm_x4(alo[ks], ad + (P1_ALO - P1_A));
        }
        #pragma unroll
        for (int pass = 0; pass < 3; pass++) {
            const uint32_t wb = bb + (pass == 1 ? P1_WLO : P1_W);
            #pragma unroll
            for (int ks = 0; ks < 2; ks++) {
                const uint32_t* A = (pass == 2) ? alo[ks] : ahi[ks];
                #pragma unroll
                for (int np = 0; np < 5; np++) {
                    uint32_t wf[4];
                    ldm_x4(wf, wb + (wNg*80 + np*16 + bHi8 + bR)*80 + ks*32 + bK);
                    mma_bf16(acc[2*np],   A, wf + 0);
                    mma_bf16(acc[2*np+1], A, wf + 2);
                }
            }
        }
    }

    const int r0 = row0 + wM*16 + (lane >> 2);
    #pragma unroll
    for (int nt = 0; nt < 10; nt++) {
        int n = nbase + wNg*80 + nt*8 + (lane & 3)*2;
        #pragma unroll
        for (int h = 0; h < 2; h++) {
            int r = r0 + h*8;
            float v0 = acc[nt][2*h], v1 = acc[nt][2*h+1];
            if (n < 32) {
                v0 += bfv[n]; v1 += bfv[n+1];
                __nv_bfloat16 h0,l0,h1,l1; split_bf16(v0,h0,l0); split_bf16(v1,h1,l1);
                *(uint32_t*)&g_f_hi[(size_t)r*CKDIM + n] = pack_bf16(h0,h1);
                *(uint32_t*)&g_f_lo[(size_t)r*CKDIM + n] = pack_bf16(l0,l1);
            } else if (n < 64) {
                v0 += bgv[n-32]; v1 += bgv[n-31];
                __nv_bfloat16 h0,l0,h1,l1; split_bf16(v0,h0,l0); split_bf16(v1,h1,l1);
                *(uint32_t*)&g_g_hi[(size_t)r*CKDIM + (n-32)] = pack_bf16(h0,h1);
                *(uint32_t*)&g_g_lo[(size_t)r*CKDIM + (n-32)] = pack_bf16(l0,l1);
            } else {
                int c = n - 64;
                v0 += bhv[c]; v1 += bhv[c+1];
                *(uint32_t*)&g_hV[(size_t)r*CDIM + c] = pack_f16(v0, v1);
            }
        }
    }
}

// ---------------------------------------------------------------------------
// Kernel 3: output GEMM.  CTA = 128 rows x 128 cols, 512 thr, 8 chunks.
// buf: A(o) hi/lo 20480 + W hi/lo 20480 = 40960; x2 = 81920.
// ---------------------------------------------------------------------------
#define P3_A    0
#define P3_ALO  10240
#define P3_W    20480
#define P3_WLO  30720
#define P3_BUF  40960
#define P3_SMEM (2*P3_BUF)

__device__ __forceinline__ void p3_load(uint32_t sb, int buf, int row0, int nbase,
                                        int kc, int tid) {
    const uint32_t bb = sb + buf*P3_BUF;
    #pragma unroll
    for (int i = 0; i < 2; i++) {           // A: o hi/lo, 1024 x 16B
        int c = tid + i*512;
        int hi = c < 512;
        int cc = hi ? c : c - 512;
        int r = cc >> 2, col = cc & 3;
        const __nv_bfloat16* src = hi ? g_o_hi : g_o_lo;
        CP_ASYNC16(bb + (hi ? P3_A : P3_ALO) + r*80 + col*16,
                   (const char*)src + ((size_t)(row0 + r)*CDIM + kc*32 + col*8)*2);
    }
    #pragma unroll
    for (int i = 0; i < 2; i++) {           // W hi/lo, 1024 x 16B
        int c = tid + i*512;
        int hi = c < 512;
        int cc = hi ? c : c - 512;
        int r = cc >> 2, col = cc & 3;
        const __nv_bfloat16* src = hi ? g_Wo_hi : g_Wo_lo;
        CP_ASYNC16(bb + (hi ? P3_W : P3_WLO) + r*80 + col*16,
                   (const char*)src + ((size_t)(nbase + r)*CDIM + kc*32 + col*8)*2);
    }
}

__global__ __launch_bounds__(512, 1) void out_gemm(
        const float* __restrict__ bov, const float* __restrict__ gammav,
        const float* __restrict__ xres, float* __restrict__ outp) {
    extern __shared__ char smc[];
    const uint32_t sb = smem_u32(smc);
    const int tid  = threadIdx.x;
    const int lane = tid & 31;
    const int wid  = tid >> 5;
    const int wM   = wid & 7;       // 8 x 16 rows
    const int wNg  = wid >> 3;      // 0..1, 64 cols each
    const int row0  = (blockIdx.x >> 1) * 128;
    const int nbase = (blockIdx.x & 1) * 128;

    const int aRow = lane & 15;
    const int aK   = (lane >> 4) * 16;
    const int bR   = lane & 7;
    const int bHi8 = (lane >> 4) * 8;
    const int bK   = ((lane >> 3) & 1) * 16;

    float acc[8][4];
    #pragma unroll
    for (int i = 0; i < 8; i++) { acc[i][0]=0.f; acc[i][1]=0.f; acc[i][2]=0.f; acc[i][3]=0.f; }

    p3_load(sb, 0, row0, nbase, 0, tid);
    CP_COMMIT();

    for (int kc = 0; kc < 8; kc++) {
        CP_WAIT(0);
        __syncthreads();
        if (kc < 7) { p3_load(sb, (kc+1)&1, row0, nbase, kc+1, tid); CP_COMMIT(); }

        const uint32_t bb = sb + (kc&1)*P3_BUF;
        uint32_t ahi[2][4], alo[2][4];
        #pragma unroll
        for (int ks = 0; ks < 2; ks++) {
            uint32_t ad = bb + P3_A + (wM*16 + aRow)*80 + ks*32 + aK;
            ldm_x4(ahi[ks], ad);
            ldm_x4(alo[ks], ad + (P3_ALO - P3_A));
        }
        #pragma unroll
        for (int pass = 0; pass < 3; pass++) {
            const uint32_t wb = bb + (pass == 1 ? P3_WLO : P3_W);
            #pragma unroll
            for (int ks = 0; ks < 2; ks++) {
                const uint32_t* A = (pass == 2) ? alo[ks] : ahi[ks];
                #pragma unroll
                for (int np = 0; np < 4; np++) {
                    uint32_t wf[4];
                    ldm_x4(wf, wb + (wNg*64 + np*16 + bHi8 + bR)*80 + ks*32 + bK);
                    mma_bf16(acc[2*np],   A, wf + 0);
                    mma_bf16(acc[2*np+1], A, wf + 2);
                }
            }
        }
    }

    const float gam = gammav[0];
    const int r0 = row0 + wM*16 + (lane >> 2);
    #pragma unroll
    for (int nt = 0; nt < 8; nt++) {
        int n = nbase + wNg*64 + nt*8 + (lane & 3)*2;
        #pragma unroll
        for (int h = 0; h < 2; h++) {
            int r = r0 + h*8;
            float2 xr = *(const float2*)(xres + (size_t)r*CDIM + n);
            float2 o;
            o.x = gam*(acc[nt][2*h]   + bov[n])   + xr.x;
            o.y = gam*(acc[nt][2*h+1] + bov[n+1]) + xr.y;
            *(float2*)(outp + (size_t)r*CDIM + n) = o;
        }
    }
}

// ---------------------------------------------------------------------------
// Kernel 2: HMMA flash attention, pair-split, 2 barriers/tile.
// Pipeline: exp/P(kt) | B1 | PV(kt)+S(kt+1) | prefetch | B2
// Rescale of accO skipped when warp-uniformly scale==1 (exact).
// ---------------------------------------------------------------------------
#define OFF_G   0                     // 2x 5120 (hi/lo)
#define OFF_F   10240                 // 2 bufs x (hi 5120 + lo 5120)
#define OFF_V   (OFF_F + 2*10240)     // 2 bufs x 64*528 = 67584
#define OFF_P   (OFF_V + 2*33792)     // 4 pairs x 16 rows x 144B = 9216
#define OFF_MAX (OFF_P + 9216)        // 1024
#define OFF_SUM (OFF_MAX + 1024)      // 1024
#define SMEM_ATT (OFF_SUM + 1024)     // 109568 B

__device__ __forceinline__ void prefetch_F(uint32_t sb, int buf, int b, int kt, int tid) {
    const size_t kbase = (size_t)b*NPIX + (size_t)kt*64;
    int fr = tid >> 2, fc = tid & 3;
    uint32_t fd = sb + OFF_F + buf*10240 + fr*80 + fc*16;
    CP_ASYNC16(fd,        (const char*)g_f_hi + ((kbase + fr)*CKDIM + fc*8)*2);
    CP_ASYNC16(fd + 5120, (const char*)g_f_lo + ((kbase + fr)*CKDIM + fc*8)*2);
}
__device__ __forceinline__ void prefetch_V(uint32_t sb, int buf, int b, int kt, int tid) {
    const size_t kbase = (size_t)b*NPIX + (size_t)kt*64;
    #pragma unroll
    for (int i = 0; i < 8; i++) {
        int chunk = tid + i*256;
        int vr = chunk >> 5, vc = chunk & 31;
        uint32_t vd = sb + OFF_V + buf*33792 + vr*528 + vc*16;
        CP_ASYNC16(vd, (const char*)g_hV + ((kbase + vr)*CDIM + vc*8)*2);
    }
}

__global__ __launch_bounds__(256, 2) void attn_hmma() {
    extern __shared__ char smc[];
    const uint32_t sb = smem_u32(smc);
    const int tid  = threadIdx.x;
    const int lane = tid & 31;
    const int wid  = tid >> 5;
    const int pair = wid >> 1;     // 0..3 : q-rows pair*16
    const int half = wid & 1;      // 0..1 : keys half*32 (S), ch half*128 (PV)
    const int b    = blockIdx.x >> 6;
    const int qt   = blockIdx.x & 63;
    const size_t qbase = (size_t)b*NPIX + qt*64;

    float* sMax = (float*)(smc + OFF_MAX);   // [pair][half][2][16]
    float* sSum = (float*)(smc + OFF_SUM);

    const int aRow = lane & 15;
    const int aK   = (lane >> 4) * 16;
    const int bR   = lane & 7;
    const int bHi8 = (lane >> 4) * 8;
    const int bK   = ((lane >> 3) & 1) * 16;
    const int tR   = lane & 15;
    const int tC   = (lane >> 4) * 16;
    const int rq   = lane >> 2;

    const uint32_t pTile = sb + OFF_P + pair*2304;
    float* myMax  = sMax + (pair*2 + half)*32;
    float* sibMax = sMax + (pair*2 + (half^1))*32;
    float* mySum  = sSum + (pair*2 + half)*32;
    float* sibSum = sSum + (pair*2 + (half^1))*32;

    // ---- prologue: stage G + F0 + V0
    {
        int gr = tid >> 2, gc = tid & 3;
        uint32_t gd = sb + OFF_G + gr*80 + gc*16;
        CP_ASYNC16(gd,        (const char*)g_g_hi + ((qbase + gr)*CKDIM + gc*8)*2);
        CP_ASYNC16(gd + 5120, (const char*)g_g_lo + ((qbase + gr)*CKDIM + gc*8)*2);
        prefetch_F(sb, 0, b, 0, tid);
        prefetch_V(sb, 0, b, 0, tid);
        CP_COMMIT();
    }
    CP_WAIT(0);
    __syncthreads();

    uint32_t gh[2][4], gl[2][4];
    #pragma unroll
    for (int ks = 0; ks < 2; ks++) {
        uint32_t ad = sb + OFF_G + (pair*16 + aRow)*80 + ks*32 + aK;
        ldm_x4(gh[ks], ad);
        ldm_x4(gl[ks], ad + 5120);
    }

    float accO[16][4];
    #pragma unroll
    for (int i = 0; i < 16; i++) { accO[i][0]=0.f; accO[i][1]=0.f; accO[i][2]=0.f; accO[i][3]=0.f; }
    float mA = -1e30f, mB = -1e30f, lA = 0.f, lB = 0.f;
    float sc[4][4];
    float tmaxA, tmaxB;

    // ---- S(0) + own max + max write
    {
        #pragma unroll
        for (int i = 0; i < 4; i++) { sc[i][0]=0.f; sc[i][1]=0.f; sc[i][2]=0.f; sc[i][3]=0.f; }
        const uint32_t fbase = sb + OFF_F;
        #pragma unroll
        for (int ks = 0; ks < 2; ks++) {
            #pragma unroll
            for (int np = 0; np < 2; np++) {
                uint32_t fr[4];
                ldm_x4(fr, fbase + (half*32 + np*16 + bHi8 + bR)*80 + ks*32 + bK);
                mma_bf16(sc[2*np],   gh[ks], fr + 0);
                mma_bf16(sc[2*np+1], gh[ks], fr + 2);
                mma_bf16(sc[2*np],   gl[ks], fr + 0);
                mma_bf16(sc[2*np+1], gl[ks], fr + 2);
            }
        }
        #pragma unroll
        for (int ks = 0; ks < 2; ks++) {
            #pragma unroll
            for (int np = 0; np < 2; np++) {
                uint32_t fr[4];
                ldm_x4(fr, fbase + 5120 + (half*32 + np*16 + bHi8 + bR)*80 + ks*32 + bK);
                mma_bf16(sc[2*np],   gh[ks], fr + 0);
                mma_bf16(sc[2*np+1], gh[ks], fr + 2);
            }
        }
        tmaxA = -1e30f; tmaxB = -1e30f;
        #pragma unroll
        for (int nt = 0; nt < 4; nt++) {
            tmaxA = fmaxf(tmaxA, fmaxf(sc[nt][0], sc[nt][1]));
            tmaxB = fmaxf(tmaxB, fmaxf(sc[nt][2], sc[nt][3]));
        }
        tmaxA = fmaxf(tmaxA, __shfl_xor_sync(0xffffffffu, tmaxA, 1));
        tmaxA = fmaxf(tmaxA, __shfl_xor_sync(0xffffffffu, tmaxA, 2));
        tmaxB = fmaxf(tmaxB, __shfl_xor_sync(0xffffffffu, tmaxB, 1));
        tmaxB = fmaxf(tmaxB, __shfl_xor_sync(0xffffffffu, tmaxB, 2));
        if ((lane & 3) == 0) { myMax[rq] = tmaxA; myMax[16 + rq] = tmaxB; }
    }
    prefetch_F(sb, 1, b, 1, tid);
    CP_COMMIT();
    __syncthreads();   // maxes(0) visible

    for (int kt = 0; kt < 64; kt++) {
        const int bf = kt & 1;

        // ---- step1: exp(kt) + P write + sums
        float mnA = fmaxf(mA, fmaxf(tmaxA, sibMax[rq]));
        float mnB = fmaxf(mB, fmaxf(tmaxB, sibMax[16 + rq]));
        float scA = __expf(mA - mnA), scB = __expf(mB - mnB);
        bool noscale = __all_sync(0xffffffffu, (scA == 1.0f) && (scB == 1.0f));
        float sumA = 0.f, sumB = 0.f;
        #pragma unroll
        for (int nt = 0; nt < 4; nt++) {
            float p0 = __expf(sc[nt][0] - mnA);
            float p1 = __expf(sc[nt][1] - mnA);
            float p2 = __expf(sc[nt][2] - mnB);
            float p3 = __expf(sc[nt][3] - mnB);
            sumA += p0 + p1; sumB += p2 + p3;
            uint32_t cOff = (half*32 + nt*8 + (lane & 3)*2)*2;
            *(uint32_t*)(smc + (pTile - sb) + rq*144 + cOff)       = pack_f16(p0, p1);
            *(uint32_t*)(smc + (pTile - sb) + (rq + 8)*144 + cOff) = pack_f16(p2, p3);
        }
        sumA += __shfl_xor_sync(0xffffffffu, sumA, 1);
        sumA += __shfl_xor_sync(0xffffffffu, sumA, 2);
        sumB += __shfl_xor_sync(0xffffffffu, sumB, 1);
        sumB += __shfl_xor_sync(0xffffffffu, sumB, 2);
        if ((lane & 3) == 0) { mySum[rq] = sumA; mySum[16 + rq] = sumB; }

        // ---- step2: V(kt), F(kt+1) arrived; P/sums visible
        CP_WAIT(0);
        __syncthreads();   // B1

        // ---- step3: stats merge + (conditional) rescale + PV(kt)
        lA = lA*scA + sumA + sibSum[rq];
        lB = lB*scB + sumB + sibSum[16 + rq];
        mA = mnA;  mB = mnB;
        if (!noscale) {
            #pragma unroll
            for (int nt = 0; nt < 16; nt++) {
                accO[nt][0] *= scA; accO[nt][1] *= scA;
                accO[nt][2] *= scB; accO[nt][3] *= scB;
            }
        }
        uint32_t pa[4][4];
        #pragma unroll
        for (int ks = 0; ks < 4; ks++)
            ldm_x4(pa[ks], pTile + aRow*144 + ks*32 + aK);
        const uint32_t vbase = sb + OFF_V + bf*33792 + half*256;
        #pragma unroll
        for (int ks = 0; ks < 4; ks++) {
            #pragma unroll
            for (int np = 0; np < 8; np++) {
                uint32_t vr[4];
                ldm_x4_trans(vr, vbase + (ks*16 + tR)*528 + np*32 + tC);
                mma_f16(accO[2*np],   pa[ks], vr + 0);
                mma_f16(accO[2*np+1], pa[ks], vr + 2);
            }
        }

        // ---- step4: S(kt+1) + own max + max write
        if (kt < 63) {
            #pragma unroll
            for (int i = 0; i < 4; i++) { sc[i][0]=0.f; sc[i][1]=0.f; sc[i][2]=0.f; sc[i][3]=0.f; }
            const uint32_t fbase = sb + OFF_F + (bf^1)*10240;
            #pragma unroll
            for (int ks = 0; ks < 2; ks++) {
                #pragma unroll
                for (int np = 0; np < 2; np++) {
                    uint32_t fr[4];
                    ldm_x4(fr, fbase + (half*32 + np*16 + bHi8 + bR)*80 + ks*32 + bK);
                    mma_bf16(sc[2*np],   gh[ks], fr + 0);
                    mma_bf16(sc[2*np+1], gh[ks], fr + 2);
                    mma_bf16(sc[2*np],   gl[ks], fr + 0);
                    mma_bf16(sc[2*np+1], gl[ks], fr + 2);
                }
            }
            #pragma unroll
            for (int ks = 0; ks < 2; ks++) {
                #pragma unroll
                for (int np = 0; np < 2; np++) {
                    uint32_t fr[4];
                    ldm_x4(fr, fbase + 5120 + (half*32 + np*16 + bHi8 + bR)*80 + ks*32 + bK);
                    mma_bf16(sc[2*np],   gh[ks], fr + 0);
                    mma_bf16(sc[2*np+1], gh[ks], fr + 2);
                }
            }
            tmaxA = -1e30f; tmaxB = -1e30f;
            #pragma unroll
            for (int nt = 0; nt < 4; nt++) {
                tmaxA = fmaxf(tmaxA, fmaxf(sc[nt][0], sc[nt][1]));
                tmaxB = fmaxf(tmaxB, fmaxf(sc[nt][2], sc[nt][3]));
            }
            tmaxA = fmaxf(tmaxA, __shfl_xor_sync(0xffffffffu, tmaxA, 1));
            tmaxA = fmaxf(tmaxA, __shfl_xor_sync(0xffffffffu, tmaxA, 2));
            tmaxB = fmaxf(tmaxB, __shfl_xor_sync(0xffffffffu, tmaxB, 1));
            tmaxB = fmaxf(tmaxB, __shfl_xor_sync(0xffffffffu, tmaxB, 2));
            if ((lane & 3) == 0) { myMax[rq] = tmaxA; myMax[16 + rq] = tmaxB; }

            // ---- step5: prefetch V(kt+1), F(kt+2)
            prefetch_V(sb, bf ^ 1, b, kt + 1, tid); CP_COMMIT();
            if (kt < 62) { prefetch_F(sb, bf, b, kt + 2, tid); CP_COMMIT(); }
        }

        __syncthreads();   // B2: max(kt+1) visible; P tile consumed
    }

    // ---- epilogue: write split-bf16 o ----
    const float invA = 1.0f / lA, invB = 1.0f / lB;
    const size_t rA = qbase + pair*16 + rq;
    const size_t rB = rA + 8;
    #pragma unroll
    for (int nt = 0; nt < 16; nt++) {
        int c = half*128 + nt*8 + (lane & 3)*2;
        float a0 = accO[nt][0]*invA, a1 = accO[nt][1]*invA;
        float b0 = accO[nt][2]*invB, b1 = accO[nt][3]*invB;
        __nv_bfloat16 h0,l0,h1,l1;
        split_bf16(a0,h0,l0); split_bf16(a1,h1,l1);
        *(uint32_t*)&g_o_hi[rA*CDIM + c] = pack_bf16(h0,h1);
        *(uint32_t*)&g_o_lo[rA*CDIM + c] = pack_bf16(l0,l1);
        split_bf16(b0,h0,l0); split_bf16(b1,h1,l1);
        *(uint32_t*)&g_o_hi[rB*CDIM + c] = pack_bf16(h0,h1);
        *(uint32_t*)&g_o_lo[rB*CDIM + c] = pack_bf16(l0,l1);
    }
}

// ---------------------------------------------------------------------------
extern "C" void kernel_launch(void* const* d_in, const int* in_sizes, int n_in,
                              void* d_out, int out_size) {
    const float* x     = (const float*)d_in[0];
    const float* Wf    = (const float*)d_in[1];
    const float* bf    = (const float*)d_in[2];
    const float* Wg    = (const float*)d_in[3];
    const float* bg    = (const float*)d_in[4];
    const float* Wh    = (const float*)d_in[5];
    const float* bh    = (const float*)d_in[6];
    const float* Wo    = (const float*)d_in[7];
    const float* bo    = (const float*)d_in[8];
    const float* gamma = (const float*)d_in[9];
    float*       out   = (float*)d_out;

    cudaFuncSetAttribute(pre_gemm,  cudaFuncAttributeMaxDynamicSharedMemorySize, P1_SMEM);
    cudaFuncSetAttribute(out_gemm,  cudaFuncAttributeMaxDynamicSharedMemorySize, P3_SMEM);
    cudaFuncSetAttribute(attn_hmma, cudaFuncAttributeMaxDynamicSharedMemorySize, SMEM_ATT);

    const int setup_blocks = (WPREN + WON + 255) / 256;   // 576
    setup_k<<<setup_blocks, 256>>>(Wf, Wg, Wh, Wo);
    pre_gemm<<<ROWS/128*2, 512, P1_SMEM>>>(x, bf, bg, bh);
    attn_hmma<<<512, 256, SMEM_ATT>>>();
    out_gemm<<<ROWS/128*2, 512, P3_SMEM>>>(bo, gamma, x, out);
}

// round 13
// speedup vs baseline: 6.7974x; 1.0293x over previous
#include <cuda_runtime.h>
#include <cuda_bf16.h>
#include <cuda_fp16.h>
#include <cstdint>
#include <math.h>

#define BATCH 8
#define NPIX  4096
#define CDIM  256
#define CKDIM 32
#define ROWS  (BATCH*NPIX)   // 32768
#define NPRE  320            // 32 f | 32 g | 256 h

// ---------------- scratch (allocation-free) ----------------
__device__ __align__(16) __nv_bfloat16 g_Wpre_hi[NPRE*CDIM];  // [n][k]
__device__ __align__(16) __nv_bfloat16 g_Wpre_lo[NPRE*CDIM];
__device__ __align__(16) __nv_bfloat16 g_Wo_hi[CDIM*CDIM];    // [n][k]
__device__ __align__(16) __nv_bfloat16 g_Wo_lo[CDIM*CDIM];
__device__ __align__(16) __nv_bfloat16 g_f_hi[ROWS*CKDIM];
__device__ __align__(16) __nv_bfloat16 g_f_lo[ROWS*CKDIM];
__device__ __align__(16) __nv_bfloat16 g_g_hi[ROWS*CKDIM];
__device__ __align__(16) __nv_bfloat16 g_g_lo[ROWS*CKDIM];
__device__ __align__(16) __half       g_hV [ROWS*CDIM];       // V: [row][c] fp16
__device__ __align__(16) __nv_bfloat16 g_o_hi[ROWS*CDIM];
__device__ __align__(16) __nv_bfloat16 g_o_lo[ROWS*CDIM];

// ---------------- PTX helpers ----------------
__device__ __forceinline__ uint32_t smem_u32(const void* p) {
    uint32_t a;
    asm("{ .reg .u64 t; cvta.to.shared.u64 t, %1; cvt.u32.u64 %0, t; }" : "=r"(a) : "l"(p));
    return a;
}
#define CP_ASYNC16(dst, src) \
    asm volatile("cp.async.cg.shared.global [%0], [%1], 16;" :: "r"(dst), "l"(src))
#define CP_COMMIT() asm volatile("cp.async.commit_group;" ::: "memory")
#define CP_WAIT(n)  asm volatile("cp.async.wait_group %0;" :: "n"(n) : "memory")

__device__ __forceinline__ void ldm_x4(uint32_t r[4], uint32_t addr) {
    asm volatile("ldmatrix.sync.aligned.m8n8.x4.shared.b16 {%0,%1,%2,%3}, [%4];"
                 : "=r"(r[0]), "=r"(r[1]), "=r"(r[2]), "=r"(r[3]) : "r"(addr));
}
__device__ __forceinline__ void ldm_x4_trans(uint32_t r[4], uint32_t addr) {
    asm volatile("ldmatrix.sync.aligned.m8n8.x4.trans.shared.b16 {%0,%1,%2,%3}, [%4];"
                 : "=r"(r[0]), "=r"(r[1]), "=r"(r[2]), "=r"(r[3]) : "r"(addr));
}
__device__ __forceinline__ void mma_bf16(float c[4], const uint32_t a[4], const uint32_t* b) {
    asm volatile("mma.sync.aligned.m16n8k16.row.col.f32.bf16.bf16.f32 "
                 "{%0,%1,%2,%3}, {%4,%5,%6,%7}, {%8,%9}, {%0,%1,%2,%3};"
                 : "+f"(c[0]), "+f"(c[1]), "+f"(c[2]), "+f"(c[3])
                 : "r"(a[0]), "r"(a[1]), "r"(a[2]), "r"(a[3]), "r"(b[0]), "r"(b[1]));
}
__device__ __forceinline__ void mma_f16(float c[4], const uint32_t a[4], const uint32_t* b) {
    asm volatile("mma.sync.aligned.m16n8k16.row.col.f32.f16.f16.f32 "
                 "{%0,%1,%2,%3}, {%4,%5,%6,%7}, {%8,%9}, {%0,%1,%2,%3};"
                 : "+f"(c[0]), "+f"(c[1]), "+f"(c[2]), "+f"(c[3])
                 : "r"(a[0]), "r"(a[1]), "r"(a[2]), "r"(a[3]), "r"(b[0]), "r"(b[1]));
}
__device__ __forceinline__ uint32_t pack_f16(float lo, float hi) {
    uint32_t d;
    asm("cvt.rn.f16x2.f32 %0, %1, %2;" : "=r"(d) : "f"(hi), "f"(lo));
    return d;
}
__device__ __forceinline__ uint32_t pack_bf16(__nv_bfloat16 a, __nv_bfloat16 b) {
    __nv_bfloat162 t(a, b);
    return *reinterpret_cast<uint32_t*>(&t);
}
__device__ __forceinline__ void split_bf16(float v, __nv_bfloat16& h, __nv_bfloat16& l) {
    h = __float2bfloat16(v);
    l = __float2bfloat16(v - __bfloat162float(h));
}

// ---------------------------------------------------------------------------
// Kernel 0: setup — split weights only
// ---------------------------------------------------------------------------
#define WPREN  (NPRE*CDIM)         // 81920
#define WON    (CDIM*CDIM)         // 65536
__global__ __launch_bounds__(256) void setup_k(
        const float* __restrict__ Wf, const float* __restrict__ Wg,
        const float* __restrict__ Wh, const float* __restrict__ Wo) {
    int id = blockIdx.x*256 + threadIdx.x;
    if (id < WPREN) {
        int n = id >> 8, k = id & 255;
        float v;
        if      (n < 32) v = Wf[k*CKDIM + n];
        else if (n < 64) v = Wg[k*CKDIM + (n-32)];
        else             v = Wh[k*CDIM + (n-64)];
        __nv_bfloat16 h, l; split_bf16(v, h, l);
        g_Wpre_hi[id] = h; g_Wpre_lo[id] = l;
    } else if (id < WPREN + WON) {
        int i = id - WPREN;
        int n = i >> 8, k = i & 255;
        __nv_bfloat16 h, l; split_bf16(Wo[k*CDIM + n], h, l);
        g_Wo_hi[i] = h; g_Wo_lo[i] = l;
    }
}

// ---------------------------------------------------------------------------
// Kernel 1: pre-projection GEMM.  CTA = 64 rows x 160 cols, 256 thr, 2 CTA/SM.
// A: x fp32 loaded to regs (prefetched), split to bf16 hi/lo -> STS.
// W: cp.async double-buffered.  8 k-chunks of 32.
// buf: A hi/lo 64x80B = 10240, W hi/lo 160x80B = 25600 -> 35840; x2 = 71680.
// ---------------------------------------------------------------------------
#define P1_A    0
#define P1_ALO  5120
#define P1_W    10240
#define P1_WLO  23040
#define P1_BUF  35840
#define P1_SMEM (2*P1_BUF)

__device__ __forceinline__ void p1_loadW(uint32_t sb, int buf, int nbase,
                                         int kc, int tid) {
    const uint32_t bb = sb + buf*P1_BUF;
    #pragma unroll
    for (int i = 0; i < 5; i++) {      // 1280 x 16B, 5 per thread
        int c = tid + i*256;
        int hi = c < 640;
        int cc = hi ? c : c - 640;
        int r = cc >> 2, col = cc & 3;
        const __nv_bfloat16* src = hi ? g_Wpre_hi : g_Wpre_lo;
        CP_ASYNC16(bb + (hi ? P1_W : P1_WLO) + r*80 + col*16,
                   (const char*)src + ((size_t)(nbase + r)*CDIM + kc*32 + col*8)*2);
    }
}

__global__ __launch_bounds__(256, 2) void pre_gemm(
        const float* __restrict__ x,
        const float* __restrict__ bfv, const float* __restrict__ bgv,
        const float* __restrict__ bhv) {
    extern __shared__ char smc[];
    const uint32_t sb = smem_u32(smc);
    const int tid  = threadIdx.x;
    const int lane = tid & 31;
    const int wid  = tid >> 5;
    const int wM   = wid & 3;       // 4 x 16 rows
    const int wNg  = wid >> 2;      // 0..1, 80 cols each
    const int row0  = (blockIdx.x >> 1) * 64;
    const int nbase = (blockIdx.x & 1) * 160;

    const int aRow = lane & 15;
    const int aK   = (lane >> 4) * 16;
    const int bR   = lane & 7;
    const int bHi8 = (lane >> 4) * 8;
    const int bK   = ((lane >> 3) & 1) * 16;

    const int xRow = tid >> 2;        // 0..63
    const int xC4  = tid & 3;         // 8-float group

    float acc[10][4];
    #pragma unroll
    for (int i = 0; i < 10; i++) { acc[i][0]=0.f; acc[i][1]=0.f; acc[i][2]=0.f; acc[i][3]=0.f; }

    const float* xrow = x + (size_t)(row0 + xRow)*CDIM + xC4*8;
    float4 xa = *(const float4*)(xrow + 0);
    float4 xb = *(const float4*)(xrow + 4);
    p1_loadW(sb, 0, nbase, 0, tid);
    CP_COMMIT();

    for (int kc = 0; kc < 8; kc++) {
        const int p = kc & 1;
        const uint32_t bb = sb + p*P1_BUF;

        // split x regs -> A hi/lo smem for this chunk
        {
            float v[8] = {xa.x, xa.y, xa.z, xa.w, xb.x, xb.y, xb.z, xb.w};
            uint4 uh, ul;
            uint32_t* ph = (uint32_t*)&uh;
            uint32_t* pl = (uint32_t*)&ul;
            #pragma unroll
            for (int j = 0; j < 4; j++) {
                __nv_bfloat16 h0,l0,h1,l1;
                split_bf16(v[2*j],   h0, l0);
                split_bf16(v[2*j+1], h1, l1);
                ph[j] = pack_bf16(h0, h1);
                pl[j] = pack_bf16(l0, l1);
            }
            *(uint4*)(smc + p*P1_BUF + P1_A   + xRow*80 + xC4*16) = uh;
            *(uint4*)(smc + p*P1_BUF + P1_ALO + xRow*80 + xC4*16) = ul;
        }
        CP_WAIT(0);
        __syncthreads();

        if (kc < 7) {
            const float* xn = x + (size_t)(row0 + xRow)*CDIM + (kc+1)*32 + xC4*8;
            xa = *(const float4*)(xn + 0);
            xb = *(const float4*)(xn + 4);
            p1_loadW(sb, p ^ 1, nbase, kc + 1, tid);
            CP_COMMIT();
        }

        uint32_t ahi[2][4], alo[2][4];
        #pragma unroll
        for (int ks = 0; ks < 2; ks++) {
            uint32_t ad = bb + P1_A + (wM*16 + aRow)*80 + ks*32 + aK;
            ldm_x4(ahi[ks], ad);
            ldm_x4(alo[ks], ad + (P1_ALO - P1_A));
        }
        #pragma unroll
        for (int pass = 0; pass < 3; pass++) {
            const uint32_t wb = bb + (pass == 1 ? P1_WLO : P1_W);
            #pragma unroll
            for (int ks = 0; ks < 2; ks++) {
                const uint32_t* A = (pass == 2) ? alo[ks] : ahi[ks];
                #pragma unroll
                for (int np = 0; np < 5; np++) {
                    uint32_t wf[4];
                    ldm_x4(wf, wb + (wNg*80 + np*16 + bHi8 + bR)*80 + ks*32 + bK);
                    mma_bf16(acc[2*np],   A, wf + 0);
                    mma_bf16(acc[2*np+1], A, wf + 2);
                }
            }
        }
        __syncthreads();
    }

    const int r0 = row0 + wM*16 + (lane >> 2);
    #pragma unroll
    for (int nt = 0; nt < 10; nt++) {
        int n = nbase + wNg*80 + nt*8 + (lane & 3)*2;
        #pragma unroll
        for (int h = 0; h < 2; h++) {
            int r = r0 + h*8;
            float v0 = acc[nt][2*h], v1 = acc[nt][2*h+1];
            if (n < 32) {
                v0 += bfv[n]; v1 += bfv[n+1];
                __nv_bfloat16 h0,l0,h1,l1; split_bf16(v0,h0,l0); split_bf16(v1,h1,l1);
                *(uint32_t*)&g_f_hi[(size_t)r*CKDIM + n] = pack_bf16(h0,h1);
                *(uint32_t*)&g_f_lo[(size_t)r*CKDIM + n] = pack_bf16(l0,l1);
            } else if (n < 64) {
                v0 += bgv[n-32]; v1 += bgv[n-31];
                __nv_bfloat16 h0,l0,h1,l1; split_bf16(v0,h0,l0); split_bf16(v1,h1,l1);
                *(uint32_t*)&g_g_hi[(size_t)r*CKDIM + (n-32)] = pack_bf16(h0,h1);
                *(uint32_t*)&g_g_lo[(size_t)r*CKDIM + (n-32)] = pack_bf16(l0,l1);
            } else {
                int c = n - 64;
                v0 += bhv[c]; v1 += bhv[c+1];
                *(uint32_t*)&g_hV[(size_t)r*CDIM + c] = pack_f16(v0, v1);
            }
        }
    }
}

// ---------------------------------------------------------------------------
// Kernel 3: output GEMM.  CTA = 64 rows x 128 cols, 256 thr, 2 CTA/SM (R11).
// ---------------------------------------------------------------------------
#define P3_A    0
#define P3_ALO  5120
#define P3_W    10240
#define P3_WLO  20480
#define P3_BUF  30720
#define P3_SMEM (2*P3_BUF)

__device__ __forceinline__ void p3_load(uint32_t sb, int buf, int row0, int nbase,
                                        int kc, int tid) {
    const uint32_t bb = sb + buf*P3_BUF;
    {
        int r = tid >> 2, c = tid & 3;
        uint32_t d = bb + P3_A + r*80 + c*16;
        CP_ASYNC16(d,          (const char*)g_o_hi + ((size_t)(row0 + r)*CDIM + kc*32 + c*8)*2);
        CP_ASYNC16(d + P3_ALO, (const char*)g_o_lo + ((size_t)(row0 + r)*CDIM + kc*32 + c*8)*2);
    }
    #pragma unroll
    for (int i = 0; i < 4; i++) {      // W: 1024 x 16B
        int chunk = tid + i*256;
        int hi = chunk < 512;
        int cc = hi ? chunk : chunk - 512;
        int r = cc >> 2, c = cc & 3;
        uint32_t d = bb + (hi ? P3_W : P3_WLO) + r*80 + c*16;
        const __nv_bfloat16* src = hi ? g_Wo_hi : g_Wo_lo;
        CP_ASYNC16(d, (const char*)src + ((size_t)(nbase + r)*CDIM + kc*32 + c*8)*2);
    }
}

__global__ __launch_bounds__(256, 2) void out_gemm(
        const float* __restrict__ bov, const float* __restrict__ gammav,
        const float* __restrict__ xres, float* __restrict__ outp) {
    extern __shared__ char smc[];
    const uint32_t sb = smem_u32(smc);
    const int tid  = threadIdx.x;
    const int lane = tid & 31;
    const int wid  = tid >> 5;
    const int wM   = wid & 3;
    const int wNg  = wid >> 2;      // 0..1, 64 cols each
    const int row0  = (blockIdx.x >> 1) * 64;
    const int nbase = (blockIdx.x & 1) * 128;

    const int aRow = lane & 15;
    const int aK   = (lane >> 4) * 16;
    const int bR   = lane & 7;
    const int bHi8 = (lane >> 4) * 8;
    const int bK   = ((lane >> 3) & 1) * 16;

    float acc[8][4];
    #pragma unroll
    for (int i = 0; i < 8; i++) { acc[i][0]=0.f; acc[i][1]=0.f; acc[i][2]=0.f; acc[i][3]=0.f; }

    p3_load(sb, 0, row0, nbase, 0, tid);
    CP_COMMIT();

    for (int kc = 0; kc < 8; kc++) {
        CP_WAIT(0);
        __syncthreads();
        if (kc < 7) { p3_load(sb, (kc+1)&1, row0, nbase, kc+1, tid); CP_COMMIT(); }

        const uint32_t bb = sb + (kc&1)*P3_BUF;
        uint32_t ahi[2][4], alo[2][4];
        #pragma unroll
        for (int ks = 0; ks < 2; ks++) {
            uint32_t ad = bb + P3_A + (wM*16 + aRow)*80 + ks*32 + aK;
            ldm_x4(ahi[ks], ad);
            ldm_x4(alo[ks], ad + (P3_ALO - P3_A));
        }
        #pragma unroll
        for (int pass = 0; pass < 3; pass++) {
            const uint32_t wb = bb + (pass == 1 ? P3_WLO : P3_W);
            #pragma unroll
            for (int ks = 0; ks < 2; ks++) {
                const uint32_t* A = (pass == 2) ? alo[ks] : ahi[ks];
                #pragma unroll
                for (int np = 0; np < 4; np++) {
                    uint32_t wf[4];
                    ldm_x4(wf, wb + (wNg*64 + np*16 + bHi8 + bR)*80 + ks*32 + bK);
                    mma_bf16(acc[2*np],   A, wf + 0);
                    mma_bf16(acc[2*np+1], A, wf + 2);
                }
            }
        }
        __syncthreads();
    }

    const float gam = gammav[0];
    const int r0 = row0 + wM*16 + (lane >> 2);
    #pragma unroll
    for (int nt = 0; nt < 8; nt++) {
        int n = nbase + wNg*64 + nt*8 + (lane & 3)*2;
        #pragma unroll
        for (int h = 0; h < 2; h++) {
            int r = r0 + h*8;
            float2 xr = *(const float2*)(xres + (size_t)r*CDIM + n);
            float2 o;
            o.x = gam*(acc[nt][2*h]   + bov[n])   + xr.x;
            o.y = gam*(acc[nt][2*h+1] + bov[n+1]) + xr.y;
            *(float2*)(outp + (size_t)r*CDIM + n) = o;
        }
    }
}

// ---------------------------------------------------------------------------
// Kernel 2: HMMA flash attention, pair-split, 2 barriers/tile.
// Prefetch issued right after B1 (before PV+S) -> full-tile load window.
// ---------------------------------------------------------------------------
#define OFF_G   0                     // 2x 5120 (hi/lo)
#define OFF_F   10240                 // 2 bufs x (hi 5120 + lo 5120)
#define OFF_V   (OFF_F + 2*10240)     // 2 bufs x 64*528 = 67584
#define OFF_P   (OFF_V + 2*33792)     // 4 pairs x 16 rows x 144B = 9216
#define OFF_MAX (OFF_P + 9216)        // 1024
#define OFF_SUM (OFF_MAX + 1024)      // 1024
#define SMEM_ATT (OFF_SUM + 1024)     // 109568 B

__device__ __forceinline__ void prefetch_F(uint32_t sb, int buf, int b, int kt, int tid) {
    const size_t kbase = (size_t)b*NPIX + (size_t)kt*64;
    int fr = tid >> 2, fc = tid & 3;
    uint32_t fd = sb + OFF_F + buf*10240 + fr*80 + fc*16;
    CP_ASYNC16(fd,        (const char*)g_f_hi + ((kbase + fr)*CKDIM + fc*8)*2);
    CP_ASYNC16(fd + 5120, (const char*)g_f_lo + ((kbase + fr)*CKDIM + fc*8)*2);
}
__device__ __forceinline__ void prefetch_V(uint32_t sb, int buf, int b, int kt, int tid) {
    const size_t kbase = (size_t)b*NPIX + (size_t)kt*64;
    #pragma unroll
    for (int i = 0; i < 8; i++) {
        int chunk = tid + i*256;
        int vr = chunk >> 5, vc = chunk & 31;
        uint32_t vd = sb + OFF_V + buf*33792 + vr*528 + vc*16;
        CP_ASYNC16(vd, (const char*)g_hV + ((kbase + vr)*CDIM + vc*8)*2);
    }
}

__global__ __launch_bounds__(256, 2) void attn_hmma() {
    extern __shared__ char smc[];
    const uint32_t sb = smem_u32(smc);
    const int tid  = threadIdx.x;
    const int lane = tid & 31;
    const int wid  = tid >> 5;
    const int pair = wid >> 1;     // 0..3 : q-rows pair*16
    const int half = wid & 1;      // 0..1 : keys half*32 (S), ch half*128 (PV)
    const int b    = blockIdx.x >> 6;
    const int qt   = blockIdx.x & 63;
    const size_t qbase = (size_t)b*NPIX + qt*64;

    float* sMax = (float*)(smc + OFF_MAX);   // [pair][half][2][16]
    float* sSum = (float*)(smc + OFF_SUM);

    const int aRow = lane & 15;
    const int aK   = (lane >> 4) * 16;
    const int bR   = lane & 7;
    const int bHi8 = (lane >> 4) * 8;
    const int bK   = ((lane >> 3) & 1) * 16;
    const int tR   = lane & 15;
    const int tC   = (lane >> 4) * 16;
    const int rq   = lane >> 2;

    const uint32_t pTile = sb + OFF_P + pair*2304;
    float* myMax  = sMax + (pair*2 + half)*32;
    float* sibMax = sMax + (pair*2 + (half^1))*32;
    float* mySum  = sSum + (pair*2 + half)*32;
    float* sibSum = sSum + (pair*2 + (half^1))*32;

    // ---- prologue: stage G + F0 + V0
    {
        int gr = tid >> 2, gc = tid & 3;
        uint32_t gd = sb + OFF_G + gr*80 + gc*16;
        CP_ASYNC16(gd,        (const char*)g_g_hi + ((qbase + gr)*CKDIM + gc*8)*2);
        CP_ASYNC16(gd + 5120, (const char*)g_g_lo + ((qbase + gr)*CKDIM + gc*8)*2);
        prefetch_F(sb, 0, b, 0, tid);
        prefetch_V(sb, 0, b, 0, tid);
        CP_COMMIT();
    }
    CP_WAIT(0);
    __syncthreads();

    uint32_t gh[2][4], gl[2][4];
    #pragma unroll
    for (int ks = 0; ks < 2; ks++) {
        uint32_t ad = sb + OFF_G + (pair*16 + aRow)*80 + ks*32 + aK;
        ldm_x4(gh[ks], ad);
        ldm_x4(gl[ks], ad + 5120);
    }

    float accO[16][4];
    #pragma unroll
    for (int i = 0; i < 16; i++) { accO[i][0]=0.f; accO[i][1]=0.f; accO[i][2]=0.f; accO[i][3]=0.f; }
    float mA = -1e30f, mB = -1e30f, lA = 0.f, lB = 0.f;
    float sc[4][4];
    float tmaxA, tmaxB;

    // ---- S(0) + own max + max write
    {
        #pragma unroll
        for (int i = 0; i < 4; i++) { sc[i][0]=0.f; sc[i][1]=0.f; sc[i][2]=0.f; sc[i][3]=0.f; }
        const uint32_t fbase = sb + OFF_F;
        #pragma unroll
        for (int ks = 0; ks < 2; ks++) {
            #pragma unroll
            for (int np = 0; np < 2; np++) {
                uint32_t fr[4];
                ldm_x4(fr, fbase + (half*32 + np*16 + bHi8 + bR)*80 + ks*32 + bK);
                mma_bf16(sc[2*np],   gh[ks], fr + 0);
                mma_bf16(sc[2*np+1], gh[ks], fr + 2);
                mma_bf16(sc[2*np],   gl[ks], fr + 0);
                mma_bf16(sc[2*np+1], gl[ks], fr + 2);
            }
        }
        #pragma unroll
        for (int ks = 0; ks < 2; ks++) {
            #pragma unroll
            for (int np = 0; np < 2; np++) {
                uint32_t fr[4];
                ldm_x4(fr, fbase + 5120 + (half*32 + np*16 + bHi8 + bR)*80 + ks*32 + bK);
                mma_bf16(sc[2*np],   gh[ks], fr + 0);
                mma_bf16(sc[2*np+1], gh[ks], fr + 2);
            }
        }
        tmaxA = -1e30f; tmaxB = -1e30f;
        #pragma unroll
        for (int nt = 0; nt < 4; nt++) {
            tmaxA = fmaxf(tmaxA, fmaxf(sc[nt][0], sc[nt][1]));
            tmaxB = fmaxf(tmaxB, fmaxf(sc[nt][2], sc[nt][3]));
        }
        tmaxA = fmaxf(tmaxA, __shfl_xor_sync(0xffffffffu, tmaxA, 1));
        tmaxA = fmaxf(tmaxA, __shfl_xor_sync(0xffffffffu, tmaxA, 2));
        tmaxB = fmaxf(tmaxB, __shfl_xor_sync(0xffffffffu, tmaxB, 1));
        tmaxB = fmaxf(tmaxB, __shfl_xor_sync(0xffffffffu, tmaxB, 2));
        if ((lane & 3) == 0) { myMax[rq] = tmaxA; myMax[16 + rq] = tmaxB; }
    }
    prefetch_F(sb, 1, b, 1, tid);
    CP_COMMIT();
    __syncthreads();   // maxes(0) visible

    for (int kt = 0; kt < 64; kt++) {
        const int bf = kt & 1;

        // ---- step1: exp(kt) + P write + sums
        float mnA = fmaxf(mA, fmaxf(tmaxA, sibMax[rq]));
        float mnB = fmaxf(mB, fmaxf(tmaxB, sibMax[16 + rq]));
        float scA = __expf(mA - mnA), scB = __expf(mB - mnB);
        bool noscale = __all_sync(0xffffffffu, (scA == 1.0f) && (scB == 1.0f));
        float sumA = 0.f, sumB = 0.f;
        #pragma unroll
        for (int nt = 0; nt < 4; nt++) {
            float p0 = __expf(sc[nt][0] - mnA);
            float p1 = __expf(sc[nt][1] - mnA);
            float p2 = __expf(sc[nt][2] - mnB);
            float p3 = __expf(sc[nt][3] - mnB);
            sumA += p0 + p1; sumB += p2 + p3;
            uint32_t cOff = (half*32 + nt*8 + (lane & 3)*2)*2;
            *(uint32_t*)(smc + (pTile - sb) + rq*144 + cOff)       = pack_f16(p0, p1);
            *(uint32_t*)(smc + (pTile - sb) + (rq + 8)*144 + cOff) = pack_f16(p2, p3);
        }
        sumA += __shfl_xor_sync(0xffffffffu, sumA, 1);
        sumA += __shfl_xor_sync(0xffffffffu, sumA, 2);
        sumB += __shfl_xor_sync(0xffffffffu, sumB, 1);
        sumB += __shfl_xor_sync(0xffffffffu, sumB, 2);
        if ((lane & 3) == 0) { mySum[rq] = sumA; mySum[16 + rq] = sumB; }

        // ---- step2: V(kt), F(kt+1) arrived; P/sums visible
        CP_WAIT(0);
        __syncthreads();   // B1

        // ---- step2b: prefetch NOW (full PV+S window before next B1 wait)
        // V buf bf^1 held V(kt-1): consumed last iter, fenced by B2.
        // F buf bf held F(kt): consumed last iter's S, fenced by B2.
        if (kt < 63) {
            prefetch_V(sb, bf ^ 1, b, kt + 1, tid); CP_COMMIT();
            if (kt < 62) { prefetch_F(sb, bf, b, kt + 2, tid); CP_COMMIT(); }
        }

        // ---- step3: stats merge + (conditional) rescale + PV(kt)
        lA = lA*scA + sumA + sibSum[rq];
        lB = lB*scB + sumB + sibSum[16 + rq];
        mA = mnA;  mB = mnB;
        if (!noscale) {
            #pragma unroll
            for (int nt = 0; nt < 16; nt++) {
                accO[nt][0] *= scA; accO[nt][1] *= scA;
                accO[nt][2] *= scB; accO[nt][3] *= scB;
            }
        }
        uint32_t pa[4][4];
        #pragma unroll
        for (int ks = 0; ks < 4; ks++)
            ldm_x4(pa[ks], pTile + aRow*144 + ks*32 + aK);
        const uint32_t vbase = sb + OFF_V + bf*33792 + half*256;
        #pragma unroll
        for (int ks = 0; ks < 4; ks++) {
            #pragma unroll
            for (int np = 0; np < 8; np++) {
                uint32_t vr[4];
                ldm_x4_trans(vr, vbase + (ks*16 + tR)*528 + np*32 + tC);
                mma_f16(accO[2*np],   pa[ks], vr + 0);
                mma_f16(accO[2*np+1], pa[ks], vr + 2);
            }
        }

        // ---- step4: S(kt+1) + own max + max write
        if (kt < 63) {
            #pragma unroll
            for (int i = 0; i < 4; i++) { sc[i][0]=0.f; sc[i][1]=0.f; sc[i][2]=0.f; sc[i][3]=0.f; }
            const uint32_t fbase = sb + OFF_F + (bf^1)*10240;
            #pragma unroll
            for (int ks = 0; ks < 2; ks++) {
                #pragma unroll
                for (int np = 0; np < 2; np++) {
                    uint32_t fr[4];
                    ldm_x4(fr, fbase + (half*32 + np*16 + bHi8 + bR)*80 + ks*32 + bK);
                    mma_bf16(sc[2*np],   gh[ks], fr + 0);
                    mma_bf16(sc[2*np+1], gh[ks], fr + 2);
                    mma_bf16(sc[2*np],   gl[ks], fr + 0);
                    mma_bf16(sc[2*np+1], gl[ks], fr + 2);
                }
            }
            #pragma unroll
            for (int ks = 0; ks < 2; ks++) {
                #pragma unroll
                for (int np = 0; np < 2; np++) {
                    uint32_t fr[4];
                    ldm_x4(fr, fbase + 5120 + (half*32 + np*16 + bHi8 + bR)*80 + ks*32 + bK);
                    mma_bf16(sc[2*np],   gh[ks], fr + 0);
                    mma_bf16(sc[2*np+1], gh[ks], fr + 2);
                }
            }
            tmaxA = -1e30f; tmaxB = -1e30f;
            #pragma unroll
            for (int nt = 0; nt < 4; nt++) {
                tmaxA = fmaxf(tmaxA, fmaxf(sc[nt][0], sc[nt][1]));
                tmaxB = fmaxf(tmaxB, fmaxf(sc[nt][2], sc[nt][3]));
            }
            tmaxA = fmaxf(tmaxA, __shfl_xor_sync(0xffffffffu, tmaxA, 1));
            tmaxA = fmaxf(tmaxA, __shfl_xor_sync(0xffffffffu, tmaxA, 2));
            tmaxB = fmaxf(tmaxB, __shfl_xor_sync(0xffffffffu, tmaxB, 1));
            tmaxB = fmaxf(tmaxB, __shfl_xor_sync(0xffffffffu, tmaxB, 2));
            if ((lane & 3) == 0) { myMax[rq] = tmaxA; myMax[16 + rq] = tmaxB; }
        }

        __syncthreads();   // B2: max(kt+1) visible; P tile consumed
    }

    // ---- epilogue: write split-bf16 o ----
    const float invA = 1.0f / lA, invB = 1.0f / lB;
    const size_t rA = qbase + pair*16 + rq;
    const size_t rB = rA + 8;
    #pragma unroll
    for (int nt = 0; nt < 16; nt++) {
        int c = half*128 + nt*8 + (lane & 3)*2;
        float a0 = accO[nt][0]*invA, a1 = accO[nt][1]*invA;
        float b0 = accO[nt][2]*invB, b1 = accO[nt][3]*invB;
        __nv_bfloat16 h0,l0,h1,l1;
        split_bf16(a0,h0,l0); split_bf16(a1,h1,l1);
        *(uint32_t*)&g_o_hi[rA*CDIM + c] = pack_bf16(h0,h1);
        *(uint32_t*)&g_o_lo[rA*CDIM + c] = pack_bf16(l0,l1);
        split_bf16(b0,h0,l0); split_bf16(b1,h1,l1);
        *(uint32_t*)&g_o_hi[rB*CDIM + c] = pack_bf16(h0,h1);
        *(uint32_t*)&g_o_lo[rB*CDIM + c] = pack_bf16(l0,l1);
    }
}

// ---------------------------------------------------------------------------
extern "C" void kernel_launch(void* const* d_in, const int* in_sizes, int n_in,
                              void* d_out, int out_size) {
    const float* x     = (const float*)d_in[0];
    const float* Wf    = (const float*)d_in[1];
    const float* bf    = (const float*)d_in[2];
    const float* Wg    = (const float*)d_in[3];
    const float* bg    = (const float*)d_in[4];
    const float* Wh    = (const float*)d_in[5];
    const float* bh    = (const float*)d_in[6];
    const float* Wo    = (const float*)d_in[7];
    const float* bo    = (const float*)d_in[8];
    const float* gamma = (const float*)d_in[9];
    float*       out   = (float*)d_out;

    cudaFuncSetAttribute(pre_gemm,  cudaFuncAttributeMaxDynamicSharedMemorySize, P1_SMEM);
    cudaFuncSetAttribute(out_gemm,  cudaFuncAttributeMaxDynamicSharedMemorySize, P3_SMEM);
    cudaFuncSetAttribute(attn_hmma, cudaFuncAttributeMaxDynamicSharedMemorySize, SMEM_ATT);

    const int setup_blocks = (WPREN + WON + 255) / 256;   // 576
    setup_k<<<setup_blocks, 256>>>(Wf, Wg, Wh, Wo);
    pre_gemm<<<ROWS/64*2, 256, P1_SMEM>>>(x, bf, bg, bh);
    attn_hmma<<<512, 256, SMEM_ATT>>>();
    out_gemm<<<ROWS/64*2, 256, P3_SMEM>>>(bo, gamma, x, out);
}

// round 14
// speedup vs baseline: 7.5198x; 1.1063x over previous
#include <cuda_runtime.h>
#include <cuda_bf16.h>
#include <cuda_fp16.h>
#include <cstdint>
#include <math.h>

#define BATCH 8
#define NPIX  4096
#define CDIM  256
#define CKDIM 32
#define ROWS  (BATCH*NPIX)   // 32768
#define NPRE  320            // 32 f | 32 g | 256 h

// ---------------- scratch (allocation-free) ----------------
__device__ __align__(16) __half g_Wpre_hi[NPRE*CDIM];  // [n][k] fp16 hi
__device__ __align__(16) __half g_Wpre_lo[NPRE*CDIM];
__device__ __align__(16) __half g_Wo_hi[CDIM*CDIM];    // [n][k]
__device__ __align__(16) __half g_Wo_lo[CDIM*CDIM];
__device__ __align__(16) __half g_f_hi[ROWS*CKDIM];
__device__ __align__(16) __half g_f_lo[ROWS*CKDIM];
__device__ __align__(16) __half g_g  [ROWS*CKDIM];     // single fp16
__device__ __align__(16) __half g_hV [ROWS*CDIM];      // V: [row][c] fp16
__device__ __align__(16) __half g_o  [ROWS*CDIM];      // single fp16

// ---------------- PTX helpers ----------------
__device__ __forceinline__ uint32_t smem_u32(const void* p) {
    uint32_t a;
    asm("{ .reg .u64 t; cvta.to.shared.u64 t, %1; cvt.u32.u64 %0, t; }" : "=r"(a) : "l"(p));
    return a;
}
#define CP_ASYNC16(dst, src) \
    asm volatile("cp.async.cg.shared.global [%0], [%1], 16;" :: "r"(dst), "l"(src))
#define CP_COMMIT() asm volatile("cp.async.commit_group;" ::: "memory")
#define CP_WAIT(n)  asm volatile("cp.async.wait_group %0;" :: "n"(n) : "memory")

__device__ __forceinline__ void ldm_x4(uint32_t r[4], uint32_t addr) {
    asm volatile("ldmatrix.sync.aligned.m8n8.x4.shared.b16 {%0,%1,%2,%3}, [%4];"
                 : "=r"(r[0]), "=r"(r[1]), "=r"(r[2]), "=r"(r[3]) : "r"(addr));
}
__device__ __forceinline__ void ldm_x4_trans(uint32_t r[4], uint32_t addr) {
    asm volatile("ldmatrix.sync.aligned.m8n8.x4.trans.shared.b16 {%0,%1,%2,%3}, [%4];"
                 : "=r"(r[0]), "=r"(r[1]), "=r"(r[2]), "=r"(r[3]) : "r"(addr));
}
__device__ __forceinline__ void mma_f16(float c[4], const uint32_t a[4], const uint32_t* b) {
    asm volatile("mma.sync.aligned.m16n8k16.row.col.f32.f16.f16.f32 "
                 "{%0,%1,%2,%3}, {%4,%5,%6,%7}, {%8,%9}, {%0,%1,%2,%3};"
                 : "+f"(c[0]), "+f"(c[1]), "+f"(c[2]), "+f"(c[3])
                 : "r"(a[0]), "r"(a[1]), "r"(a[2]), "r"(a[3]), "r"(b[0]), "r"(b[1]));
}
__device__ __forceinline__ uint32_t pack_f16(float lo, float hi) {
    uint32_t d;
    asm("cvt.rn.f16x2.f32 %0, %1, %2;" : "=r"(d) : "f"(hi), "f"(lo));
    return d;
}
__device__ __forceinline__ void split_f16(float v, __half& h, __half& l) {
    h = __float2half_rn(v);
    l = __float2half_rn(v - __half2float(h));
}
__device__ __forceinline__ uint32_t pack_h2(__half a, __half b) {
    __half2 t(a, b);
    return *reinterpret_cast<uint32_t*>(&t);
}

// ---------------------------------------------------------------------------
// Kernel 0: setup — split weights to fp16 hi/lo
// ---------------------------------------------------------------------------
#define WPREN  (NPRE*CDIM)         // 81920
#define WON    (CDIM*CDIM)         // 65536
__global__ __launch_bounds__(256) void setup_k(
        const float* __restrict__ Wf, const float* __restrict__ Wg,
        const float* __restrict__ Wh, const float* __restrict__ Wo) {
    int id = blockIdx.x*256 + threadIdx.x;
    if (id < WPREN) {
        int n = id >> 8, k = id & 255;
        float v;
        if      (n < 32) v = Wf[k*CKDIM + n];
        else if (n < 64) v = Wg[k*CKDIM + (n-32)];
        else             v = Wh[k*CDIM + (n-64)];
        __half h, l; split_f16(v, h, l);
        g_Wpre_hi[id] = h; g_Wpre_lo[id] = l;
    } else if (id < WPREN + WON) {
        int i = id - WPREN;
        int n = i >> 8, k = i & 255;
        __half h, l; split_f16(Wo[k*CDIM + n], h, l);
        g_Wo_hi[i] = h; g_Wo_lo[i] = l;
    }
}

// ---------------------------------------------------------------------------
// Kernel 1: pre-projection GEMM.  CTA = 64 rows x 160 cols, 256 thr, 2 CTA/SM.
// A: x fp32 -> regs -> single fp16 STS.  W: fp16 hi/lo cp.async.  2 MMA passes.
// buf: A 64x80B = 5120, W hi/lo 160x80B = 25600 -> 30720; x2 = 61440.
// ---------------------------------------------------------------------------
#define P1_A    0
#define P1_W    5120
#define P1_WLO  17920
#define P1_BUF  30720
#define P1_SMEM (2*P1_BUF)

__device__ __forceinline__ void p1_loadW(uint32_t sb, int buf, int nbase,
                                         int kc, int tid) {
    const uint32_t bb = sb + buf*P1_BUF;
    #pragma unroll
    for (int i = 0; i < 5; i++) {      // 1280 x 16B, 5 per thread
        int c = tid + i*256;
        int hi = c < 640;
        int cc = hi ? c : c - 640;
        int r = cc >> 2, col = cc & 3;
        const __half* src = hi ? g_Wpre_hi : g_Wpre_lo;
        CP_ASYNC16(bb + (hi ? P1_W : P1_WLO) + r*80 + col*16,
                   (const char*)src + ((size_t)(nbase + r)*CDIM + kc*32 + col*8)*2);
    }
}

__global__ __launch_bounds__(256, 2) void pre_gemm(
        const float* __restrict__ x,
        const float* __restrict__ bfv, const float* __restrict__ bgv,
        const float* __restrict__ bhv) {
    extern __shared__ char smc[];
    const uint32_t sb = smem_u32(smc);
    const int tid  = threadIdx.x;
    const int lane = tid & 31;
    const int wid  = tid >> 5;
    const int wM   = wid & 3;       // 4 x 16 rows
    const int wNg  = wid >> 2;      // 0..1, 80 cols each
    const int row0  = (blockIdx.x >> 1) * 64;
    const int nbase = (blockIdx.x & 1) * 160;

    const int aRow = lane & 15;
    const int aK   = (lane >> 4) * 16;
    const int bR   = lane & 7;
    const int bHi8 = (lane >> 4) * 8;
    const int bK   = ((lane >> 3) & 1) * 16;

    const int xRow = tid >> 2;        // 0..63
    const int xC4  = tid & 3;         // 8-float group

    float acc[10][4];
    #pragma unroll
    for (int i = 0; i < 10; i++) { acc[i][0]=0.f; acc[i][1]=0.f; acc[i][2]=0.f; acc[i][3]=0.f; }

    const float* xrow = x + (size_t)(row0 + xRow)*CDIM + xC4*8;
    float4 xa = *(const float4*)(xrow + 0);
    float4 xb = *(const float4*)(xrow + 4);
    p1_loadW(sb, 0, nbase, 0, tid);
    CP_COMMIT();

    for (int kc = 0; kc < 8; kc++) {
        const int p = kc & 1;
        const uint32_t bb = sb + p*P1_BUF;

        // x regs -> single fp16 A smem
        {
            uint4 u;
            uint32_t* pu = (uint32_t*)&u;
            pu[0] = pack_f16(xa.x, xa.y);
            pu[1] = pack_f16(xa.z, xa.w);
            pu[2] = pack_f16(xb.x, xb.y);
            pu[3] = pack_f16(xb.z, xb.w);
            *(uint4*)(smc + p*P1_BUF + P1_A + xRow*80 + xC4*16) = u;
        }
        CP_WAIT(0);
        __syncthreads();

        if (kc < 7) {
            const float* xn = x + (size_t)(row0 + xRow)*CDIM + (kc+1)*32 + xC4*8;
            xa = *(const float4*)(xn + 0);
            xb = *(const float4*)(xn + 4);
            p1_loadW(sb, p ^ 1, nbase, kc + 1, tid);
            CP_COMMIT();
        }

        uint32_t af[2][4];
        #pragma unroll
        for (int ks = 0; ks < 2; ks++)
            ldm_x4(af[ks], bb + P1_A + (wM*16 + aRow)*80 + ks*32 + aK);
        #pragma unroll
        for (int pass = 0; pass < 2; pass++) {
            const uint32_t wb = bb + (pass == 1 ? P1_WLO : P1_W);
            #pragma unroll
            for (int ks = 0; ks < 2; ks++) {
                #pragma unroll
                for (int np = 0; np < 5; np++) {
                    uint32_t wf[4];
                    ldm_x4(wf, wb + (wNg*80 + np*16 + bHi8 + bR)*80 + ks*32 + bK);
                    mma_f16(acc[2*np],   af[ks], wf + 0);
                    mma_f16(acc[2*np+1], af[ks], wf + 2);
                }
            }
        }
        __syncthreads();
    }

    const int r0 = row0 + wM*16 + (lane >> 2);
    #pragma unroll
    for (int nt = 0; nt < 10; nt++) {
        int n = nbase + wNg*80 + nt*8 + (lane & 3)*2;
        #pragma unroll
        for (int h = 0; h < 2; h++) {
            int r = r0 + h*8;
            float v0 = acc[nt][2*h], v1 = acc[nt][2*h+1];
            if (n < 32) {
                v0 += bfv[n]; v1 += bfv[n+1];
                __half h0,l0,h1,l1; split_f16(v0,h0,l0); split_f16(v1,h1,l1);
                *(uint32_t*)&g_f_hi[(size_t)r*CKDIM + n] = pack_h2(h0,h1);
                *(uint32_t*)&g_f_lo[(size_t)r*CKDIM + n] = pack_h2(l0,l1);
            } else if (n < 64) {
                v0 += bgv[n-32]; v1 += bgv[n-31];
                *(uint32_t*)&g_g[(size_t)r*CKDIM + (n-32)] = pack_f16(v0, v1);
            } else {
                int c = n - 64;
                v0 += bhv[c]; v1 += bhv[c+1];
                *(uint32_t*)&g_hV[(size_t)r*CDIM + c] = pack_f16(v0, v1);
            }
        }
    }
}

// ---------------------------------------------------------------------------
// Kernel 3: output GEMM.  CTA = 64 rows x 128 cols, 256 thr, 2 CTA/SM.
// A: o single fp16.  W: Wo hi/lo fp16.  2 MMA passes.
// buf: A 5120 + W 20480 = 25600; x2 = 51200.
// ---------------------------------------------------------------------------
#define P3_A    0
#define P3_W    5120
#define P3_WLO  15360
#define P3_BUF  25600
#define P3_SMEM (2*P3_BUF)

__device__ __forceinline__ void p3_load(uint32_t sb, int buf, int row0, int nbase,
                                        int kc, int tid) {
    const uint32_t bb = sb + buf*P3_BUF;
    {
        int r = tid >> 2, c = tid & 3;
        CP_ASYNC16(bb + P3_A + r*80 + c*16,
                   (const char*)g_o + ((size_t)(row0 + r)*CDIM + kc*32 + c*8)*2);
    }
    #pragma unroll
    for (int i = 0; i < 4; i++) {      // W: 1024 x 16B
        int chunk = tid + i*256;
        int hi = chunk < 512;
        int cc = hi ? chunk : chunk - 512;
        int r = cc >> 2, c = cc & 3;
        const __half* src = hi ? g_Wo_hi : g_Wo_lo;
        CP_ASYNC16(bb + (hi ? P3_W : P3_WLO) + r*80 + c*16,
                   (const char*)src + ((size_t)(nbase + r)*CDIM + kc*32 + c*8)*2);
    }
}

__global__ __launch_bounds__(256, 2) void out_gemm(
        const float* __restrict__ bov, const float* __restrict__ gammav,
        const float* __restrict__ xres, float* __restrict__ outp) {
    extern __shared__ char smc[];
    const uint32_t sb = smem_u32(smc);
    const int tid  = threadIdx.x;
    const int lane = tid & 31;
    const int wid  = tid >> 5;
    const int wM   = wid & 3;
    const int wNg  = wid >> 2;      // 0..1, 64 cols each
    const int row0  = (blockIdx.x >> 1) * 64;
    const int nbase = (blockIdx.x & 1) * 128;

    const int aRow = lane & 15;
    const int aK   = (lane >> 4) * 16;
    const int bR   = lane & 7;
    const int bHi8 = (lane >> 4) * 8;
    const int bK   = ((lane >> 3) & 1) * 16;

    float acc[8][4];
    #pragma unroll
    for (int i = 0; i < 8; i++) { acc[i][0]=0.f; acc[i][1]=0.f; acc[i][2]=0.f; acc[i][3]=0.f; }

    p3_load(sb, 0, row0, nbase, 0, tid);
    CP_COMMIT();

    for (int kc = 0; kc < 8; kc++) {
        CP_WAIT(0);
        __syncthreads();
        if (kc < 7) { p3_load(sb, (kc+1)&1, row0, nbase, kc+1, tid); CP_COMMIT(); }

        const uint32_t bb = sb + (kc&1)*P3_BUF;
        uint32_t af[2][4];
        #pragma unroll
        for (int ks = 0; ks < 2; ks++)
            ldm_x4(af[ks], bb + P3_A + (wM*16 + aRow)*80 + ks*32 + aK);
        #pragma unroll
        for (int pass = 0; pass < 2; pass++) {
            const uint32_t wb = bb + (pass == 1 ? P3_WLO : P3_W);
            #pragma unroll
            for (int ks = 0; ks < 2; ks++) {
                #pragma unroll
                for (int np = 0; np < 4; np++) {
                    uint32_t wf[4];
                    ldm_x4(wf, wb + (wNg*64 + np*16 + bHi8 + bR)*80 + ks*32 + bK);
                    mma_f16(acc[2*np],   af[ks], wf + 0);
                    mma_f16(acc[2*np+1], af[ks], wf + 2);
                }
            }
        }
        __syncthreads();
    }

    const float gam = gammav[0];
    const int r0 = row0 + wM*16 + (lane >> 2);
    #pragma unroll
    for (int nt = 0; nt < 8; nt++) {
        int n = nbase + wNg*64 + nt*8 + (lane & 3)*2;
        #pragma unroll
        for (int h = 0; h < 2; h++) {
            int r = r0 + h*8;
            float2 xr = *(const float2*)(xres + (size_t)r*CDIM + n);
            float2 o;
            o.x = gam*(acc[nt][2*h]   + bov[n])   + xr.x;
            o.y = gam*(acc[nt][2*h+1] + bov[n+1]) + xr.y;
            *(float2*)(outp + (size_t)r*CDIM + n) = o;
        }
    }
}

// ---------------------------------------------------------------------------
// Kernel 2: HMMA flash attention, pair-split, fp16 S (2 passes).
// G single fp16; F fp16 hi/lo.  Pipeline as R13.
// ---------------------------------------------------------------------------
#define OFF_G   0                     // 5120 (single)
#define OFF_F   5120                  // 2 bufs x (hi 5120 + lo 5120)
#define OFF_V   (OFF_F + 2*10240)     // 2 bufs x 64*528 = 67584
#define OFF_P   (OFF_V + 2*33792)     // 4 pairs x 16 rows x 144B = 9216
#define OFF_MAX (OFF_P + 9216)        // 1024
#define OFF_SUM (OFF_MAX + 1024)      // 1024
#define SMEM_ATT (OFF_SUM + 1024)     // 104448 B

__device__ __forceinline__ void prefetch_F(uint32_t sb, int buf, int b, int kt, int tid) {
    const size_t kbase = (size_t)b*NPIX + (size_t)kt*64;
    int fr = tid >> 2, fc = tid & 3;
    uint32_t fd = sb + OFF_F + buf*10240 + fr*80 + fc*16;
    CP_ASYNC16(fd,        (const char*)g_f_hi + ((kbase + fr)*CKDIM + fc*8)*2);
    CP_ASYNC16(fd + 5120, (const char*)g_f_lo + ((kbase + fr)*CKDIM + fc*8)*2);
}
__device__ __forceinline__ void prefetch_V(uint32_t sb, int buf, int b, int kt, int tid) {
    const size_t kbase = (size_t)b*NPIX + (size_t)kt*64;
    #pragma unroll
    for (int i = 0; i < 8; i++) {
        int chunk = tid + i*256;
        int vr = chunk >> 5, vc = chunk & 31;
        uint32_t vd = sb + OFF_V + buf*33792 + vr*528 + vc*16;
        CP_ASYNC16(vd, (const char*)g_hV + ((kbase + vr)*CDIM + vc*8)*2);
    }
}

__global__ __launch_bounds__(256, 2) void attn_hmma() {
    extern __shared__ char smc[];
    const uint32_t sb = smem_u32(smc);
    const int tid  = threadIdx.x;
    const int lane = tid & 31;
    const int wid  = tid >> 5;
    const int pair = wid >> 1;     // 0..3 : q-rows pair*16
    const int half = wid & 1;      // 0..1 : keys half*32 (S), ch half*128 (PV)
    const int b    = blockIdx.x >> 6;
    const int qt   = blockIdx.x & 63;
    const size_t qbase = (size_t)b*NPIX + qt*64;

    float* sMax = (float*)(smc + OFF_MAX);   // [pair][half][2][16]
    float* sSum = (float*)(smc + OFF_SUM);

    const int aRow = lane & 15;
    const int aK   = (lane >> 4) * 16;
    const int bR   = lane & 7;
    const int bHi8 = (lane >> 4) * 8;
    const int bK   = ((lane >> 3) & 1) * 16;
    const int tR   = lane & 15;
    const int tC   = (lane >> 4) * 16;
    const int rq   = lane >> 2;

    const uint32_t pTile = sb + OFF_P + pair*2304;
    float* myMax  = sMax + (pair*2 + half)*32;
    float* sibMax = sMax + (pair*2 + (half^1))*32;
    float* mySum  = sSum + (pair*2 + half)*32;
    float* sibSum = sSum + (pair*2 + (half^1))*32;

    // ---- prologue: stage G + F0 + V0
    {
        int gr = tid >> 2, gc = tid & 3;
        CP_ASYNC16(sb + OFF_G + gr*80 + gc*16,
                   (const char*)g_g + ((qbase + gr)*CKDIM + gc*8)*2);
        prefetch_F(sb, 0, b, 0, tid);
        prefetch_V(sb, 0, b, 0, tid);
        CP_COMMIT();
    }
    CP_WAIT(0);
    __syncthreads();

    uint32_t gfr[2][4];
    #pragma unroll
    for (int ks = 0; ks < 2; ks++)
        ldm_x4(gfr[ks], sb + OFF_G + (pair*16 + aRow)*80 + ks*32 + aK);

    float accO[16][4];
    #pragma unroll
    for (int i = 0; i < 16; i++) { accO[i][0]=0.f; accO[i][1]=0.f; accO[i][2]=0.f; accO[i][3]=0.f; }
    float mA = -1e30f, mB = -1e30f, lA = 0.f, lB = 0.f;
    float sc[4][4];
    float tmaxA, tmaxB;

    // ---- S(0): G x (Fhi + Flo), 2 passes
    {
        #pragma unroll
        for (int i = 0; i < 4; i++) { sc[i][0]=0.f; sc[i][1]=0.f; sc[i][2]=0.f; sc[i][3]=0.f; }
        const uint32_t fbase = sb + OFF_F;
        #pragma unroll
        for (int pass = 0; pass < 2; pass++) {
            const uint32_t fb = fbase + pass*5120;
            #pragma unroll
            for (int ks = 0; ks < 2; ks++) {
                #pragma unroll
                for (int np = 0; np < 2; np++) {
                    uint32_t fr[4];
                    ldm_x4(fr, fb + (half*32 + np*16 + bHi8 + bR)*80 + ks*32 + bK);
                    mma_f16(sc[2*np],   gfr[ks], fr + 0);
                    mma_f16(sc[2*np+1], gfr[ks], fr + 2);
                }
            }
        }
        tmaxA = -1e30f; tmaxB = -1e30f;
        #pragma unroll
        for (int nt = 0; nt < 4; nt++) {
            tmaxA = fmaxf(tmaxA, fmaxf(sc[nt][0], sc[nt][1]));
            tmaxB = fmaxf(tmaxB, fmaxf(sc[nt][2], sc[nt][3]));
        }
        tmaxA = fmaxf(tmaxA, __shfl_xor_sync(0xffffffffu, tmaxA, 1));
        tmaxA = fmaxf(tmaxA, __shfl_xor_sync(0xffffffffu, tmaxA, 2));
        tmaxB = fmaxf(tmaxB, __shfl_xor_sync(0xffffffffu, tmaxB, 1));
        tmaxB = fmaxf(tmaxB, __shfl_xor_sync(0xffffffffu, tmaxB, 2));
        if ((lane & 3) == 0) { myMax[rq] = tmaxA; myMax[16 + rq] = tmaxB; }
    }
    prefetch_F(sb, 1, b, 1, tid);
    CP_COMMIT();
    __syncthreads();   // maxes(0) visible

    for (int kt = 0; kt < 64; kt++) {
        const int bf = kt & 1;

        // ---- step1: exp(kt) + P write + sums
        float mnA = fmaxf(mA, fmaxf(tmaxA, sibMax[rq]));
        float mnB = fmaxf(mB, fmaxf(tmaxB, sibMax[16 + rq]));
        float scA = __expf(mA - mnA), scB = __expf(mB - mnB);
        bool noscale = __all_sync(0xffffffffu, (scA == 1.0f) && (scB == 1.0f));
        float sumA = 0.f, sumB = 0.f;
        #pragma unroll
        for (int nt = 0; nt < 4; nt++) {
            float p0 = __expf(sc[nt][0] - mnA);
            float p1 = __expf(sc[nt][1] - mnA);
            float p2 = __expf(sc[nt][2] - mnB);
            float p3 = __expf(sc[nt][3] - mnB);
            sumA += p0 + p1; sumB += p2 + p3;
            uint32_t cOff = (half*32 + nt*8 + (lane & 3)*2)*2;
            *(uint32_t*)(smc + (pTile - sb) + rq*144 + cOff)       = pack_f16(p0, p1);
            *(uint32_t*)(smc + (pTile - sb) + (rq + 8)*144 + cOff) = pack_f16(p2, p3);
        }
        sumA += __shfl_xor_sync(0xffffffffu, sumA, 1);
        sumA += __shfl_xor_sync(0xffffffffu, sumA, 2);
        sumB += __shfl_xor_sync(0xffffffffu, sumB, 1);
        sumB += __shfl_xor_sync(0xffffffffu, sumB, 2);
        if ((lane & 3) == 0) { mySum[rq] = sumA; mySum[16 + rq] = sumB; }

        // ---- step2: V(kt), F(kt+1) arrived; P/sums visible
        CP_WAIT(0);
        __syncthreads();   // B1

        // ---- step2b: prefetch now (full PV+S window)
        if (kt < 63) {
            prefetch_V(sb, bf ^ 1, b, kt + 1, tid); CP_COMMIT();
            if (kt < 62) { prefetch_F(sb, bf, b, kt + 2, tid); CP_COMMIT(); }
        }

        // ---- step3: stats merge + (conditional) rescale + PV(kt)
        lA = lA*scA + sumA + sibSum[rq];
        lB = lB*scB + sumB + sibSum[16 + rq];
        mA = mnA;  mB = mnB;
        if (!noscale) {
            #pragma unroll
            for (int nt = 0; nt < 16; nt++) {
                accO[nt][0] *= scA; accO[nt][1] *= scA;
                accO[nt][2] *= scB; accO[nt][3] *= scB;
            }
        }
        uint32_t pa[4][4];
        #pragma unroll
        for (int ks = 0; ks < 4; ks++)
            ldm_x4(pa[ks], pTile + aRow*144 + ks*32 + aK);
        const uint32_t vbase = sb + OFF_V + bf*33792 + half*256;
        #pragma unroll
        for (int ks = 0; ks < 4; ks++) {
            #pragma unroll
            for (int np = 0; np < 8; np++) {
                uint32_t vr[4];
                ldm_x4_trans(vr, vbase + (ks*16 + tR)*528 + np*32 + tC);
                mma_f16(accO[2*np],   pa[ks], vr + 0);
                mma_f16(accO[2*np+1], pa[ks], vr + 2);
            }
        }

        // ---- step4: S(kt+1) + own max + max write
        if (kt < 63) {
            #pragma unroll
            for (int i = 0; i < 4; i++) { sc[i][0]=0.f; sc[i][1]=0.f; sc[i][2]=0.f; sc[i][3]=0.f; }
            const uint32_t fbase = sb + OFF_F + (bf^1)*10240;
            #pragma unroll
            for (int pass = 0; pass < 2; pass++) {
                const uint32_t fb = fbase + pass*5120;
                #pragma unroll
                for (int ks = 0; ks < 2; ks++) {
                    #pragma unroll
                    for (int np = 0; np < 2; np++) {
                        uint32_t fr[4];
                        ldm_x4(fr, fb + (half*32 + np*16 + bHi8 + bR)*80 + ks*32 + bK);
                        mma_f16(sc[2*np],   gfr[ks], fr + 0);
                        mma_f16(sc[2*np+1], gfr[ks], fr + 2);
                    }
                }
            }
            tmaxA = -1e30f; tmaxB = -1e30f;
            #pragma unroll
            for (int nt = 0; nt < 4; nt++) {
                tmaxA = fmaxf(tmaxA, fmaxf(sc[nt][0], sc[nt][1]));
                tmaxB = fmaxf(tmaxB, fmaxf(sc[nt][2], sc[nt][3]));
            }
            tmaxA = fmaxf(tmaxA, __shfl_xor_sync(0xffffffffu, tmaxA, 1));
            tmaxA = fmaxf(tmaxA, __shfl_xor_sync(0xffffffffu, tmaxA, 2));
            tmaxB = fmaxf(tmaxB, __shfl_xor_sync(0xffffffffu, tmaxB, 1));
            tmaxB = fmaxf(tmaxB, __shfl_xor_sync(0xffffffffu, tmaxB, 2));
            if ((lane & 3) == 0) { myMax[rq] = tmaxA; myMax[16 + rq] = tmaxB; }
        }

        __syncthreads();   // B2: max(kt+1) visible; P tile consumed
    }

    // ---- epilogue: write single fp16 o ----
    const float invA = 1.0f / lA, invB = 1.0f / lB;
    const size_t rA = qbase + pair*16 + rq;
    const size_t rB = rA + 8;
    #pragma unroll
    for (int nt = 0; nt < 16; nt++) {
        int c = half*128 + nt*8 + (lane & 3)*2;
        *(uint32_t*)&g_o[rA*CDIM + c] = pack_f16(accO[nt][0]*invA, accO[nt][1]*invA);
        *(uint32_t*)&g_o[rB*CDIM + c] = pack_f16(accO[nt][2]*invB, accO[nt][3]*invB);
    }
}

// ---------------------------------------------------------------------------
extern "C" void kernel_launch(void* const* d_in, const int* in_sizes, int n_in,
                              void* d_out, int out_size) {
    const float* x     = (const float*)d_in[0];
    const float* Wf    = (const float*)d_in[1];
    const float* bf    = (const float*)d_in[2];
    const float* Wg    = (const float*)d_in[3];
    const float* bg    = (const float*)d_in[4];
    const float* Wh    = (const float*)d_in[5];
    const float* bh    = (const float*)d_in[6];
    const float* Wo    = (const float*)d_in[7];
    const float* bo    = (const float*)d_in[8];
    const float* gamma = (const float*)d_in[9];
    float*       out   = (float*)d_out;

    cudaFuncSetAttribute(pre_gemm,  cudaFuncAttributeMaxDynamicSharedMemorySize, P1_SMEM);
    cudaFuncSetAttribute(out_gemm,  cudaFuncAttributeMaxDynamicSharedMemorySize, P3_SMEM);
    cudaFuncSetAttribute(attn_hmma, cudaFuncAttributeMaxDynamicSharedMemorySize, SMEM_ATT);

    const int setup_blocks = (WPREN + WON + 255) / 256;   // 576
    setup_k<<<setup_blocks, 256>>>(Wf, Wg, Wh, Wo);
    pre_gemm<<<ROWS/64*2, 256, P1_SMEM>>>(x, bf, bg, bh);
    attn_hmma<<<512, 256, SMEM_ATT>>>();
    out_gemm<<<ROWS/64*2, 256, P3_SMEM>>>(bo, gamma, x, out);
}